// round 2
// baseline (speedup 1.0000x reference)
#include <cuda_runtime.h>
#include <stdint.h>

#define OBS  32
#define ACTD 8
#define CIN  40
#define HID  200
#define DOUTD 33
#define PMAX 100352

// ---------------- scratch (device globals; no allocs allowed) ----------------
__device__ uint32_t g_bits[PMAX];
__device__ unsigned long long g_slot[PMAX];
__device__ uint32_t g_hist[65536];
__device__ uint32_t g_bstart[65537];
__device__ uint32_t g_cursor[65536];
__device__ uint32_t g_rank1[PMAX];
__device__ uint32_t g_rank2[PMAX];
__device__ uint32_t g_src[PMAX];
__device__ float g_Z[(size_t)PMAX * CIN];
__device__ float g_Abuf[(size_t)PMAX * HID];
__device__ float g_Bbuf[(size_t)PMAX * HID];
__device__ float g_O[(size_t)PMAX * 2 * DOUTD];

// ---------------- threefry2x32 (JAX-compatible) ----------------
__host__ __device__ __forceinline__ uint32_t rotl32(uint32_t v, int d) {
    return (v << d) | (v >> (32 - d));
}

__host__ __device__ inline void threefry2x32(uint32_t k0, uint32_t k1,
                                             uint32_t x0, uint32_t x1,
                                             uint32_t* o0, uint32_t* o1) {
    uint32_t ks2 = k0 ^ k1 ^ 0x1BD11BDAu;
    x0 += k0; x1 += k1;
#define TFR(a) x0 += x1; x1 = rotl32(x1, a); x1 ^= x0;
    TFR(13) TFR(15) TFR(26) TFR(6)
    x0 += k1;  x1 += ks2 + 1u;
    TFR(17) TFR(29) TFR(16) TFR(24)
    x0 += ks2; x1 += k0 + 2u;
    TFR(13) TFR(15) TFR(26) TFR(6)
    x0 += k0;  x1 += k1 + 3u;
    TFR(17) TFR(29) TFR(16) TFR(24)
    x0 += k1;  x1 += ks2 + 4u;
    TFR(13) TFR(15) TFR(26) TFR(6)
    x0 += ks2; x1 += k0 + 5u;
#undef TFR
    *o0 = x0; *o1 = x1;
}

// partitionable-mode random bits: counter (0, idx), output y0^y1
__device__ __forceinline__ uint32_t rbits32(uint32_t k0, uint32_t k1, uint32_t idx) {
    uint32_t a, b;
    threefry2x32(k0, k1, 0u, idx, &a, &b);
    return a ^ b;
}

__device__ __forceinline__ float softplusf(float x) {
    return fmaxf(x, 0.0f) + log1pf(expf(-fabsf(x)));
}

// jax.random.normal from raw 32 bits: uniform in [nextafter(-1,0), 1), sqrt(2)*erfinv
__device__ __forceinline__ float normal_from_bits(uint32_t bits) {
    float f = __uint_as_float((bits >> 9) | 0x3F800000u) - 1.0f;  // [0,1)
    const float lo = -0.99999994f;        // nextafter(-1, 0) in f32
    float val = fmaf(f, 2.0f, lo);        // span (1 - lo) rounds to exactly 2.0f
    val = fmaxf(lo, val);
    return 1.41421354f * erfinvf(val);
}

// ---------------- stable-rank machinery ----------------
__global__ void zero_hist_kernel() {
    int t = blockIdx.x * blockDim.x + threadIdx.x;
    if (t < 65536) g_hist[t] = 0u;
}

__global__ void hist_kernel(uint32_t k0, uint32_t k1, int P) {
    int p = blockIdx.x * blockDim.x + threadIdx.x;
    if (p >= P) return;
    uint32_t b = rbits32(k0, k1, (uint32_t)p);
    g_bits[p] = b;
    atomicAdd(&g_hist[b >> 16], 1u);
}

__global__ void scan_kernel() {
    __shared__ uint32_t part[1024];
    int t = threadIdx.x;
    uint32_t s = 0;
    #pragma unroll 8
    for (int i = 0; i < 64; i++) s += g_hist[t * 64 + i];
    part[t] = s;
    __syncthreads();
    // Hillis-Steele inclusive scan over 1024 partials
    for (int off = 1; off < 1024; off <<= 1) {
        uint32_t v = part[t];
        uint32_t add = (t >= off) ? part[t - off] : 0u;
        __syncthreads();
        part[t] = v + add;
        __syncthreads();
    }
    uint32_t run = (t == 0) ? 0u : part[t - 1];
    for (int i = 0; i < 64; i++) {
        int idx = t * 64 + i;
        g_bstart[idx] = run;
        g_cursor[idx] = run;
        run += g_hist[idx];
    }
    if (t == 1023) g_bstart[65536] = run;
}

__global__ void scatter_kernel(int P) {
    int p = blockIdx.x * blockDim.x + threadIdx.x;
    if (p >= P) return;
    uint32_t b = g_bits[p];
    uint32_t slot = atomicAdd(&g_cursor[b >> 16], 1u);
    g_slot[slot] = (((unsigned long long)(b & 0xFFFFu)) << 17) | (unsigned long long)p;
}

__global__ void rank_kernel(int P, int round) {
    int p = blockIdx.x * blockDim.x + threadIdx.x;
    if (p >= P) return;
    uint32_t b = g_bits[p];
    uint32_t hi = b >> 16;
    uint32_t s0 = g_bstart[hi], s1 = g_bstart[hi + 1];
    unsigned long long my = (((unsigned long long)(b & 0xFFFFu)) << 17) | (unsigned long long)p;
    uint32_t c = 0;
    for (uint32_t s = s0; s < s1; s++) c += (g_slot[s] < my) ? 1u : 0u;
    uint32_t rk = s0 + c;
    if (round == 0) g_rank1[p] = rk; else g_rank2[p] = rk;
}

// ---------------- gather + normalize into permuted ensemble layout ----------------
__global__ void gather_kernel(const float* __restrict__ obs, const float* __restrict__ act,
                              const float* __restrict__ mu, const float* __restrict__ sd,
                              int n, int P) {
    int i = blockIdx.x * blockDim.x + threadIdx.x;
    if (i >= P) return;
    uint32_t q = g_rank2[g_rank1[i]];
    g_src[q] = (uint32_t)i;
    float* zr = &g_Z[(size_t)q * CIN];
    if (i < n) {
        #pragma unroll
        for (int c = 0; c < OBS; c++)
            zr[c] = (obs[(size_t)i * OBS + c] - mu[c]) / sd[c];
        #pragma unroll
        for (int c = 0; c < ACTD; c++)
            zr[OBS + c] = (act[(size_t)i * ACTD + c] - mu[OBS + c]) / sd[OBS + c];
    } else {
        #pragma unroll
        for (int c = 0; c < CIN; c++) zr[c] = 0.0f;
    }
}

// ---------------- fp32 tiled GEMM: C[m-region] = act(A W[elite] + b[elite]) ----------------
#define BM 128
#define BN 64
#define BK 16
// 256 threads, 4x8 register tile
__global__ void gemm_kernel(int sel, const float* __restrict__ W,
                            const float* __restrict__ bias,
                            const int* __restrict__ elites,
                            int r, int K, int N, int applyAct) {
    const float* A;
    float* C;
    if (sel == 0)      { A = g_Z;    C = g_Abuf; }
    else if (sel == 1) { A = g_Abuf; C = g_Bbuf; }
    else if (sel == 2) { A = g_Bbuf; C = g_Abuf; }
    else               { A = g_Abuf; C = g_O;    }

    int m = blockIdx.z;
    int ev = elites[m];
    const float* Wm = W + (size_t)ev * K * N;
    const float* bm = bias + (size_t)ev * N;
    int row0 = blockIdx.y * BM;
    int col0 = blockIdx.x * BN;
    size_t abase = (size_t)m * r * K;
    size_t cbase = (size_t)m * r * N;

    __shared__ __align__(16) float As[BK][BM + 4];  // 16 x 132
    __shared__ __align__(16) float Bs[BK][BN];

    int tid = threadIdx.x;
    int tr = tid >> 3;   // 0..31
    int tc = tid & 7;    // 0..7

    float acc[4][8];
    #pragma unroll
    for (int i = 0; i < 4; i++)
        #pragma unroll
        for (int j = 0; j < 8; j++) acc[i][j] = 0.0f;

    for (int k0 = 0; k0 < K; k0 += BK) {
        // A tile: 128 rows x 16 k
        #pragma unroll
        for (int it = 0; it < (BM * BK) / 256; it++) {
            int t = tid + it * 256;
            int lk = t % BK, lr = t / BK;
            int row = row0 + lr, kk = k0 + lk;
            float v = 0.0f;
            if (row < r && kk < K) v = A[abase + (size_t)row * K + kk];
            As[lk][lr] = v;
        }
        // W tile: 16 k x 64 cols
        #pragma unroll
        for (int it = 0; it < (BK * BN) / 256; it++) {
            int t = tid + it * 256;
            int ln = t % BN, lk = t / BN;
            int kk = k0 + lk, col = col0 + ln;
            float v = 0.0f;
            if (kk < K && col < N) v = Wm[(size_t)kk * N + col];
            Bs[lk][ln] = v;
        }
        __syncthreads();
        #pragma unroll
        for (int kk = 0; kk < BK; kk++) {
            float4 av  = *(const float4*)(&As[kk][tr * 4]);
            float4 bv0 = *(const float4*)(&Bs[kk][tc * 8]);
            float4 bv1 = *(const float4*)(&Bs[kk][tc * 8 + 4]);
            float a[4] = {av.x, av.y, av.z, av.w};
            float b[8] = {bv0.x, bv0.y, bv0.z, bv0.w, bv1.x, bv1.y, bv1.z, bv1.w};
            #pragma unroll
            for (int i = 0; i < 4; i++)
                #pragma unroll
                for (int j = 0; j < 8; j++)
                    acc[i][j] = fmaf(a[i], b[j], acc[i][j]);
        }
        __syncthreads();
    }

    #pragma unroll
    for (int i = 0; i < 4; i++) {
        int row = row0 + tr * 4 + i;
        if (row >= r) continue;
        #pragma unroll
        for (int j = 0; j < 8; j++) {
            int col = col0 + tc * 8 + j;
            if (col >= N) continue;
            float v = acc[i][j] + bm[col];
            if (applyAct) v = v / (1.0f + expf(-v));  // swish
            C[cbase + (size_t)row * N + col] = v;
        }
    }
}

// ---------------- sampling epilogue ----------------
__global__ void sample_kernel(const float* __restrict__ obs,
                              const int* __restrict__ elites,
                              float* __restrict__ out,
                              int n, int P, int r) {
    int q = blockIdx.x * blockDim.x + threadIdx.x;
    if (q >= P) return;
    int k = q / r;
    int j = q - k * r;
    int i = (int)g_src[q];
    if (i >= n) return;
    int ev = elites[k];
    const float* orow = &g_O[(size_t)q * (2 * DOUTD)];
    uint32_t fbase = ((uint32_t)ev * (uint32_t)r + (uint32_t)j) * (uint32_t)DOUTD;
    float sumsq = 0.0f;
    #pragma unroll 3
    for (int d = 0; d < DOUTD; d++) {
        float mean = orow[d];
        float lv = orow[DOUTD + d];
        lv = 0.5f  - softplusf(0.5f - lv);
        lv = -10.0f + softplusf(lv + 10.0f);
        float sd = expf(0.5f * lv);
        float nz = normal_from_bits(rbits32(0u, 0u, fbase + (uint32_t)d));
        float s = fmaf(nz, sd, mean);
        if (d < OBS) {
            float no = s + obs[(size_t)i * OBS + d];
            out[(size_t)i * OBS + d] = no;
            sumsq += no * no;
        } else {
            out[(size_t)n * OBS + i] = s;  // reward (scale=1, bias=0)
        }
    }
    out[(size_t)n * (OBS + 1) + i] = (sqrtf(sumsq) > 50.0f) ? 1.0f : 0.0f;
}

// ---------------- launch ----------------
extern "C" void kernel_launch(void* const* d_in, const int* in_sizes, int n_in,
                              void* d_out, int out_size) {
    const float* obs = (const float*)d_in[0];
    const float* act = (const float*)d_in[1];
    const float* mu  = (const float*)d_in[2];
    const float* sdv = (const float*)d_in[3];
    const float* W1  = (const float*)d_in[4];
    const float* b1  = (const float*)d_in[5];
    const float* W2  = (const float*)d_in[6];
    const float* b2  = (const float*)d_in[7];
    const float* W3  = (const float*)d_in[8];
    const float* b3  = (const float*)d_in[9];
    const float* W4  = (const float*)d_in[10];
    const float* b4  = (const float*)d_in[11];
    const int* elites = (const int*)d_in[12];

    int n = in_sizes[0] / OBS;
    int e = in_sizes[12];
    int r = (n - 1) / e + 1;
    int P = e * r;
    if (P > PMAX) P = PMAX;  // safety (never hit for this problem)

    // host-side threefry for the two shuffle subkeys (fold-like split, partitionable mode)
    uint32_t nk0, nk1, s1a, s1b, s2a, s2b;
    threefry2x32(0u, 0u, 0u, 0u, &nk0, &nk1);   // split(key)[0] -> new key
    threefry2x32(0u, 0u, 0u, 1u, &s1a, &s1b);   // split(key)[1] -> subkey round 1
    threefry2x32(nk0, nk1, 0u, 1u, &s2a, &s2b); // split(new key)[1] -> subkey round 2

    const int TB = 256;
    int gb = (P + TB - 1) / TB;

    // round 1 stable ranks
    zero_hist_kernel<<<256, 256>>>();
    hist_kernel<<<gb, TB>>>(s1a, s1b, P);
    scan_kernel<<<1, 1024>>>();
    scatter_kernel<<<gb, TB>>>(P);
    rank_kernel<<<gb, TB>>>(P, 0);
    // round 2 stable ranks
    zero_hist_kernel<<<256, 256>>>();
    hist_kernel<<<gb, TB>>>(s2a, s2b, P);
    scan_kernel<<<1, 1024>>>();
    scatter_kernel<<<gb, TB>>>(P);
    rank_kernel<<<gb, TB>>>(P, 1);

    // gather + normalize into permuted layout
    gather_kernel<<<gb, TB>>>(obs, act, mu, sdv, n, P);

    // MLP
    dim3 grid1((HID + BN - 1) / BN, (r + BM - 1) / BM, e);
    gemm_kernel<<<grid1, 256>>>(0, W1, b1, elites, r, CIN, HID, 1);
    gemm_kernel<<<grid1, 256>>>(1, W2, b2, elites, r, HID, HID, 1);
    gemm_kernel<<<grid1, 256>>>(2, W3, b3, elites, r, HID, HID, 1);
    dim3 grid4((2 * DOUTD + BN - 1) / BN, (r + BM - 1) / BM, e);
    gemm_kernel<<<grid4, 256>>>(3, W4, b4, elites, r, HID, 2 * DOUTD, 0);

    // sampling + scatter + reward + terminal
    sample_kernel<<<gb, TB>>>(obs, elites, (float*)d_out, n, P, r);
}

// round 7
// speedup vs baseline: 1.7809x; 1.7809x over previous
#include <cuda_runtime.h>
#include <cuda_bf16.h>
#include <stdint.h>

#define OBS   32
#define ACTD  8
#define CIN   40
#define HID   200
#define DOUTD 33
#define PMAX  100352
#define MMAX  8

// ================= scratch (device globals; referenced ONLY from device code) =========
__device__ uint32_t g_bits[PMAX];
__device__ unsigned long long g_slot[PMAX];
__device__ uint32_t g_hist[65536];
__device__ uint32_t g_bstart[65537];
__device__ uint32_t g_cursor[65536];
__device__ uint32_t g_rank1[PMAX];
__device__ uint32_t g_rank2[PMAX];
__device__ uint32_t g_src[PMAX];
// activations, stride 256 bf16 (hi/lo split). L1 input lives in g_Ah/g_Al at stride 64.
__device__ __nv_bfloat16 g_Ah[(size_t)PMAX * 256];
__device__ __nv_bfloat16 g_Al[(size_t)PMAX * 256];
__device__ __nv_bfloat16 g_Bh[(size_t)PMAX * 256];
__device__ __nv_bfloat16 g_Bl[(size_t)PMAX * 256];
// transposed/split weights: [m][n_pad][k_pad]
__device__ __nv_bfloat16 g_W1h[MMAX * 256 * 64],  g_W1l[MMAX * 256 * 64];
__device__ __nv_bfloat16 g_W2h[MMAX * 256 * 256], g_W2l[MMAX * 256 * 256];
__device__ __nv_bfloat16 g_W3h[MMAX * 256 * 256], g_W3l[MMAX * 256 * 256];
__device__ __nv_bfloat16 g_W4h[MMAX * 80 * 256],  g_W4l[MMAX * 80 * 256];

// ================= threefry (JAX partitionable) =================
__host__ __device__ __forceinline__ uint32_t rotl32(uint32_t v, int d) {
    return (v << d) | (v >> (32 - d));
}
__host__ __device__ __forceinline__ void threefry2x32(uint32_t k0, uint32_t k1,
                                                      uint32_t x0, uint32_t x1,
                                                      uint32_t& o0, uint32_t& o1) {
    uint32_t ks2 = k0 ^ k1 ^ 0x1BD11BDAu;
    x0 += k0; x1 += k1;
#define TFR(a) x0 += x1; x1 = rotl32(x1, a); x1 ^= x0;
    TFR(13) TFR(15) TFR(26) TFR(6)
    x0 += k1;  x1 += ks2 + 1u;
    TFR(17) TFR(29) TFR(16) TFR(24)
    x0 += ks2; x1 += k0 + 2u;
    TFR(13) TFR(15) TFR(26) TFR(6)
    x0 += k0;  x1 += k1 + 3u;
    TFR(17) TFR(29) TFR(16) TFR(24)
    x0 += k1;  x1 += ks2 + 4u;
    TFR(13) TFR(15) TFR(26) TFR(6)
    x0 += ks2; x1 += k0 + 5u;
#undef TFR
    o0 = x0; o1 = x1;
}
__device__ __forceinline__ uint32_t rbits32(uint32_t k0, uint32_t k1, uint32_t idx) {
    uint32_t a, b;
    threefry2x32(k0, k1, 0u, idx, a, b);
    return a ^ b;
}
__device__ __forceinline__ float softplusf(float x) {
    return fmaxf(x, 0.0f) + log1pf(expf(-fabsf(x)));
}
__device__ __forceinline__ float normal_from_bits(uint32_t bits) {
    float f = __uint_as_float((bits >> 9) | 0x3F800000u) - 1.0f;
    const float lo = -0.99999994f;
    float val = fmaf(f, 2.0f, lo);
    val = fmaxf(lo, val);
    return 1.41421354f * erfinvf(val);
}

// ================= asm macros (all scalar operands) =================
__device__ __forceinline__ uint32_t smem_u32(const void* p) {
    uint32_t a;
    asm("{ .reg .u64 t; cvta.to.shared.u64 t, %1; cvt.u32.u64 %0, t; }" : "=r"(a) : "l"(p));
    return a;
}
#define LDSM4(r0, r1, r2, r3, addr) \
    asm volatile("ldmatrix.sync.aligned.m8n8.x4.shared.b16 {%0,%1,%2,%3}, [%4];" \
                 : "=r"(r0), "=r"(r1), "=r"(r2), "=r"(r3) : "r"(addr))
#define LDSM2(r0, r1, addr) \
    asm volatile("ldmatrix.sync.aligned.m8n8.x2.shared.b16 {%0,%1}, [%2];" \
                 : "=r"(r0), "=r"(r1) : "r"(addr))
#define MMAQ(cp, a0, a1, a2, a3, b0, b1) \
    asm volatile("mma.sync.aligned.m16n8k16.row.col.f32.bf16.bf16.f32 " \
                 "{%0,%1,%2,%3}, {%4,%5,%6,%7}, {%8,%9}, {%0,%1,%2,%3};" \
                 : "+f"(cp##0), "+f"(cp##1), "+f"(cp##2), "+f"(cp##3) \
                 : "r"(a0), "r"(a1), "r"(a2), "r"(a3), "r"(b0), "r"(b1))

__device__ __forceinline__ uint32_t pack_hi(float v0, float v1) {
    __nv_bfloat16 h0 = __float2bfloat16(v0), h1 = __float2bfloat16(v1);
    return (uint32_t)__bfloat16_as_ushort(h0) | ((uint32_t)__bfloat16_as_ushort(h1) << 16);
}
__device__ __forceinline__ uint32_t pack_lo(float v0, float v1) {
    __nv_bfloat16 h0 = __float2bfloat16(v0), h1 = __float2bfloat16(v1);
    __nv_bfloat16 l0 = __float2bfloat16(v0 - __bfloat162float(h0));
    __nv_bfloat16 l1 = __float2bfloat16(v1 - __bfloat162float(h1));
    return (uint32_t)__bfloat16_as_ushort(l0) | ((uint32_t)__bfloat16_as_ushort(l1) << 16);
}

// ================= permutation machinery (R1, known clean) =================
__global__ void zero_hist_kernel() {
    int t = blockIdx.x * blockDim.x + threadIdx.x;
    if (t < 65536) g_hist[t] = 0u;
}
__global__ void hist_kernel(uint32_t k0, uint32_t k1, int P) {
    int p = blockIdx.x * blockDim.x + threadIdx.x;
    if (p >= P) return;
    uint32_t b = rbits32(k0, k1, (uint32_t)p);
    g_bits[p] = b;
    atomicAdd(&g_hist[b >> 16], 1u);
}
__global__ void scan_kernel() {
    __shared__ uint32_t part[1024];
    int t = threadIdx.x;
    uint32_t s = 0;
    #pragma unroll 8
    for (int i = 0; i < 64; i++) s += g_hist[t * 64 + i];
    part[t] = s;
    __syncthreads();
    for (int off = 1; off < 1024; off <<= 1) {
        uint32_t v = part[t];
        uint32_t add = (t >= off) ? part[t - off] : 0u;
        __syncthreads();
        part[t] = v + add;
        __syncthreads();
    }
    uint32_t run = (t == 0) ? 0u : part[t - 1];
    for (int i = 0; i < 64; i++) {
        int idx = t * 64 + i;
        g_bstart[idx] = run;
        g_cursor[idx] = run;
        run += g_hist[idx];
    }
    if (t == 1023) g_bstart[65536] = run;
}
__global__ void scatter_kernel(int P) {
    int p = blockIdx.x * blockDim.x + threadIdx.x;
    if (p >= P) return;
    uint32_t b = g_bits[p];
    uint32_t slot = atomicAdd(&g_cursor[b >> 16], 1u);
    g_slot[slot] = (((unsigned long long)(b & 0xFFFFu)) << 17) | (unsigned long long)p;
}
__global__ void rank_kernel(int P, int round) {
    int p = blockIdx.x * blockDim.x + threadIdx.x;
    if (p >= P) return;
    uint32_t b = g_bits[p];
    uint32_t hi = b >> 16;
    uint32_t s0 = g_bstart[hi], s1 = g_bstart[hi + 1];
    unsigned long long my = (((unsigned long long)(b & 0xFFFFu)) << 17) | (unsigned long long)p;
    uint32_t c = 0;
    for (uint32_t s = s0; s < s1; s++) c += (g_slot[s] < my) ? 1u : 0u;
    uint32_t rk = s0 + c;
    if (round == 0) g_rank1[p] = rk; else g_rank2[p] = rk;
}

// ================= gather + normalize -> bf16 hi/lo (stride 64) =================
__global__ void gather_kernel(const float* __restrict__ obs, const float* __restrict__ act,
                              const float* __restrict__ mu, const float* __restrict__ sd,
                              int n, int P) {
    int i = blockIdx.x * blockDim.x + threadIdx.x;
    if (i >= P) return;
    uint32_t q = g_rank2[g_rank1[i]];
    g_src[q] = (uint32_t)i;
    uint32_t* oh = reinterpret_cast<uint32_t*>(g_Ah + (size_t)q * 64);
    uint32_t* ol = reinterpret_cast<uint32_t*>(g_Al + (size_t)q * 64);
    if (i < n) {
        #pragma unroll
        for (int c = 0; c < CIN; c += 2) {
            float x0 = (c < OBS) ? obs[(size_t)i * OBS + c] : act[(size_t)i * ACTD + (c - OBS)];
            float x1 = (c + 1 < OBS) ? obs[(size_t)i * OBS + c + 1]
                                     : act[(size_t)i * ACTD + (c + 1 - OBS)];
            float v0 = (x0 - mu[c]) / sd[c];
            float v1 = (x1 - mu[c + 1]) / sd[c + 1];
            oh[c >> 1] = pack_hi(v0, v1);
            ol[c >> 1] = pack_lo(v0, v1);
        }
        #pragma unroll
        for (int c = CIN; c < 64; c += 2) { oh[c >> 1] = 0u; ol[c >> 1] = 0u; }
    } else {
        #pragma unroll
        for (int c = 0; c < 64; c += 2) { oh[c >> 1] = 0u; ol[c >> 1] = 0u; }
    }
}

// ====== weight transpose/convert: W[m][k][n] -> Wt[m][n_pad][k_pad] hi/lo.
// Target arrays selected in DEVICE code (never pass device symbols from host).
__global__ void prep_w(const float* __restrict__ W, int which,
                       int K, int N, int Nrows, int Kpad, int total) {
    int t = blockIdx.x * blockDim.x + threadIdx.x;
    if (t >= total) return;
    __nv_bfloat16* Wh;
    __nv_bfloat16* Wl;
    if (which == 0)      { Wh = g_W1h; Wl = g_W1l; }
    else if (which == 1) { Wh = g_W2h; Wl = g_W2l; }
    else if (which == 2) { Wh = g_W3h; Wl = g_W3l; }
    else                 { Wh = g_W4h; Wl = g_W4l; }
    int kp = t % Kpad;
    int rest = t / Kpad;
    int nn = rest % Nrows;
    int mm = rest / Nrows;
    float v = 0.0f;
    if (nn < N && kp < K) v = W[((size_t)mm * K + kp) * N + nn];
    __nv_bfloat16 h = __float2bfloat16(v);
    __nv_bfloat16 l = __float2bfloat16(v - __bfloat162float(h));
    Wh[t] = h;
    Wl[t] = l;
}

// stride of smem tile rows (bytes): 64 bf16 = 128B + 16B pad
#define ASTR 144

// ======== hidden-layer GEMM, CTA tile 64x64, static smem, all-scalar regs ========
// layer 0: g_Ah(64) x W1 -> g_Bh ; layer 1: g_Bh(256) x W2 -> g_Ah ; layer 2: g_Ah(256) x W3 -> g_Bh
__global__ void __launch_bounds__(256, 1) gemm64(
    int layer, const float* __restrict__ bias, const int* __restrict__ elites,
    int r, int K, int N)
{
    const __nv_bfloat16* Ah;
    const __nv_bfloat16* Al;
    const __nv_bfloat16* Wh;
    const __nv_bfloat16* Wl;
    __nv_bfloat16* Ch;
    __nv_bfloat16* Cl;
    int strideA, wKpad;
    if (layer == 0) {
        Ah = g_Ah; Al = g_Al; Wh = g_W1h; Wl = g_W1l; Ch = g_Bh; Cl = g_Bl;
        strideA = 64; wKpad = 64;
    } else if (layer == 1) {
        Ah = g_Bh; Al = g_Bl; Wh = g_W2h; Wl = g_W2l; Ch = g_Ah; Cl = g_Al;
        strideA = 256; wKpad = 256;
    } else {
        Ah = g_Ah; Al = g_Al; Wh = g_W3h; Wl = g_W3l; Ch = g_Bh; Cl = g_Bl;
        strideA = 256; wKpad = 256;
    }

    // smem: A hi [0,9216), A lo [9216,18432), B hi [18432,27648), B lo [27648,36864)
    __shared__ __align__(16) char sm[36864];
    uint32_t sb = smem_u32(sm);
    int tid = threadIdx.x, lane = tid & 31, wid = tid >> 5;
    int warp_m = wid >> 1, warp_n = wid & 1;
    int row0 = blockIdx.x * 64, col0 = blockIdx.y * 64;
    int m = blockIdx.z;
    int ev = elites[m];
    size_t qbase = (size_t)m * r;
    size_t wbase = (size_t)ev * 256 * wKpad;
    const float* biasm = bias + (size_t)ev * N;

    float c00 = 0.f, c01 = 0.f, c02 = 0.f, c03 = 0.f;
    float c10 = 0.f, c11 = 0.f, c12 = 0.f, c13 = 0.f;
    float c20 = 0.f, c21 = 0.f, c22 = 0.f, c23 = 0.f;
    float c30 = 0.f, c31 = 0.f, c32 = 0.f, c33 = 0.f;

    uint32_t a_addr = sb + (uint32_t)((warp_m * 16 + (lane & 15)) * ASTR + (lane >> 4) * 16);
    uint32_t b_addr = sb + 18432u +
        (uint32_t)((warp_n * 32 + (lane & 7) + ((lane >> 4) << 3)) * ASTR + ((lane >> 3) & 1) * 16);

    int chunks = (K + 63) >> 6;
    for (int c = 0; c < chunks; c++) {
        int ccol = c * 64;
        #pragma unroll
        for (int i = 0; i < 2; i++) {
            int idx = tid + i * 256;
            int rr = idx >> 3, u = idx & 7;
            int grow = row0 + rr;
            uint4 vh = make_uint4(0, 0, 0, 0), vl = make_uint4(0, 0, 0, 0);
            if (grow < r) {
                size_t g = (qbase + grow) * (size_t)strideA + ccol + u * 8;
                vh = *reinterpret_cast<const uint4*>(Ah + g);
                vl = *reinterpret_cast<const uint4*>(Al + g);
            }
            *reinterpret_cast<uint4*>(sm + rr * ASTR + u * 16) = vh;
            *reinterpret_cast<uint4*>(sm + 9216 + rr * ASTR + u * 16) = vl;
        }
        #pragma unroll
        for (int i = 0; i < 2; i++) {
            int idx = tid + i * 256;
            int nr = idx >> 3, u = idx & 7;
            size_t g = wbase + (size_t)(col0 + nr) * wKpad + ccol + u * 8;
            *reinterpret_cast<uint4*>(sm + 18432 + nr * ASTR + u * 16) =
                *reinterpret_cast<const uint4*>(Wh + g);
            *reinterpret_cast<uint4*>(sm + 27648 + nr * ASTR + u * 16) =
                *reinterpret_cast<const uint4*>(Wl + g);
        }
        __syncthreads();

        int steps = (K - ccol + 15) >> 4;
        if (steps > 4) steps = 4;
        for (int s = 0; s < steps; s++) {
            uint32_t ko = (uint32_t)(s * 32);
            uint32_t ah0, ah1, ah2, ah3, al0, al1, al2, al3;
            uint32_t bh0, bh1, bh2, bh3, bh4, bh5, bh6, bh7;
            uint32_t bl0, bl1, bl2, bl3, bl4, bl5, bl6, bl7;
            LDSM4(ah0, ah1, ah2, ah3, a_addr + ko);
            LDSM4(al0, al1, al2, al3, a_addr + 9216u + ko);
            LDSM4(bh0, bh1, bh2, bh3, b_addr + ko);
            LDSM4(bh4, bh5, bh6, bh7, b_addr + 16u * ASTR + ko);
            LDSM4(bl0, bl1, bl2, bl3, b_addr + 9216u + ko);
            LDSM4(bl4, bl5, bl6, bl7, b_addr + 9216u + 16u * ASTR + ko);
            MMAQ(c0, ah0, ah1, ah2, ah3, bh0, bh1);
            MMAQ(c1, ah0, ah1, ah2, ah3, bh2, bh3);
            MMAQ(c2, ah0, ah1, ah2, ah3, bh4, bh5);
            MMAQ(c3, ah0, ah1, ah2, ah3, bh6, bh7);
            MMAQ(c0, ah0, ah1, ah2, ah3, bl0, bl1);
            MMAQ(c1, ah0, ah1, ah2, ah3, bl2, bl3);
            MMAQ(c2, ah0, ah1, ah2, ah3, bl4, bl5);
            MMAQ(c3, ah0, ah1, ah2, ah3, bl6, bl7);
            MMAQ(c0, al0, al1, al2, al3, bh0, bh1);
            MMAQ(c1, al0, al1, al2, al3, bh2, bh3);
            MMAQ(c2, al0, al1, al2, al3, bh4, bh5);
            MMAQ(c3, al0, al1, al2, al3, bh6, bh7);
        }
        __syncthreads();
    }

    // epilogue: bias + swish, split hi/lo, store (zeros pad cols >= N)
    int rlo = row0 + warp_m * 16 + (lane >> 2);
    int colb = col0 + warp_n * 32 + (lane & 3) * 2;
#define EPI64(cp, toff) do { \
    int col = colb + (toff); \
    if (rlo < r) { \
        float v0 = 0.0f, v1 = 0.0f; \
        if (col < N) { \
            float d0 = cp##0 + biasm[col]; \
            float d1 = cp##1 + biasm[col + 1]; \
            v0 = d0 / (1.0f + expf(-d0)); \
            v1 = d1 / (1.0f + expf(-d1)); \
        } \
        size_t o = ((qbase + rlo) * 256 + col) >> 1; \
        reinterpret_cast<uint32_t*>(Ch)[o] = pack_hi(v0, v1); \
        reinterpret_cast<uint32_t*>(Cl)[o] = pack_lo(v0, v1); \
    } \
    if (rlo + 8 < r) { \
        float v0 = 0.0f, v1 = 0.0f; \
        if (col < N) { \
            float d0 = cp##2 + biasm[col]; \
            float d1 = cp##3 + biasm[col + 1]; \
            v0 = d0 / (1.0f + expf(-d0)); \
            v1 = d1 / (1.0f + expf(-d1)); \
        } \
        size_t o = ((qbase + rlo + 8) * 256 + col) >> 1; \
        reinterpret_cast<uint32_t*>(Ch)[o] = pack_hi(v0, v1); \
        reinterpret_cast<uint32_t*>(Cl)[o] = pack_lo(v0, v1); \
    } \
} while (0)
    EPI64(c0, 0);
    EPI64(c1, 8);
    EPI64(c2, 16);
    EPI64(c3, 24);
#undef EPI64
}

// ======== layer-4 GEMM (N=66 padded 80) fused with sampling epilogue ========
// A = g_Bh/g_Bl (stride 256), W = g_W4h/g_W4l — bound in device code.
__global__ void __launch_bounds__(256, 1) gemm_l4(
    const float* __restrict__ b4, const int* __restrict__ elites,
    int r, int K,
    const float* __restrict__ obs, float* __restrict__ out, int n)
{
    const __nv_bfloat16* Ah = g_Bh;
    const __nv_bfloat16* Al = g_Bl;
    const __nv_bfloat16* Wh = g_W4h;
    const __nv_bfloat16* Wl = g_W4l;

    // smem: A hi [0,9216), A lo [9216,18432), B hi [18432,29952), B lo [29952,41472)
    __shared__ __align__(16) char sm[41472];
    uint32_t sb = smem_u32(sm);
    int tid = threadIdx.x, lane = tid & 31, wid = tid >> 5;
    int warp_m = wid >> 1, warp_n = wid & 1;
    int row0 = blockIdx.x * 64;
    int m = blockIdx.y;
    int ev = elites[m];
    size_t qbase = (size_t)m * r;
    size_t wbase = (size_t)ev * 80 * 256;

    float d00 = 0.f, d01 = 0.f, d02 = 0.f, d03 = 0.f;
    float d10 = 0.f, d11 = 0.f, d12 = 0.f, d13 = 0.f;
    float d20 = 0.f, d21 = 0.f, d22 = 0.f, d23 = 0.f;
    float d30 = 0.f, d31 = 0.f, d32 = 0.f, d33 = 0.f;
    float d40 = 0.f, d41 = 0.f, d42 = 0.f, d43 = 0.f;

    uint32_t a_addr = sb + (uint32_t)((warp_m * 16 + (lane & 15)) * ASTR + (lane >> 4) * 16);
    uint32_t b_addr = sb + 18432u +
        (uint32_t)((warp_n * 40 + (lane & 7) + ((lane >> 4) << 3)) * ASTR + ((lane >> 3) & 1) * 16);
    uint32_t b2_addr = sb + 18432u +
        (uint32_t)((warp_n * 40 + 32 + (lane & 7)) * ASTR + ((lane >> 3) & 1) * 16);

    int chunks = (K + 63) >> 6;
    for (int c = 0; c < chunks; c++) {
        int ccol = c * 64;
        #pragma unroll
        for (int i = 0; i < 2; i++) {
            int idx = tid + i * 256;
            int rr = idx >> 3, u = idx & 7;
            int grow = row0 + rr;
            uint4 vh = make_uint4(0, 0, 0, 0), vl = make_uint4(0, 0, 0, 0);
            if (grow < r) {
                size_t g = (qbase + grow) * 256 + ccol + u * 8;
                vh = *reinterpret_cast<const uint4*>(Ah + g);
                vl = *reinterpret_cast<const uint4*>(Al + g);
            }
            *reinterpret_cast<uint4*>(sm + rr * ASTR + u * 16) = vh;
            *reinterpret_cast<uint4*>(sm + 9216 + rr * ASTR + u * 16) = vl;
        }
        #pragma unroll
        for (int i = 0; i < 3; i++) {
            int idx = tid + i * 256;
            if (idx < 640) {
                int nr = idx >> 3, u = idx & 7;
                size_t g = wbase + (size_t)nr * 256 + ccol + u * 8;
                *reinterpret_cast<uint4*>(sm + 18432 + nr * ASTR + u * 16) =
                    *reinterpret_cast<const uint4*>(Wh + g);
                *reinterpret_cast<uint4*>(sm + 29952 + nr * ASTR + u * 16) =
                    *reinterpret_cast<const uint4*>(Wl + g);
            }
        }
        __syncthreads();

        int steps = (K - ccol + 15) >> 4;
        if (steps > 4) steps = 4;
        for (int s = 0; s < steps; s++) {
            uint32_t ko = (uint32_t)(s * 32);
            uint32_t ah0, ah1, ah2, ah3, al0, al1, al2, al3;
            uint32_t bh0, bh1, bh2, bh3, bh4, bh5, bh6, bh7;
            uint32_t bl0, bl1, bl2, bl3, bl4, bl5, bl6, bl7;
            uint32_t p0, p1, q0, q1;
            LDSM4(ah0, ah1, ah2, ah3, a_addr + ko);
            LDSM4(al0, al1, al2, al3, a_addr + 9216u + ko);
            LDSM4(bh0, bh1, bh2, bh3, b_addr + ko);
            LDSM4(bh4, bh5, bh6, bh7, b_addr + 16u * ASTR + ko);
            LDSM4(bl0, bl1, bl2, bl3, b_addr + 11520u + ko);
            LDSM4(bl4, bl5, bl6, bl7, b_addr + 11520u + 16u * ASTR + ko);
            LDSM2(p0, p1, b2_addr + ko);
            LDSM2(q0, q1, b2_addr + 11520u + ko);
            MMAQ(d0, ah0, ah1, ah2, ah3, bh0, bh1);
            MMAQ(d1, ah0, ah1, ah2, ah3, bh2, bh3);
            MMAQ(d2, ah0, ah1, ah2, ah3, bh4, bh5);
            MMAQ(d3, ah0, ah1, ah2, ah3, bh6, bh7);
            MMAQ(d4, ah0, ah1, ah2, ah3, p0, p1);
            MMAQ(d0, ah0, ah1, ah2, ah3, bl0, bl1);
            MMAQ(d1, ah0, ah1, ah2, ah3, bl2, bl3);
            MMAQ(d2, ah0, ah1, ah2, ah3, bl4, bl5);
            MMAQ(d3, ah0, ah1, ah2, ah3, bl6, bl7);
            MMAQ(d4, ah0, ah1, ah2, ah3, q0, q1);
            MMAQ(d0, al0, al1, al2, al3, bh0, bh1);
            MMAQ(d1, al0, al1, al2, al3, bh2, bh3);
            MMAQ(d2, al0, al1, al2, al3, bh4, bh5);
            MMAQ(d3, al0, al1, al2, al3, bh6, bh7);
            MMAQ(d4, al0, al1, al2, al3, p0, p1);
        }
        __syncthreads();
    }

    // stage accumulators to smem [64][80] f32
    float* stg = reinterpret_cast<float*>(sm);
    {
        int rlo = warp_m * 16 + (lane >> 2);
        int colb = warp_n * 40 + (lane & 3) * 2;
#define STG4(cp, toff) do { \
        int col = colb + (toff); \
        stg[rlo * 80 + col]           = cp##0; \
        stg[rlo * 80 + col + 1]       = cp##1; \
        stg[(rlo + 8) * 80 + col]     = cp##2; \
        stg[(rlo + 8) * 80 + col + 1] = cp##3; \
} while (0)
        STG4(d0, 0);
        STG4(d1, 8);
        STG4(d2, 16);
        STG4(d3, 24);
        STG4(d4, 32);
#undef STG4
    }
    __syncthreads();

    // per-row sampling / scatter / reward / terminal
    if (tid < 64) {
        int j = row0 + tid;
        if (j < r) {
            size_t q = qbase + j;
            int i = (int)g_src[q];
            if (i < n) {
                const float* bm = b4 + (size_t)ev * 66;
                const float* row = stg + tid * 80;
                uint32_t fbase = ((uint32_t)ev * (uint32_t)r + (uint32_t)j) * 33u;
                float sumsq = 0.0f;
                for (int d = 0; d < 33; d++) {
                    float mean = row[d] + bm[d];
                    float lv = row[33 + d] + bm[33 + d];
                    lv = 0.5f - softplusf(0.5f - lv);
                    lv = -10.0f + softplusf(lv + 10.0f);
                    float sd = expf(0.5f * lv);
                    float nz = normal_from_bits(rbits32(0u, 0u, fbase + (uint32_t)d));
                    float s = fmaf(nz, sd, mean);
                    if (d < 32) {
                        float no = s + obs[(size_t)i * OBS + d];
                        out[(size_t)i * OBS + d] = no;
                        sumsq += no * no;
                    } else {
                        out[(size_t)n * OBS + i] = s;
                    }
                }
                out[(size_t)n * (OBS + 1) + i] = (sqrtf(sumsq) > 50.0f) ? 1.0f : 0.0f;
            }
        }
    }
}

// ================= launch =================
extern "C" void kernel_launch(void* const* d_in, const int* in_sizes, int n_in,
                              void* d_out, int out_size) {
    const float* obs = (const float*)d_in[0];
    const float* act = (const float*)d_in[1];
    const float* mu  = (const float*)d_in[2];
    const float* sdv = (const float*)d_in[3];
    const float* W1  = (const float*)d_in[4];
    const float* b1  = (const float*)d_in[5];
    const float* W2  = (const float*)d_in[6];
    const float* b2  = (const float*)d_in[7];
    const float* W3  = (const float*)d_in[8];
    const float* b3  = (const float*)d_in[9];
    const float* W4  = (const float*)d_in[10];
    const float* b4  = (const float*)d_in[11];
    const int* elites = (const int*)d_in[12];

    int n = in_sizes[0] / OBS;
    int e = in_sizes[12];
    int r = (n - 1) / e + 1;
    int P = e * r;
    if (P > PMAX) P = PMAX;
    int Mm = in_sizes[4] / (CIN * HID);
    if (Mm > MMAX) Mm = MMAX;

    uint32_t nk0, nk1, s1a, s1b, s2a, s2b;
    threefry2x32(0u, 0u, 0u, 0u, nk0, nk1);
    threefry2x32(0u, 0u, 0u, 1u, s1a, s1b);
    threefry2x32(nk0, nk1, 0u, 1u, s2a, s2b);

    const int TB = 256;
    int gb = (P + TB - 1) / TB;

    // weight transpose/convert (device-side target selection)
    {
        int t1 = Mm * 256 * 64;
        prep_w<<<(t1 + 255) / 256, 256>>>(W1, 0, CIN, HID, 256, 64, t1);
        int t2 = Mm * 256 * 256;
        prep_w<<<(t2 + 255) / 256, 256>>>(W2, 1, HID, HID, 256, 256, t2);
        prep_w<<<(t2 + 255) / 256, 256>>>(W3, 2, HID, HID, 256, 256, t2);
        int t4 = Mm * 80 * 256;
        prep_w<<<(t4 + 255) / 256, 256>>>(W4, 3, HID, 2 * DOUTD, 80, 256, t4);
    }

    // permutation (two stable-rank rounds)
    zero_hist_kernel<<<256, 256>>>();
    hist_kernel<<<gb, TB>>>(s1a, s1b, P);
    scan_kernel<<<1, 1024>>>();
    scatter_kernel<<<gb, TB>>>(P);
    rank_kernel<<<gb, TB>>>(P, 0);
    zero_hist_kernel<<<256, 256>>>();
    hist_kernel<<<gb, TB>>>(s2a, s2b, P);
    scan_kernel<<<1, 1024>>>();
    scatter_kernel<<<gb, TB>>>(P);
    rank_kernel<<<gb, TB>>>(P, 1);

    gather_kernel<<<gb, TB>>>(obs, act, mu, sdv, n, P);

    int mt = (r + 63) / 64;
    dim3 gridH(mt, 4, e);  // 4 N-tiles of 64 cover 200 (padded 256)
    gemm64<<<gridH, 256>>>(0, b1, elites, r, CIN, HID);
    gemm64<<<gridH, 256>>>(1, b2, elites, r, HID, HID);
    gemm64<<<gridH, 256>>>(2, b3, elites, r, HID, HID);
    dim3 gridL4(mt, e);
    gemm_l4<<<gridL4, 256>>>(b4, elites, r, HID, obs, (float*)d_out, n);
}

// round 8
// speedup vs baseline: 1.8275x; 1.0262x over previous
#include <cuda_runtime.h>
#include <cuda_bf16.h>
#include <stdint.h>

#define OBS   32
#define ACTD  8
#define CIN   40
#define HID   200
#define DOUTD 33
#define PMAX  100352
#define MMAX  8

// ================= scratch (device globals; referenced ONLY from device code) =========
__device__ uint32_t g_bits[PMAX];
__device__ unsigned long long g_slot[PMAX];
__device__ uint32_t g_hist[65536];
__device__ uint32_t g_bstart[65537];
__device__ uint32_t g_cursor[65536];
__device__ uint32_t g_rank1[PMAX];
__device__ uint32_t g_rank2[PMAX];
__device__ uint32_t g_src[PMAX];
// activations, stride 256 bf16 (hi/lo split). L1 input lives in g_Ah/g_Al at stride 64.
__device__ __nv_bfloat16 g_Ah[(size_t)PMAX * 256];
__device__ __nv_bfloat16 g_Al[(size_t)PMAX * 256];
__device__ __nv_bfloat16 g_Bh[(size_t)PMAX * 256];
__device__ __nv_bfloat16 g_Bl[(size_t)PMAX * 256];
// transposed/split weights: [m][n_pad][k_pad]
__device__ __nv_bfloat16 g_W1h[MMAX * 256 * 64],  g_W1l[MMAX * 256 * 64];
__device__ __nv_bfloat16 g_W2h[MMAX * 256 * 256], g_W2l[MMAX * 256 * 256];
__device__ __nv_bfloat16 g_W3h[MMAX * 256 * 256], g_W3l[MMAX * 256 * 256];
__device__ __nv_bfloat16 g_W4h[MMAX * 80 * 256],  g_W4l[MMAX * 80 * 256];

// ================= threefry (JAX partitionable) =================
__host__ __device__ __forceinline__ uint32_t rotl32(uint32_t v, int d) {
    return (v << d) | (v >> (32 - d));
}
__host__ __device__ __forceinline__ void threefry2x32(uint32_t k0, uint32_t k1,
                                                      uint32_t x0, uint32_t x1,
                                                      uint32_t& o0, uint32_t& o1) {
    uint32_t ks2 = k0 ^ k1 ^ 0x1BD11BDAu;
    x0 += k0; x1 += k1;
#define TFR(a) x0 += x1; x1 = rotl32(x1, a); x1 ^= x0;
    TFR(13) TFR(15) TFR(26) TFR(6)
    x0 += k1;  x1 += ks2 + 1u;
    TFR(17) TFR(29) TFR(16) TFR(24)
    x0 += ks2; x1 += k0 + 2u;
    TFR(13) TFR(15) TFR(26) TFR(6)
    x0 += k0;  x1 += k1 + 3u;
    TFR(17) TFR(29) TFR(16) TFR(24)
    x0 += k1;  x1 += ks2 + 4u;
    TFR(13) TFR(15) TFR(26) TFR(6)
    x0 += ks2; x1 += k0 + 5u;
#undef TFR
    o0 = x0; o1 = x1;
}
__device__ __forceinline__ uint32_t rbits32(uint32_t k0, uint32_t k1, uint32_t idx) {
    uint32_t a, b;
    threefry2x32(k0, k1, 0u, idx, a, b);
    return a ^ b;
}
__device__ __forceinline__ float softplusf(float x) {
    return fmaxf(x, 0.0f) + log1pf(expf(-fabsf(x)));
}
__device__ __forceinline__ float normal_from_bits(uint32_t bits) {
    float f = __uint_as_float((bits >> 9) | 0x3F800000u) - 1.0f;
    const float lo = -0.99999994f;
    float val = fmaf(f, 2.0f, lo);
    val = fmaxf(lo, val);
    return 1.41421354f * erfinvf(val);
}

// ================= asm macros (all scalar operands) =================
__device__ __forceinline__ uint32_t smem_u32(const void* p) {
    uint32_t a;
    asm("{ .reg .u64 t; cvta.to.shared.u64 t, %1; cvt.u32.u64 %0, t; }" : "=r"(a) : "l"(p));
    return a;
}
#define LDSM4(r0, r1, r2, r3, addr) \
    asm volatile("ldmatrix.sync.aligned.m8n8.x4.shared.b16 {%0,%1,%2,%3}, [%4];" \
                 : "=r"(r0), "=r"(r1), "=r"(r2), "=r"(r3) : "r"(addr))
#define LDSM2(r0, r1, addr) \
    asm volatile("ldmatrix.sync.aligned.m8n8.x2.shared.b16 {%0,%1}, [%2];" \
                 : "=r"(r0), "=r"(r1) : "r"(addr))
#define MMAQ(cp, a0, a1, a2, a3, b0, b1) \
    asm volatile("mma.sync.aligned.m16n8k16.row.col.f32.bf16.bf16.f32 " \
                 "{%0,%1,%2,%3}, {%4,%5,%6,%7}, {%8,%9}, {%0,%1,%2,%3};" \
                 : "+f"(cp##0), "+f"(cp##1), "+f"(cp##2), "+f"(cp##3) \
                 : "r"(a0), "r"(a1), "r"(a2), "r"(a3), "r"(b0), "r"(b1))
#define CPA16(dst, src, pb) \
    asm volatile("cp.async.cg.shared.global [%0], [%1], 16, %2;" \
                 :: "r"(dst), "l"(src), "r"(pb) : "memory")
#define CPA_COMMIT() asm volatile("cp.async.commit_group;" ::: "memory")
#define CPA_WAIT0() asm volatile("cp.async.wait_group 0;" ::: "memory")
#define CPA_WAIT1() asm volatile("cp.async.wait_group 1;" ::: "memory")

__device__ __forceinline__ uint32_t pack_hi(float v0, float v1) {
    __nv_bfloat16 h0 = __float2bfloat16(v0), h1 = __float2bfloat16(v1);
    return (uint32_t)__bfloat16_as_ushort(h0) | ((uint32_t)__bfloat16_as_ushort(h1) << 16);
}
__device__ __forceinline__ uint32_t pack_lo(float v0, float v1) {
    __nv_bfloat16 h0 = __float2bfloat16(v0), h1 = __float2bfloat16(v1);
    __nv_bfloat16 l0 = __float2bfloat16(v0 - __bfloat162float(h0));
    __nv_bfloat16 l1 = __float2bfloat16(v1 - __bfloat162float(h1));
    return (uint32_t)__bfloat16_as_ushort(l0) | ((uint32_t)__bfloat16_as_ushort(l1) << 16);
}

// ================= permutation machinery (known clean) =================
__global__ void zero_hist_kernel() {
    int t = blockIdx.x * blockDim.x + threadIdx.x;
    if (t < 65536) g_hist[t] = 0u;
}
__global__ void hist_kernel(uint32_t k0, uint32_t k1, int P) {
    int p = blockIdx.x * blockDim.x + threadIdx.x;
    if (p >= P) return;
    uint32_t b = rbits32(k0, k1, (uint32_t)p);
    g_bits[p] = b;
    atomicAdd(&g_hist[b >> 16], 1u);
}
__global__ void scan_kernel() {
    __shared__ uint32_t part[1024];
    int t = threadIdx.x;
    uint32_t s = 0;
    #pragma unroll 8
    for (int i = 0; i < 64; i++) s += g_hist[t * 64 + i];
    part[t] = s;
    __syncthreads();
    for (int off = 1; off < 1024; off <<= 1) {
        uint32_t v = part[t];
        uint32_t add = (t >= off) ? part[t - off] : 0u;
        __syncthreads();
        part[t] = v + add;
        __syncthreads();
    }
    uint32_t run = (t == 0) ? 0u : part[t - 1];
    for (int i = 0; i < 64; i++) {
        int idx = t * 64 + i;
        g_bstart[idx] = run;
        g_cursor[idx] = run;
        run += g_hist[idx];
    }
    if (t == 1023) g_bstart[65536] = run;
}
__global__ void scatter_kernel(int P) {
    int p = blockIdx.x * blockDim.x + threadIdx.x;
    if (p >= P) return;
    uint32_t b = g_bits[p];
    uint32_t slot = atomicAdd(&g_cursor[b >> 16], 1u);
    g_slot[slot] = (((unsigned long long)(b & 0xFFFFu)) << 17) | (unsigned long long)p;
}
__global__ void rank_kernel(int P, int round) {
    int p = blockIdx.x * blockDim.x + threadIdx.x;
    if (p >= P) return;
    uint32_t b = g_bits[p];
    uint32_t hi = b >> 16;
    uint32_t s0 = g_bstart[hi], s1 = g_bstart[hi + 1];
    unsigned long long my = (((unsigned long long)(b & 0xFFFFu)) << 17) | (unsigned long long)p;
    uint32_t c = 0;
    for (uint32_t s = s0; s < s1; s++) c += (g_slot[s] < my) ? 1u : 0u;
    uint32_t rk = s0 + c;
    if (round == 0) g_rank1[p] = rk; else g_rank2[p] = rk;
}

// ================= gather + normalize -> bf16 hi/lo (stride 64) =================
__global__ void gather_kernel(const float* __restrict__ obs, const float* __restrict__ act,
                              const float* __restrict__ mu, const float* __restrict__ sd,
                              int n, int P) {
    int i = blockIdx.x * blockDim.x + threadIdx.x;
    if (i >= P) return;
    uint32_t q = g_rank2[g_rank1[i]];
    g_src[q] = (uint32_t)i;
    uint32_t* oh = reinterpret_cast<uint32_t*>(g_Ah + (size_t)q * 64);
    uint32_t* ol = reinterpret_cast<uint32_t*>(g_Al + (size_t)q * 64);
    if (i < n) {
        #pragma unroll
        for (int c = 0; c < CIN; c += 2) {
            float x0 = (c < OBS) ? obs[(size_t)i * OBS + c] : act[(size_t)i * ACTD + (c - OBS)];
            float x1 = (c + 1 < OBS) ? obs[(size_t)i * OBS + c + 1]
                                     : act[(size_t)i * ACTD + (c + 1 - OBS)];
            float v0 = (x0 - mu[c]) / sd[c];
            float v1 = (x1 - mu[c + 1]) / sd[c + 1];
            oh[c >> 1] = pack_hi(v0, v1);
            ol[c >> 1] = pack_lo(v0, v1);
        }
        #pragma unroll
        for (int c = CIN; c < 64; c += 2) { oh[c >> 1] = 0u; ol[c >> 1] = 0u; }
    } else {
        #pragma unroll
        for (int c = 0; c < 64; c += 2) { oh[c >> 1] = 0u; ol[c >> 1] = 0u; }
    }
}

// ====== weight transpose/convert: W[m][k][n] -> Wt[m][n_pad][k_pad] hi/lo ======
__global__ void prep_w(const float* __restrict__ W, int which,
                       int K, int N, int Nrows, int Kpad, int total) {
    int t = blockIdx.x * blockDim.x + threadIdx.x;
    if (t >= total) return;
    __nv_bfloat16* Wh;
    __nv_bfloat16* Wl;
    if (which == 0)      { Wh = g_W1h; Wl = g_W1l; }
    else if (which == 1) { Wh = g_W2h; Wl = g_W2l; }
    else if (which == 2) { Wh = g_W3h; Wl = g_W3l; }
    else                 { Wh = g_W4h; Wl = g_W4l; }
    int kp = t % Kpad;
    int rest = t / Kpad;
    int nn = rest % Nrows;
    int mm = rest / Nrows;
    float v = 0.0f;
    if (nn < N && kp < K) v = W[((size_t)mm * K + kp) * N + nn];
    __nv_bfloat16 h = __float2bfloat16(v);
    __nv_bfloat16 l = __float2bfloat16(v - __bfloat162float(h));
    Wh[t] = h;
    Wl[t] = l;
}

// stride of smem tile rows (bytes): 64 bf16 = 128B + 16B pad
#define ASTR 144
#define STAGE_BYTES 36864

// ======== hidden-layer GEMM, CTA tile 64x64, 2-stage cp.async pipeline ========
// layer 0: g_Ah(64) x W1 -> g_Bh ; layer 1: g_Bh(256) x W2 -> g_Ah ; layer 2: g_Ah(256) x W3 -> g_Bh
__global__ void __launch_bounds__(256, 1) gemm64(
    int layer, const float* __restrict__ bias, const int* __restrict__ elites,
    int r, int K, int N)
{
    const __nv_bfloat16* Ah;
    const __nv_bfloat16* Al;
    const __nv_bfloat16* Wh;
    const __nv_bfloat16* Wl;
    __nv_bfloat16* Ch;
    __nv_bfloat16* Cl;
    int strideA, wKpad;
    if (layer == 0) {
        Ah = g_Ah; Al = g_Al; Wh = g_W1h; Wl = g_W1l; Ch = g_Bh; Cl = g_Bl;
        strideA = 64; wKpad = 64;
    } else if (layer == 1) {
        Ah = g_Bh; Al = g_Bl; Wh = g_W2h; Wl = g_W2l; Ch = g_Ah; Cl = g_Al;
        strideA = 256; wKpad = 256;
    } else {
        Ah = g_Ah; Al = g_Al; Wh = g_W3h; Wl = g_W3l; Ch = g_Bh; Cl = g_Bl;
        strideA = 256; wKpad = 256;
    }

    // dynamic smem: 2 stages x [A hi 9216 | A lo 9216 | B hi 9216 | B lo 9216]
    extern __shared__ __align__(16) char sm[];
    uint32_t sb = smem_u32(sm);
    int tid = threadIdx.x, lane = tid & 31, wid = tid >> 5;
    int warp_m = wid >> 1, warp_n = wid & 1;
    int row0 = blockIdx.x * 64, col0 = blockIdx.y * 64;
    int m = blockIdx.z;
    int ev = elites[m];
    size_t qbase = (size_t)m * r;
    size_t wbase = (size_t)ev * 256 * wKpad;
    const float* biasm = bias + (size_t)ev * N;

    float c00 = 0.f, c01 = 0.f, c02 = 0.f, c03 = 0.f;
    float c10 = 0.f, c11 = 0.f, c12 = 0.f, c13 = 0.f;
    float c20 = 0.f, c21 = 0.f, c22 = 0.f, c23 = 0.f;
    float c30 = 0.f, c31 = 0.f, c32 = 0.f, c33 = 0.f;

    // per-lane ldmatrix addresses (within stage 0; add stage offset per chunk)
    uint32_t a_addr0 = sb + (uint32_t)((warp_m * 16 + (lane & 15)) * ASTR + (lane >> 4) * 16);
    uint32_t b_addr0 = sb + 18432u +
        (uint32_t)((warp_n * 32 + (lane & 7) + ((lane >> 4) << 3)) * ASTR + ((lane >> 3) & 1) * 16);

    // per-thread cp.async source/dest fragments
    int arr = tid >> 3, au = tid & 7;                 // A: row (0..31 per half), 16B seg
    int arr2 = (tid + 256) >> 3, au2 = (tid + 256) & 7;

    int chunks = (K + 63) >> 6;

    // issue chunk c into stage stg
#define ISSUE_CHUNK(c_, stg_) do { \
    uint32_t sbase = sb + (uint32_t)(stg_) * STAGE_BYTES; \
    int ccol = (c_) * 64; \
    { \
        int grow = row0 + arr; \
        uint32_t pb = (grow < r) ? 16u : 0u; \
        size_t gix = (qbase + (grow < r ? grow : 0)) * (size_t)strideA + ccol + au * 8; \
        uint32_t d = sbase + (uint32_t)(arr * ASTR + au * 16); \
        CPA16(d, Ah + gix, pb); \
        CPA16(d + 9216u, Al + gix, pb); \
    } \
    { \
        int grow = row0 + arr2; \
        uint32_t pb = (grow < r) ? 16u : 0u; \
        size_t gix = (qbase + (grow < r ? grow : 0)) * (size_t)strideA + ccol + au2 * 8; \
        uint32_t d = sbase + (uint32_t)(arr2 * ASTR + au2 * 16); \
        CPA16(d, Ah + gix, pb); \
        CPA16(d + 9216u, Al + gix, pb); \
    } \
    { \
        size_t gix = wbase + (size_t)(col0 + arr) * wKpad + ccol + au * 8; \
        uint32_t d = sbase + 18432u + (uint32_t)(arr * ASTR + au * 16); \
        CPA16(d, Wh + gix, 16u); \
        CPA16(d + 9216u, Wl + gix, 16u); \
    } \
    { \
        size_t gix = wbase + (size_t)(col0 + arr2) * wKpad + ccol + au2 * 8; \
        uint32_t d = sbase + 18432u + (uint32_t)(arr2 * ASTR + au2 * 16); \
        CPA16(d, Wh + gix, 16u); \
        CPA16(d + 9216u, Wl + gix, 16u); \
    } \
    CPA_COMMIT(); \
} while (0)

    ISSUE_CHUNK(0, 0);

    for (int c = 0; c < chunks; c++) {
        int stg = c & 1;
        if (c + 1 < chunks) {
            ISSUE_CHUNK(c + 1, (c + 1) & 1);
            CPA_WAIT1();
        } else {
            CPA_WAIT0();
        }
        __syncthreads();

        uint32_t soff = (uint32_t)stg * STAGE_BYTES;
        uint32_t a_addr = a_addr0 + soff;
        uint32_t b_addr = b_addr0 + soff;

        int steps = (K - c * 64 + 15) >> 4;
        if (steps > 4) steps = 4;
        for (int s = 0; s < steps; s++) {
            uint32_t ko = (uint32_t)(s * 32);
            uint32_t ah0, ah1, ah2, ah3, al0, al1, al2, al3;
            uint32_t bh0, bh1, bh2, bh3, bh4, bh5, bh6, bh7;
            uint32_t bl0, bl1, bl2, bl3, bl4, bl5, bl6, bl7;
            LDSM4(ah0, ah1, ah2, ah3, a_addr + ko);
            LDSM4(al0, al1, al2, al3, a_addr + 9216u + ko);
            LDSM4(bh0, bh1, bh2, bh3, b_addr + ko);
            LDSM4(bh4, bh5, bh6, bh7, b_addr + 16u * ASTR + ko);
            LDSM4(bl0, bl1, bl2, bl3, b_addr + 9216u + ko);
            LDSM4(bl4, bl5, bl6, bl7, b_addr + 9216u + 16u * ASTR + ko);
            MMAQ(c0, ah0, ah1, ah2, ah3, bh0, bh1);
            MMAQ(c1, ah0, ah1, ah2, ah3, bh2, bh3);
            MMAQ(c2, ah0, ah1, ah2, ah3, bh4, bh5);
            MMAQ(c3, ah0, ah1, ah2, ah3, bh6, bh7);
            MMAQ(c0, ah0, ah1, ah2, ah3, bl0, bl1);
            MMAQ(c1, ah0, ah1, ah2, ah3, bl2, bl3);
            MMAQ(c2, ah0, ah1, ah2, ah3, bl4, bl5);
            MMAQ(c3, ah0, ah1, ah2, ah3, bl6, bl7);
            MMAQ(c0, al0, al1, al2, al3, bh0, bh1);
            MMAQ(c1, al0, al1, al2, al3, bh2, bh3);
            MMAQ(c2, al0, al1, al2, al3, bh4, bh5);
            MMAQ(c3, al0, al1, al2, al3, bh6, bh7);
        }
        __syncthreads();
    }
#undef ISSUE_CHUNK

    // epilogue: bias + swish, split hi/lo, store (zeros pad cols >= N)
    int rlo = row0 + warp_m * 16 + (lane >> 2);
    int colb = col0 + warp_n * 32 + (lane & 3) * 2;
#define EPI64(cp, toff) do { \
    int col = colb + (toff); \
    if (rlo < r) { \
        float v0 = 0.0f, v1 = 0.0f; \
        if (col < N) { \
            float d0 = cp##0 + biasm[col]; \
            float d1 = cp##1 + biasm[col + 1]; \
            v0 = d0 / (1.0f + expf(-d0)); \
            v1 = d1 / (1.0f + expf(-d1)); \
        } \
        size_t o = ((qbase + rlo) * 256 + col) >> 1; \
        reinterpret_cast<uint32_t*>(Ch)[o] = pack_hi(v0, v1); \
        reinterpret_cast<uint32_t*>(Cl)[o] = pack_lo(v0, v1); \
    } \
    if (rlo + 8 < r) { \
        float v0 = 0.0f, v1 = 0.0f; \
        if (col < N) { \
            float d0 = cp##2 + biasm[col]; \
            float d1 = cp##3 + biasm[col + 1]; \
            v0 = d0 / (1.0f + expf(-d0)); \
            v1 = d1 / (1.0f + expf(-d1)); \
        } \
        size_t o = ((qbase + rlo + 8) * 256 + col) >> 1; \
        reinterpret_cast<uint32_t*>(Ch)[o] = pack_hi(v0, v1); \
        reinterpret_cast<uint32_t*>(Cl)[o] = pack_lo(v0, v1); \
    } \
} while (0)
    EPI64(c0, 0);
    EPI64(c1, 8);
    EPI64(c2, 16);
    EPI64(c3, 24);
#undef EPI64
}

// ======== layer-4 GEMM (N=66 padded 80) fused with sampling epilogue (unchanged) ========
__global__ void __launch_bounds__(256, 1) gemm_l4(
    const float* __restrict__ b4, const int* __restrict__ elites,
    int r, int K,
    const float* __restrict__ obs, float* __restrict__ out, int n)
{
    const __nv_bfloat16* Ah = g_Bh;
    const __nv_bfloat16* Al = g_Bl;
    const __nv_bfloat16* Wh = g_W4h;
    const __nv_bfloat16* Wl = g_W4l;

    __shared__ __align__(16) char sm[41472];
    uint32_t sb = smem_u32(sm);
    int tid = threadIdx.x, lane = tid & 31, wid = tid >> 5;
    int warp_m = wid >> 1, warp_n = wid & 1;
    int row0 = blockIdx.x * 64;
    int m = blockIdx.y;
    int ev = elites[m];
    size_t qbase = (size_t)m * r;
    size_t wbase = (size_t)ev * 80 * 256;

    float d00 = 0.f, d01 = 0.f, d02 = 0.f, d03 = 0.f;
    float d10 = 0.f, d11 = 0.f, d12 = 0.f, d13 = 0.f;
    float d20 = 0.f, d21 = 0.f, d22 = 0.f, d23 = 0.f;
    float d30 = 0.f, d31 = 0.f, d32 = 0.f, d33 = 0.f;
    float d40 = 0.f, d41 = 0.f, d42 = 0.f, d43 = 0.f;

    uint32_t a_addr = sb + (uint32_t)((warp_m * 16 + (lane & 15)) * ASTR + (lane >> 4) * 16);
    uint32_t b_addr = sb + 18432u +
        (uint32_t)((warp_n * 40 + (lane & 7) + ((lane >> 4) << 3)) * ASTR + ((lane >> 3) & 1) * 16);
    uint32_t b2_addr = sb + 18432u +
        (uint32_t)((warp_n * 40 + 32 + (lane & 7)) * ASTR + ((lane >> 3) & 1) * 16);

    int chunks = (K + 63) >> 6;
    for (int c = 0; c < chunks; c++) {
        int ccol = c * 64;
        #pragma unroll
        for (int i = 0; i < 2; i++) {
            int idx = tid + i * 256;
            int rr = idx >> 3, u = idx & 7;
            int grow = row0 + rr;
            uint4 vh = make_uint4(0, 0, 0, 0), vl = make_uint4(0, 0, 0, 0);
            if (grow < r) {
                size_t g = (qbase + grow) * 256 + ccol + u * 8;
                vh = *reinterpret_cast<const uint4*>(Ah + g);
                vl = *reinterpret_cast<const uint4*>(Al + g);
            }
            *reinterpret_cast<uint4*>(sm + rr * ASTR + u * 16) = vh;
            *reinterpret_cast<uint4*>(sm + 9216 + rr * ASTR + u * 16) = vl;
        }
        #pragma unroll
        for (int i = 0; i < 3; i++) {
            int idx = tid + i * 256;
            if (idx < 640) {
                int nr = idx >> 3, u = idx & 7;
                size_t g = wbase + (size_t)nr * 256 + ccol + u * 8;
                *reinterpret_cast<uint4*>(sm + 18432 + nr * ASTR + u * 16) =
                    *reinterpret_cast<const uint4*>(Wh + g);
                *reinterpret_cast<uint4*>(sm + 29952 + nr * ASTR + u * 16) =
                    *reinterpret_cast<const uint4*>(Wl + g);
            }
        }
        __syncthreads();

        int steps = (K - ccol + 15) >> 4;
        if (steps > 4) steps = 4;
        for (int s = 0; s < steps; s++) {
            uint32_t ko = (uint32_t)(s * 32);
            uint32_t ah0, ah1, ah2, ah3, al0, al1, al2, al3;
            uint32_t bh0, bh1, bh2, bh3, bh4, bh5, bh6, bh7;
            uint32_t bl0, bl1, bl2, bl3, bl4, bl5, bl6, bl7;
            uint32_t p0, p1, q0, q1;
            LDSM4(ah0, ah1, ah2, ah3, a_addr + ko);
            LDSM4(al0, al1, al2, al3, a_addr + 9216u + ko);
            LDSM4(bh0, bh1, bh2, bh3, b_addr + ko);
            LDSM4(bh4, bh5, bh6, bh7, b_addr + 16u * ASTR + ko);
            LDSM4(bl0, bl1, bl2, bl3, b_addr + 11520u + ko);
            LDSM4(bl4, bl5, bl6, bl7, b_addr + 11520u + 16u * ASTR + ko);
            LDSM2(p0, p1, b2_addr + ko);
            LDSM2(q0, q1, b2_addr + 11520u + ko);
            MMAQ(d0, ah0, ah1, ah2, ah3, bh0, bh1);
            MMAQ(d1, ah0, ah1, ah2, ah3, bh2, bh3);
            MMAQ(d2, ah0, ah1, ah2, ah3, bh4, bh5);
            MMAQ(d3, ah0, ah1, ah2, ah3, bh6, bh7);
            MMAQ(d4, ah0, ah1, ah2, ah3, p0, p1);
            MMAQ(d0, ah0, ah1, ah2, ah3, bl0, bl1);
            MMAQ(d1, ah0, ah1, ah2, ah3, bl2, bl3);
            MMAQ(d2, ah0, ah1, ah2, ah3, bl4, bl5);
            MMAQ(d3, ah0, ah1, ah2, ah3, bl6, bl7);
            MMAQ(d4, ah0, ah1, ah2, ah3, q0, q1);
            MMAQ(d0, al0, al1, al2, al3, bh0, bh1);
            MMAQ(d1, al0, al1, al2, al3, bh2, bh3);
            MMAQ(d2, al0, al1, al2, al3, bh4, bh5);
            MMAQ(d3, al0, al1, al2, al3, bh6, bh7);
            MMAQ(d4, al0, al1, al2, al3, p0, p1);
        }
        __syncthreads();
    }

    // stage accumulators to smem [64][80] f32
    float* stg = reinterpret_cast<float*>(sm);
    {
        int rlo = warp_m * 16 + (lane >> 2);
        int colb = warp_n * 40 + (lane & 3) * 2;
#define STG4(cp, toff) do { \
        int col = colb + (toff); \
        stg[rlo * 80 + col]           = cp##0; \
        stg[rlo * 80 + col + 1]       = cp##1; \
        stg[(rlo + 8) * 80 + col]     = cp##2; \
        stg[(rlo + 8) * 80 + col + 1] = cp##3; \
} while (0)
        STG4(d0, 0);
        STG4(d1, 8);
        STG4(d2, 16);
        STG4(d3, 24);
        STG4(d4, 32);
#undef STG4
    }
    __syncthreads();

    // per-row sampling / scatter / reward / terminal
    if (tid < 64) {
        int j = row0 + tid;
        if (j < r) {
            size_t q = qbase + j;
            int i = (int)g_src[q];
            if (i < n) {
                const float* bm = b4 + (size_t)ev * 66;
                const float* row = stg + tid * 80;
                uint32_t fbase = ((uint32_t)ev * (uint32_t)r + (uint32_t)j) * 33u;
                float sumsq = 0.0f;
                for (int d = 0; d < 33; d++) {
                    float mean = row[d] + bm[d];
                    float lv = row[33 + d] + bm[33 + d];
                    lv = 0.5f - softplusf(0.5f - lv);
                    lv = -10.0f + softplusf(lv + 10.0f);
                    float sd = expf(0.5f * lv);
                    float nz = normal_from_bits(rbits32(0u, 0u, fbase + (uint32_t)d));
                    float s = fmaf(nz, sd, mean);
                    if (d < 32) {
                        float no = s + obs[(size_t)i * OBS + d];
                        out[(size_t)i * OBS + d] = no;
                        sumsq += no * no;
                    } else {
                        out[(size_t)n * OBS + i] = s;
                    }
                }
                out[(size_t)n * (OBS + 1) + i] = (sqrtf(sumsq) > 50.0f) ? 1.0f : 0.0f;
            }
        }
    }
}

// ================= launch =================
extern "C" void kernel_launch(void* const* d_in, const int* in_sizes, int n_in,
                              void* d_out, int out_size) {
    const float* obs = (const float*)d_in[0];
    const float* act = (const float*)d_in[1];
    const float* mu  = (const float*)d_in[2];
    const float* sdv = (const float*)d_in[3];
    const float* W1  = (const float*)d_in[4];
    const float* b1  = (const float*)d_in[5];
    const float* W2  = (const float*)d_in[6];
    const float* b2  = (const float*)d_in[7];
    const float* W3  = (const float*)d_in[8];
    const float* b3  = (const float*)d_in[9];
    const float* W4  = (const float*)d_in[10];
    const float* b4  = (const float*)d_in[11];
    const int* elites = (const int*)d_in[12];

    int n = in_sizes[0] / OBS;
    int e = in_sizes[12];
    int r = (n - 1) / e + 1;
    int P = e * r;
    if (P > PMAX) P = PMAX;
    int Mm = in_sizes[4] / (CIN * HID);
    if (Mm > MMAX) Mm = MMAX;

    uint32_t nk0, nk1, s1a, s1b, s2a, s2b;
    threefry2x32(0u, 0u, 0u, 0u, nk0, nk1);
    threefry2x32(0u, 0u, 0u, 1u, s1a, s1b);
    threefry2x32(nk0, nk1, 0u, 1u, s2a, s2b);

    const int TB = 256;
    int gb = (P + TB - 1) / TB;

    // weight transpose/convert (device-side target selection)
    {
        int t1 = Mm * 256 * 64;
        prep_w<<<(t1 + 255) / 256, 256>>>(W1, 0, CIN, HID, 256, 64, t1);
        int t2 = Mm * 256 * 256;
        prep_w<<<(t2 + 255) / 256, 256>>>(W2, 1, HID, HID, 256, 256, t2);
        prep_w<<<(t2 + 255) / 256, 256>>>(W3, 2, HID, HID, 256, 256, t2);
        int t4 = Mm * 80 * 256;
        prep_w<<<(t4 + 255) / 256, 256>>>(W4, 3, HID, 2 * DOUTD, 80, 256, t4);
    }

    // permutation (two stable-rank rounds)
    zero_hist_kernel<<<256, 256>>>();
    hist_kernel<<<gb, TB>>>(s1a, s1b, P);
    scan_kernel<<<1, 1024>>>();
    scatter_kernel<<<gb, TB>>>(P);
    rank_kernel<<<gb, TB>>>(P, 0);
    zero_hist_kernel<<<256, 256>>>();
    hist_kernel<<<gb, TB>>>(s2a, s2b, P);
    scan_kernel<<<1, 1024>>>();
    scatter_kernel<<<gb, TB>>>(P);
    rank_kernel<<<gb, TB>>>(P, 1);

    gather_kernel<<<gb, TB>>>(obs, act, mu, sdv, n, P);

    cudaFuncSetAttribute(gemm64, cudaFuncAttributeMaxDynamicSharedMemorySize,
                         2 * STAGE_BYTES);

    int mt = (r + 63) / 64;
    dim3 gridH(mt, 4, e);  // 4 N-tiles of 64 cover 200 (padded 256)
    gemm64<<<gridH, 256, 2 * STAGE_BYTES>>>(0, b1, elites, r, CIN, HID);
    gemm64<<<gridH, 256, 2 * STAGE_BYTES>>>(1, b2, elites, r, HID, HID);
    gemm64<<<gridH, 256, 2 * STAGE_BYTES>>>(2, b3, elites, r, HID, HID);
    dim3 gridL4(mt, e);
    gemm_l4<<<gridL4, 256>>>(b4, elites, r, HID, obs, (float*)d_out, n);
}

// round 9
// speedup vs baseline: 1.9591x; 1.0720x over previous
#include <cuda_runtime.h>
#include <cuda_bf16.h>
#include <stdint.h>

#define OBS   32
#define ACTD  8
#define CIN   40
#define HID   200
#define DOUTD 33
#define PMAX  100352
#define MMAX  8

// ================= scratch (device globals; referenced ONLY from device code) =========
__device__ uint32_t g_bits[PMAX];
__device__ unsigned long long g_slot[PMAX];
__device__ uint32_t g_hist[65536];
__device__ uint32_t g_bstart[65537];
__device__ uint32_t g_cursor[65536];
__device__ uint32_t g_rank1[PMAX];
__device__ uint32_t g_rank2[PMAX];
__device__ uint32_t g_src[PMAX];
// activations, stride 256 bf16 (hi/lo split). L1 input lives in g_Ah/g_Al at stride 64.
__device__ __nv_bfloat16 g_Ah[(size_t)PMAX * 256];
__device__ __nv_bfloat16 g_Al[(size_t)PMAX * 256];
__device__ __nv_bfloat16 g_Bh[(size_t)PMAX * 256];
__device__ __nv_bfloat16 g_Bl[(size_t)PMAX * 256];
// transposed/split weights: [m][n_pad][k_pad]
__device__ __nv_bfloat16 g_W1h[MMAX * 256 * 64],  g_W1l[MMAX * 256 * 64];
__device__ __nv_bfloat16 g_W2h[MMAX * 256 * 256], g_W2l[MMAX * 256 * 256];
__device__ __nv_bfloat16 g_W3h[MMAX * 256 * 256], g_W3l[MMAX * 256 * 256];
__device__ __nv_bfloat16 g_W4h[MMAX * 80 * 256],  g_W4l[MMAX * 80 * 256];

// ================= threefry (JAX partitionable) =================
__host__ __device__ __forceinline__ uint32_t rotl32(uint32_t v, int d) {
    return (v << d) | (v >> (32 - d));
}
__host__ __device__ __forceinline__ void threefry2x32(uint32_t k0, uint32_t k1,
                                                      uint32_t x0, uint32_t x1,
                                                      uint32_t& o0, uint32_t& o1) {
    uint32_t ks2 = k0 ^ k1 ^ 0x1BD11BDAu;
    x0 += k0; x1 += k1;
#define TFR(a) x0 += x1; x1 = rotl32(x1, a); x1 ^= x0;
    TFR(13) TFR(15) TFR(26) TFR(6)
    x0 += k1;  x1 += ks2 + 1u;
    TFR(17) TFR(29) TFR(16) TFR(24)
    x0 += ks2; x1 += k0 + 2u;
    TFR(13) TFR(15) TFR(26) TFR(6)
    x0 += k0;  x1 += k1 + 3u;
    TFR(17) TFR(29) TFR(16) TFR(24)
    x0 += k1;  x1 += ks2 + 4u;
    TFR(13) TFR(15) TFR(26) TFR(6)
    x0 += ks2; x1 += k0 + 5u;
#undef TFR
    o0 = x0; o1 = x1;
}
__device__ __forceinline__ uint32_t rbits32(uint32_t k0, uint32_t k1, uint32_t idx) {
    uint32_t a, b;
    threefry2x32(k0, k1, 0u, idx, a, b);
    return a ^ b;
}
__device__ __forceinline__ float softplusf(float x) {
    return fmaxf(x, 0.0f) + log1pf(expf(-fabsf(x)));
}
__device__ __forceinline__ float normal_from_bits(uint32_t bits) {
    float f = __uint_as_float((bits >> 9) | 0x3F800000u) - 1.0f;
    const float lo = -0.99999994f;
    float val = fmaf(f, 2.0f, lo);
    val = fmaxf(lo, val);
    return 1.41421354f * erfinvf(val);
}

// ================= asm macros =================
__device__ __forceinline__ uint32_t smem_u32(const void* p) {
    uint32_t a;
    asm("{ .reg .u64 t; cvta.to.shared.u64 t, %1; cvt.u32.u64 %0, t; }" : "=r"(a) : "l"(p));
    return a;
}
#define LDSM4(r0, r1, r2, r3, addr) \
    asm volatile("ldmatrix.sync.aligned.m8n8.x4.shared.b16 {%0,%1,%2,%3}, [%4];" \
                 : "=r"(r0), "=r"(r1), "=r"(r2), "=r"(r3) : "r"(addr))
#define LDSM4A(rr, addr) LDSM4((rr)[0], (rr)[1], (rr)[2], (rr)[3], addr)
#define LDSM2(r0, r1, addr) \
    asm volatile("ldmatrix.sync.aligned.m8n8.x2.shared.b16 {%0,%1}, [%2];" \
                 : "=r"(r0), "=r"(r1) : "r"(addr))
#define MMAQ(cp, a0, a1, a2, a3, b0, b1) \
    asm volatile("mma.sync.aligned.m16n8k16.row.col.f32.bf16.bf16.f32 " \
                 "{%0,%1,%2,%3}, {%4,%5,%6,%7}, {%8,%9}, {%0,%1,%2,%3};" \
                 : "+f"(cp##0), "+f"(cp##1), "+f"(cp##2), "+f"(cp##3) \
                 : "r"(a0), "r"(a1), "r"(a2), "r"(a3), "r"(b0), "r"(b1))
#define MMA4(c, a, b0, b1) \
    asm volatile("mma.sync.aligned.m16n8k16.row.col.f32.bf16.bf16.f32 " \
                 "{%0,%1,%2,%3}, {%4,%5,%6,%7}, {%8,%9}, {%0,%1,%2,%3};" \
                 : "+f"((c)[0]), "+f"((c)[1]), "+f"((c)[2]), "+f"((c)[3]) \
                 : "r"((a)[0]), "r"((a)[1]), "r"((a)[2]), "r"((a)[3]), "r"(b0), "r"(b1))
#define CPA16(dst, src, pb) \
    asm volatile("cp.async.cg.shared.global [%0], [%1], 16, %2;" \
                 :: "r"(dst), "l"(src), "r"(pb) : "memory")
#define CPA_COMMIT() asm volatile("cp.async.commit_group;" ::: "memory")
#define CPA_WAIT0() asm volatile("cp.async.wait_group 0;" ::: "memory")
#define CPA_WAIT1() asm volatile("cp.async.wait_group 1;" ::: "memory")

__device__ __forceinline__ uint32_t pack_hi(float v0, float v1) {
    __nv_bfloat16 h0 = __float2bfloat16(v0), h1 = __float2bfloat16(v1);
    return (uint32_t)__bfloat16_as_ushort(h0) | ((uint32_t)__bfloat16_as_ushort(h1) << 16);
}
__device__ __forceinline__ uint32_t pack_lo(float v0, float v1) {
    __nv_bfloat16 h0 = __float2bfloat16(v0), h1 = __float2bfloat16(v1);
    __nv_bfloat16 l0 = __float2bfloat16(v0 - __bfloat162float(h0));
    __nv_bfloat16 l1 = __float2bfloat16(v1 - __bfloat162float(h1));
    return (uint32_t)__bfloat16_as_ushort(l0) | ((uint32_t)__bfloat16_as_ushort(l1) << 16);
}

// ================= permutation machinery (known clean) =================
__global__ void zero_hist_kernel() {
    int t = blockIdx.x * blockDim.x + threadIdx.x;
    if (t < 65536) g_hist[t] = 0u;
}
__global__ void hist_kernel(uint32_t k0, uint32_t k1, int P) {
    int p = blockIdx.x * blockDim.x + threadIdx.x;
    if (p >= P) return;
    uint32_t b = rbits32(k0, k1, (uint32_t)p);
    g_bits[p] = b;
    atomicAdd(&g_hist[b >> 16], 1u);
}
__global__ void scan_kernel() {
    __shared__ uint32_t part[1024];
    int t = threadIdx.x;
    uint32_t s = 0;
    #pragma unroll 8
    for (int i = 0; i < 64; i++) s += g_hist[t * 64 + i];
    part[t] = s;
    __syncthreads();
    for (int off = 1; off < 1024; off <<= 1) {
        uint32_t v = part[t];
        uint32_t add = (t >= off) ? part[t - off] : 0u;
        __syncthreads();
        part[t] = v + add;
        __syncthreads();
    }
    uint32_t run = (t == 0) ? 0u : part[t - 1];
    for (int i = 0; i < 64; i++) {
        int idx = t * 64 + i;
        g_bstart[idx] = run;
        g_cursor[idx] = run;
        run += g_hist[idx];
    }
    if (t == 1023) g_bstart[65536] = run;
}
__global__ void scatter_kernel(int P) {
    int p = blockIdx.x * blockDim.x + threadIdx.x;
    if (p >= P) return;
    uint32_t b = g_bits[p];
    uint32_t slot = atomicAdd(&g_cursor[b >> 16], 1u);
    g_slot[slot] = (((unsigned long long)(b & 0xFFFFu)) << 17) | (unsigned long long)p;
}
__global__ void rank_kernel(int P, int round) {
    int p = blockIdx.x * blockDim.x + threadIdx.x;
    if (p >= P) return;
    uint32_t b = g_bits[p];
    uint32_t hi = b >> 16;
    uint32_t s0 = g_bstart[hi], s1 = g_bstart[hi + 1];
    unsigned long long my = (((unsigned long long)(b & 0xFFFFu)) << 17) | (unsigned long long)p;
    uint32_t c = 0;
    for (uint32_t s = s0; s < s1; s++) c += (g_slot[s] < my) ? 1u : 0u;
    uint32_t rk = s0 + c;
    if (round == 0) g_rank1[p] = rk; else g_rank2[p] = rk;
}

// ================= gather + normalize -> bf16 hi/lo (stride 64) =================
__global__ void gather_kernel(const float* __restrict__ obs, const float* __restrict__ act,
                              const float* __restrict__ mu, const float* __restrict__ sd,
                              int n, int P) {
    int i = blockIdx.x * blockDim.x + threadIdx.x;
    if (i >= P) return;
    uint32_t q = g_rank2[g_rank1[i]];
    g_src[q] = (uint32_t)i;
    uint32_t* oh = reinterpret_cast<uint32_t*>(g_Ah + (size_t)q * 64);
    uint32_t* ol = reinterpret_cast<uint32_t*>(g_Al + (size_t)q * 64);
    if (i < n) {
        #pragma unroll
        for (int c = 0; c < CIN; c += 2) {
            float x0 = (c < OBS) ? obs[(size_t)i * OBS + c] : act[(size_t)i * ACTD + (c - OBS)];
            float x1 = (c + 1 < OBS) ? obs[(size_t)i * OBS + c + 1]
                                     : act[(size_t)i * ACTD + (c + 1 - OBS)];
            float v0 = (x0 - mu[c]) / sd[c];
            float v1 = (x1 - mu[c + 1]) / sd[c + 1];
            oh[c >> 1] = pack_hi(v0, v1);
            ol[c >> 1] = pack_lo(v0, v1);
        }
        #pragma unroll
        for (int c = CIN; c < 64; c += 2) { oh[c >> 1] = 0u; ol[c >> 1] = 0u; }
    } else {
        #pragma unroll
        for (int c = 0; c < 64; c += 2) { oh[c >> 1] = 0u; ol[c >> 1] = 0u; }
    }
}

// ====== weight transpose/convert: W[m][k][n] -> Wt[m][n_pad][k_pad] hi/lo ======
__global__ void prep_w(const float* __restrict__ W, int which,
                       int K, int N, int Nrows, int Kpad, int total) {
    int t = blockIdx.x * blockDim.x + threadIdx.x;
    if (t >= total) return;
    __nv_bfloat16* Wh;
    __nv_bfloat16* Wl;
    if (which == 0)      { Wh = g_W1h; Wl = g_W1l; }
    else if (which == 1) { Wh = g_W2h; Wl = g_W2l; }
    else if (which == 2) { Wh = g_W3h; Wl = g_W3l; }
    else                 { Wh = g_W4h; Wl = g_W4l; }
    int kp = t % Kpad;
    int rest = t / Kpad;
    int nn = rest % Nrows;
    int mm = rest / Nrows;
    float v = 0.0f;
    if (nn < N && kp < K) v = W[((size_t)mm * K + kp) * N + nn];
    __nv_bfloat16 h = __float2bfloat16(v);
    __nv_bfloat16 l = __float2bfloat16(v - __bfloat162float(h));
    Wh[t] = h;
    Wl[t] = l;
}

// stride of smem tile rows (bytes): 64 bf16 = 128B + 16B pad
#define ASTR 144

// ======== hidden-layer GEMM, CTA tile 128 x (NT*16), 2-stage cp.async pipeline ========
// NT = number of n8-atoms per warp (warp tile = 32 x NT*8, 2 warp_n groups).
// layer 0: g_Ah(64) x W1 -> g_Bh ; layer 1: g_Bh(256) x W2 -> g_Ah ; layer 2: g_Ah(256) x W3 -> g_Bh
template <int NT>
__global__ void __launch_bounds__(256, 2) gemm128(
    int layer, int col00, const float* __restrict__ bias, const int* __restrict__ elites,
    int r, int K, int N)
{
    constexpr int BROWS = NT * 16;                 // B smem rows (CTA N extent)
    constexpr int ABYTES = 128 * ASTR;             // 18432 per A buffer
    constexpr int BBYTES = BROWS * ASTR;           // per B buffer
    constexpr int STG = 2 * ABYTES + 2 * BBYTES;   // stage bytes

    const __nv_bfloat16* Ah;
    const __nv_bfloat16* Al;
    const __nv_bfloat16* Wh;
    const __nv_bfloat16* Wl;
    __nv_bfloat16* Ch;
    __nv_bfloat16* Cl;
    int strideA, wKpad;
    if (layer == 0) {
        Ah = g_Ah; Al = g_Al; Wh = g_W1h; Wl = g_W1l; Ch = g_Bh; Cl = g_Bl;
        strideA = 64; wKpad = 64;
    } else if (layer == 1) {
        Ah = g_Bh; Al = g_Bl; Wh = g_W2h; Wl = g_W2l; Ch = g_Ah; Cl = g_Al;
        strideA = 256; wKpad = 256;
    } else {
        Ah = g_Ah; Al = g_Al; Wh = g_W3h; Wl = g_W3l; Ch = g_Bh; Cl = g_Bl;
        strideA = 256; wKpad = 256;
    }

    extern __shared__ __align__(16) char sm[];
    uint32_t sb = smem_u32(sm);
    int tid = threadIdx.x, lane = tid & 31, wid = tid >> 5;
    int warp_m = wid >> 1, warp_n = wid & 1;       // 4 x 2 warp grid
    int row0 = blockIdx.x * 128;
    int c0col = col00 + blockIdx.y * 64;           // CTA first column
    int m = blockIdx.z;
    int ev = elites[m];
    size_t qbase = (size_t)m * r;
    size_t wbase = (size_t)ev * 256 * wKpad;
    const float* biasm = bias + (size_t)ev * N;

    float acc[2][NT][4];
    #pragma unroll
    for (int i = 0; i < 2; i++)
        #pragma unroll
        for (int j = 0; j < NT; j++)
            #pragma unroll
            for (int x = 0; x < 4; x++) acc[i][j][x] = 0.0f;

    // ldmatrix per-lane addresses (stage 0 base)
    uint32_t a_addr0 = sb + (uint32_t)((warp_m * 32 + (lane & 15)) * ASTR + (lane >> 4) * 16);
    uint32_t b_addr0;
    if (NT == 4) {
        b_addr0 = sb + 2u * ABYTES +
            (uint32_t)((warp_n * 32 + (lane & 7) + ((lane >> 4) << 3)) * ASTR +
                       ((lane >> 3) & 1) * 16);
    } else {
        b_addr0 = sb + 2u * ABYTES +
            (uint32_t)((warp_n * 8 + (lane & 7)) * ASTR + ((lane >> 3) & 1) * 16);
    }

    int chunks = (K + 63) >> 6;

#define ISSUE_CHUNK(c_, stg_) do { \
    uint32_t sbase = sb + (uint32_t)(stg_) * STG; \
    int ccol = (c_) * 64; \
    _Pragma("unroll") \
    for (int i = 0; i < 4; i++) { \
        int idx = tid + i * 256; \
        int rr = idx >> 3, u = idx & 7; \
        int grow = row0 + rr; \
        uint32_t pb = (grow < r) ? 16u : 0u; \
        size_t gix = (qbase + (grow < r ? grow : 0)) * (size_t)strideA + ccol + u * 8; \
        uint32_t d = sbase + (uint32_t)(rr * ASTR + u * 16); \
        CPA16(d, Ah + gix, pb); \
        CPA16(d + (uint32_t)ABYTES, Al + gix, pb); \
    } \
    _Pragma("unroll") \
    for (int i = 0; i < (BROWS * 8 + 255) / 256; i++) { \
        int idx = tid + i * 256; \
        if (idx < BROWS * 8) { \
            int nr = idx >> 3, u = idx & 7; \
            size_t gix = wbase + (size_t)(c0col + nr) * wKpad + ccol + u * 8; \
            uint32_t d = sbase + 2u * ABYTES + (uint32_t)(nr * ASTR + u * 16); \
            CPA16(d, Wh + gix, 16u); \
            CPA16(d + (uint32_t)BBYTES, Wl + gix, 16u); \
        } \
    } \
    CPA_COMMIT(); \
} while (0)

    ISSUE_CHUNK(0, 0);

    for (int c = 0; c < chunks; c++) {
        int stg = c & 1;
        if (c + 1 < chunks) {
            ISSUE_CHUNK(c + 1, (c + 1) & 1);
            CPA_WAIT1();
        } else {
            CPA_WAIT0();
        }
        __syncthreads();

        uint32_t soff = (uint32_t)stg * STG;
        uint32_t a_addr = a_addr0 + soff;
        uint32_t b_addr = b_addr0 + soff;

        int steps = (K - c * 64 + 15) >> 4;
        if (steps > 4) steps = 4;
        for (int s = 0; s < steps; s++) {
            uint32_t ko = (uint32_t)(s * 32);
            uint32_t ah[2][4], al[2][4];
            LDSM4A(ah[0], a_addr + ko);
            LDSM4A(ah[1], a_addr + 16u * ASTR + ko);
            LDSM4A(al[0], a_addr + (uint32_t)ABYTES + ko);
            LDSM4A(al[1], a_addr + (uint32_t)ABYTES + 16u * ASTR + ko);
            if (NT == 4) {
                uint32_t bh[2][4], bl[2][4];
                LDSM4A(bh[0], b_addr + ko);
                LDSM4A(bh[1], b_addr + 16u * ASTR + ko);
                LDSM4A(bl[0], b_addr + (uint32_t)BBYTES + ko);
                LDSM4A(bl[1], b_addr + (uint32_t)BBYTES + 16u * ASTR + ko);
                // term-major: hi*hi over all 8 quads, then hi*lo, then lo*hi
                #pragma unroll
                for (int mi = 0; mi < 2; mi++)
                    #pragma unroll
                    for (int nn = 0; nn < 4; nn++)
                        MMA4(acc[mi][nn], ah[mi], bh[nn >> 1][(nn & 1) * 2],
                             bh[nn >> 1][(nn & 1) * 2 + 1]);
                #pragma unroll
                for (int mi = 0; mi < 2; mi++)
                    #pragma unroll
                    for (int nn = 0; nn < 4; nn++)
                        MMA4(acc[mi][nn], ah[mi], bl[nn >> 1][(nn & 1) * 2],
                             bl[nn >> 1][(nn & 1) * 2 + 1]);
                #pragma unroll
                for (int mi = 0; mi < 2; mi++)
                    #pragma unroll
                    for (int nn = 0; nn < 4; nn++)
                        MMA4(acc[mi][nn], al[mi], bh[nn >> 1][(nn & 1) * 2],
                             bh[nn >> 1][(nn & 1) * 2 + 1]);
            } else {
                uint32_t bh0, bh1, bl0, bl1;
                LDSM2(bh0, bh1, b_addr + ko);
                LDSM2(bl0, bl1, b_addr + (uint32_t)BBYTES + ko);
                #pragma unroll
                for (int mi = 0; mi < 2; mi++)
                    MMA4(acc[mi][0], ah[mi], bh0, bh1);
                #pragma unroll
                for (int mi = 0; mi < 2; mi++)
                    MMA4(acc[mi][0], ah[mi], bl0, bl1);
                #pragma unroll
                for (int mi = 0; mi < 2; mi++)
                    MMA4(acc[mi][0], al[mi], bh0, bh1);
            }
        }
        __syncthreads();
    }
#undef ISSUE_CHUNK

    // epilogue: bias + swish, split hi/lo, store (zeros for cols >= N)
    #pragma unroll
    for (int mi = 0; mi < 2; mi++) {
        int rlo = row0 + warp_m * 32 + mi * 16 + (lane >> 2);
        #pragma unroll
        for (int nn = 0; nn < NT; nn++) {
            int col = c0col + warp_n * (NT * 8) + nn * 8 + (lane & 3) * 2;
            if (rlo < r) {
                float v0 = 0.0f, v1 = 0.0f;
                if (col < N) {
                    float d0 = acc[mi][nn][0] + biasm[col];
                    float d1 = acc[mi][nn][1] + biasm[col + 1];
                    v0 = d0 / (1.0f + expf(-d0));
                    v1 = d1 / (1.0f + expf(-d1));
                }
                size_t o = ((qbase + rlo) * 256 + col) >> 1;
                reinterpret_cast<uint32_t*>(Ch)[o] = pack_hi(v0, v1);
                reinterpret_cast<uint32_t*>(Cl)[o] = pack_lo(v0, v1);
            }
            if (rlo + 8 < r) {
                float v0 = 0.0f, v1 = 0.0f;
                if (col < N) {
                    float d0 = acc[mi][nn][2] + biasm[col];
                    float d1 = acc[mi][nn][3] + biasm[col + 1];
                    v0 = d0 / (1.0f + expf(-d0));
                    v1 = d1 / (1.0f + expf(-d1));
                }
                size_t o = ((qbase + rlo + 8) * 256 + col) >> 1;
                reinterpret_cast<uint32_t*>(Ch)[o] = pack_hi(v0, v1);
                reinterpret_cast<uint32_t*>(Cl)[o] = pack_lo(v0, v1);
            }
        }
    }
}

// ======== layer-4 GEMM (N=66 padded 80) fused with sampling epilogue (unchanged) ========
__global__ void __launch_bounds__(256, 1) gemm_l4(
    const float* __restrict__ b4, const int* __restrict__ elites,
    int r, int K,
    const float* __restrict__ obs, float* __restrict__ out, int n)
{
    const __nv_bfloat16* Ah = g_Bh;
    const __nv_bfloat16* Al = g_Bl;
    const __nv_bfloat16* Wh = g_W4h;
    const __nv_bfloat16* Wl = g_W4l;

    __shared__ __align__(16) char sm[41472];
    uint32_t sb = smem_u32(sm);
    int tid = threadIdx.x, lane = tid & 31, wid = tid >> 5;
    int warp_m = wid >> 1, warp_n = wid & 1;
    int row0 = blockIdx.x * 64;
    int m = blockIdx.y;
    int ev = elites[m];
    size_t qbase = (size_t)m * r;
    size_t wbase = (size_t)ev * 80 * 256;

    float d00 = 0.f, d01 = 0.f, d02 = 0.f, d03 = 0.f;
    float d10 = 0.f, d11 = 0.f, d12 = 0.f, d13 = 0.f;
    float d20 = 0.f, d21 = 0.f, d22 = 0.f, d23 = 0.f;
    float d30 = 0.f, d31 = 0.f, d32 = 0.f, d33 = 0.f;
    float d40 = 0.f, d41 = 0.f, d42 = 0.f, d43 = 0.f;

    uint32_t a_addr = sb + (uint32_t)((warp_m * 16 + (lane & 15)) * ASTR + (lane >> 4) * 16);
    uint32_t b_addr = sb + 18432u +
        (uint32_t)((warp_n * 40 + (lane & 7) + ((lane >> 4) << 3)) * ASTR + ((lane >> 3) & 1) * 16);
    uint32_t b2_addr = sb + 18432u +
        (uint32_t)((warp_n * 40 + 32 + (lane & 7)) * ASTR + ((lane >> 3) & 1) * 16);

    int chunks = (K + 63) >> 6;
    for (int c = 0; c < chunks; c++) {
        int ccol = c * 64;
        #pragma unroll
        for (int i = 0; i < 2; i++) {
            int idx = tid + i * 256;
            int rr = idx >> 3, u = idx & 7;
            int grow = row0 + rr;
            uint4 vh = make_uint4(0, 0, 0, 0), vl = make_uint4(0, 0, 0, 0);
            if (grow < r) {
                size_t g = (qbase + grow) * 256 + ccol + u * 8;
                vh = *reinterpret_cast<const uint4*>(Ah + g);
                vl = *reinterpret_cast<const uint4*>(Al + g);
            }
            *reinterpret_cast<uint4*>(sm + rr * ASTR + u * 16) = vh;
            *reinterpret_cast<uint4*>(sm + 9216 + rr * ASTR + u * 16) = vl;
        }
        #pragma unroll
        for (int i = 0; i < 3; i++) {
            int idx = tid + i * 256;
            if (idx < 640) {
                int nr = idx >> 3, u = idx & 7;
                size_t g = wbase + (size_t)nr * 256 + ccol + u * 8;
                *reinterpret_cast<uint4*>(sm + 18432 + nr * ASTR + u * 16) =
                    *reinterpret_cast<const uint4*>(Wh + g);
                *reinterpret_cast<uint4*>(sm + 29952 + nr * ASTR + u * 16) =
                    *reinterpret_cast<const uint4*>(Wl + g);
            }
        }
        __syncthreads();

        int steps = (K - ccol + 15) >> 4;
        if (steps > 4) steps = 4;
        for (int s = 0; s < steps; s++) {
            uint32_t ko = (uint32_t)(s * 32);
            uint32_t ah0, ah1, ah2, ah3, al0, al1, al2, al3;
            uint32_t bh0, bh1, bh2, bh3, bh4, bh5, bh6, bh7;
            uint32_t bl0, bl1, bl2, bl3, bl4, bl5, bl6, bl7;
            uint32_t p0, p1, q0, q1;
            LDSM4(ah0, ah1, ah2, ah3, a_addr + ko);
            LDSM4(al0, al1, al2, al3, a_addr + 9216u + ko);
            LDSM4(bh0, bh1, bh2, bh3, b_addr + ko);
            LDSM4(bh4, bh5, bh6, bh7, b_addr + 16u * ASTR + ko);
            LDSM4(bl0, bl1, bl2, bl3, b_addr + 11520u + ko);
            LDSM4(bl4, bl5, bl6, bl7, b_addr + 11520u + 16u * ASTR + ko);
            LDSM2(p0, p1, b2_addr + ko);
            LDSM2(q0, q1, b2_addr + 11520u + ko);
            MMAQ(d0, ah0, ah1, ah2, ah3, bh0, bh1);
            MMAQ(d1, ah0, ah1, ah2, ah3, bh2, bh3);
            MMAQ(d2, ah0, ah1, ah2, ah3, bh4, bh5);
            MMAQ(d3, ah0, ah1, ah2, ah3, bh6, bh7);
            MMAQ(d4, ah0, ah1, ah2, ah3, p0, p1);
            MMAQ(d0, ah0, ah1, ah2, ah3, bl0, bl1);
            MMAQ(d1, ah0, ah1, ah2, ah3, bl2, bl3);
            MMAQ(d2, ah0, ah1, ah2, ah3, bl4, bl5);
            MMAQ(d3, ah0, ah1, ah2, ah3, bl6, bl7);
            MMAQ(d4, ah0, ah1, ah2, ah3, q0, q1);
            MMAQ(d0, al0, al1, al2, al3, bh0, bh1);
            MMAQ(d1, al0, al1, al2, al3, bh2, bh3);
            MMAQ(d2, al0, al1, al2, al3, bh4, bh5);
            MMAQ(d3, al0, al1, al2, al3, bh6, bh7);
            MMAQ(d4, al0, al1, al2, al3, p0, p1);
        }
        __syncthreads();
    }

    // stage accumulators to smem [64][80] f32
    float* stg = reinterpret_cast<float*>(sm);
    {
        int rlo = warp_m * 16 + (lane >> 2);
        int colb = warp_n * 40 + (lane & 3) * 2;
#define STG4(cp, toff) do { \
        int col = colb + (toff); \
        stg[rlo * 80 + col]           = cp##0; \
        stg[rlo * 80 + col + 1]       = cp##1; \
        stg[(rlo + 8) * 80 + col]     = cp##2; \
        stg[(rlo + 8) * 80 + col + 1] = cp##3; \
} while (0)
        STG4(d0, 0);
        STG4(d1, 8);
        STG4(d2, 16);
        STG4(d3, 24);
        STG4(d4, 32);
#undef STG4
    }
    __syncthreads();

    // per-row sampling / scatter / reward / terminal
    if (tid < 64) {
        int j = row0 + tid;
        if (j < r) {
            size_t q = qbase + j;
            int i = (int)g_src[q];
            if (i < n) {
                const float* bm = b4 + (size_t)ev * 66;
                const float* row = stg + tid * 80;
                uint32_t fbase = ((uint32_t)ev * (uint32_t)r + (uint32_t)j) * 33u;
                float sumsq = 0.0f;
                for (int d = 0; d < 33; d++) {
                    float mean = row[d] + bm[d];
                    float lv = row[33 + d] + bm[33 + d];
                    lv = 0.5f - softplusf(0.5f - lv);
                    lv = -10.0f + softplusf(lv + 10.0f);
                    float sd = expf(0.5f * lv);
                    float nz = normal_from_bits(rbits32(0u, 0u, fbase + (uint32_t)d));
                    float s = fmaf(nz, sd, mean);
                    if (d < 32) {
                        float no = s + obs[(size_t)i * OBS + d];
                        out[(size_t)i * OBS + d] = no;
                        sumsq += no * no;
                    } else {
                        out[(size_t)n * OBS + i] = s;
                    }
                }
                out[(size_t)n * (OBS + 1) + i] = (sqrtf(sumsq) > 50.0f) ? 1.0f : 0.0f;
            }
        }
    }
}

// ================= launch =================
extern "C" void kernel_launch(void* const* d_in, const int* in_sizes, int n_in,
                              void* d_out, int out_size) {
    const float* obs = (const float*)d_in[0];
    const float* act = (const float*)d_in[1];
    const float* mu  = (const float*)d_in[2];
    const float* sdv = (const float*)d_in[3];
    const float* W1  = (const float*)d_in[4];
    const float* b1  = (const float*)d_in[5];
    const float* W2  = (const float*)d_in[6];
    const float* b2  = (const float*)d_in[7];
    const float* W3  = (const float*)d_in[8];
    const float* b3  = (const float*)d_in[9];
    const float* W4  = (const float*)d_in[10];
    const float* b4  = (const float*)d_in[11];
    const int* elites = (const int*)d_in[12];

    int n = in_sizes[0] / OBS;
    int e = in_sizes[12];
    int r = (n - 1) / e + 1;
    int P = e * r;
    if (P > PMAX) P = PMAX;
    int Mm = in_sizes[4] / (CIN * HID);
    if (Mm > MMAX) Mm = MMAX;

    uint32_t nk0, nk1, s1a, s1b, s2a, s2b;
    threefry2x32(0u, 0u, 0u, 0u, nk0, nk1);
    threefry2x32(0u, 0u, 0u, 1u, s1a, s1b);
    threefry2x32(nk0, nk1, 0u, 1u, s2a, s2b);

    const int TB = 256;
    int gb = (P + TB - 1) / TB;

    // weight transpose/convert (device-side target selection)
    {
        int t1 = Mm * 256 * 64;
        prep_w<<<(t1 + 255) / 256, 256>>>(W1, 0, CIN, HID, 256, 64, t1);
        int t2 = Mm * 256 * 256;
        prep_w<<<(t2 + 255) / 256, 256>>>(W2, 1, HID, HID, 256, 256, t2);
        prep_w<<<(t2 + 255) / 256, 256>>>(W3, 2, HID, HID, 256, 256, t2);
        int t4 = Mm * 80 * 256;
        prep_w<<<(t4 + 255) / 256, 256>>>(W4, 3, HID, 2 * DOUTD, 80, 256, t4);
    }

    // permutation (two stable-rank rounds)
    zero_hist_kernel<<<256, 256>>>();
    hist_kernel<<<gb, TB>>>(s1a, s1b, P);
    scan_kernel<<<1, 1024>>>();
    scatter_kernel<<<gb, TB>>>(P);
    rank_kernel<<<gb, TB>>>(P, 0);
    zero_hist_kernel<<<256, 256>>>();
    hist_kernel<<<gb, TB>>>(s2a, s2b, P);
    scan_kernel<<<1, 1024>>>();
    scatter_kernel<<<gb, TB>>>(P);
    rank_kernel<<<gb, TB>>>(P, 1);

    gather_kernel<<<gb, TB>>>(obs, act, mu, sdv, n, P);

    // smem opt-in: NT=4 stage = 2*18432 + 2*9216 = 55296; x2 stages = 110592
    //              NT=1 stage = 2*18432 + 2*2304 = 41472; x2 stages = 82944
    cudaFuncSetAttribute(gemm128<4>, cudaFuncAttributeMaxDynamicSharedMemorySize, 110592);
    cudaFuncSetAttribute(gemm128<1>, cudaFuncAttributeMaxDynamicSharedMemorySize, 82944);

    int mt = (r + 127) / 128;
    dim3 gridF(mt, 3, e);   // full tiles: cols 0..191
    dim3 gridT(mt, 1, e);   // tail tile:  cols 192..199 (stores zeros for 200..207)
    gemm128<4><<<gridF, 256, 110592>>>(0, 0,   b1, elites, r, CIN, HID);
    gemm128<1><<<gridT, 256, 82944 >>>(0, 192, b1, elites, r, CIN, HID);
    gemm128<4><<<gridF, 256, 110592>>>(1, 0,   b2, elites, r, HID, HID);
    gemm128<1><<<gridT, 256, 82944 >>>(1, 192, b2, elites, r, HID, HID);
    gemm128<4><<<gridF, 256, 110592>>>(2, 0,   b3, elites, r, HID, HID);
    gemm128<1><<<gridT, 256, 82944 >>>(2, 192, b3, elites, r, HID, HID);

    int mt4 = (r + 63) / 64;
    dim3 gridL4(mt4, e);
    gemm_l4<<<gridL4, 256>>>(b4, elites, r, HID, obs, (float*)d_out, n);
}

// round 10
// speedup vs baseline: 2.4419x; 1.2464x over previous
#include <cuda_runtime.h>
#include <cuda_fp16.h>
#include <stdint.h>

#define OBS   32
#define ACTD  8
#define CIN   40
#define HID   200
#define DOUTD 33
#define PMAX  100352
#define MMAX  8

// ================= scratch (device globals; referenced ONLY from device code) =========
__device__ uint32_t g_bits[PMAX];
__device__ unsigned long long g_slot[PMAX];
__device__ uint32_t g_hist[65536];
__device__ uint32_t g_bstart[65537];
__device__ uint32_t g_cursor[65536];
__device__ uint32_t g_rank1[PMAX];
__device__ uint32_t g_rank2[PMAX];
__device__ uint32_t g_src[PMAX];
// activations, fp16. L1 input lives in g_A at stride 64; hidden activations stride 256.
__device__ __half g_A[(size_t)PMAX * 256];
__device__ __half g_B[(size_t)PMAX * 256];
// transposed fp16 weights: [m][n_pad][k_pad]
__device__ __half g_W1[MMAX * 256 * 64];
__device__ __half g_W2[MMAX * 256 * 256];
__device__ __half g_W3[MMAX * 256 * 256];
__device__ __half g_W4[MMAX * 80 * 256];

// ================= threefry (JAX partitionable) =================
__host__ __device__ __forceinline__ uint32_t rotl32(uint32_t v, int d) {
    return (v << d) | (v >> (32 - d));
}
__host__ __device__ __forceinline__ void threefry2x32(uint32_t k0, uint32_t k1,
                                                      uint32_t x0, uint32_t x1,
                                                      uint32_t& o0, uint32_t& o1) {
    uint32_t ks2 = k0 ^ k1 ^ 0x1BD11BDAu;
    x0 += k0; x1 += k1;
#define TFR(a) x0 += x1; x1 = rotl32(x1, a); x1 ^= x0;
    TFR(13) TFR(15) TFR(26) TFR(6)
    x0 += k1;  x1 += ks2 + 1u;
    TFR(17) TFR(29) TFR(16) TFR(24)
    x0 += ks2; x1 += k0 + 2u;
    TFR(13) TFR(15) TFR(26) TFR(6)
    x0 += k0;  x1 += k1 + 3u;
    TFR(17) TFR(29) TFR(16) TFR(24)
    x0 += k1;  x1 += ks2 + 4u;
    TFR(13) TFR(15) TFR(26) TFR(6)
    x0 += ks2; x1 += k0 + 5u;
#undef TFR
    o0 = x0; o1 = x1;
}
__device__ __forceinline__ uint32_t rbits32(uint32_t k0, uint32_t k1, uint32_t idx) {
    uint32_t a, b;
    threefry2x32(k0, k1, 0u, idx, a, b);
    return a ^ b;
}
__device__ __forceinline__ float softplusf(float x) {
    return fmaxf(x, 0.0f) + log1pf(expf(-fabsf(x)));
}
__device__ __forceinline__ float normal_from_bits(uint32_t bits) {
    float f = __uint_as_float((bits >> 9) | 0x3F800000u) - 1.0f;
    const float lo = -0.99999994f;
    float val = fmaf(f, 2.0f, lo);
    val = fmaxf(lo, val);
    return 1.41421354f * erfinvf(val);
}

// ================= asm macros =================
__device__ __forceinline__ uint32_t smem_u32(const void* p) {
    uint32_t a;
    asm("{ .reg .u64 t; cvta.to.shared.u64 t, %1; cvt.u32.u64 %0, t; }" : "=r"(a) : "l"(p));
    return a;
}
#define LDSM4(r0, r1, r2, r3, addr) \
    asm volatile("ldmatrix.sync.aligned.m8n8.x4.shared.b16 {%0,%1,%2,%3}, [%4];" \
                 : "=r"(r0), "=r"(r1), "=r"(r2), "=r"(r3) : "r"(addr))
#define LDSM4A(rr, addr) LDSM4((rr)[0], (rr)[1], (rr)[2], (rr)[3], addr)
#define LDSM2(r0, r1, addr) \
    asm volatile("ldmatrix.sync.aligned.m8n8.x2.shared.b16 {%0,%1}, [%2];" \
                 : "=r"(r0), "=r"(r1) : "r"(addr))
#define MMAQ(cp, a0, a1, a2, a3, b0, b1) \
    asm volatile("mma.sync.aligned.m16n8k16.row.col.f32.f16.f16.f32 " \
                 "{%0,%1,%2,%3}, {%4,%5,%6,%7}, {%8,%9}, {%0,%1,%2,%3};" \
                 : "+f"(cp##0), "+f"(cp##1), "+f"(cp##2), "+f"(cp##3) \
                 : "r"(a0), "r"(a1), "r"(a2), "r"(a3), "r"(b0), "r"(b1))
#define MMA4(c, a, b0, b1) \
    asm volatile("mma.sync.aligned.m16n8k16.row.col.f32.f16.f16.f32 " \
                 "{%0,%1,%2,%3}, {%4,%5,%6,%7}, {%8,%9}, {%0,%1,%2,%3};" \
                 : "+f"((c)[0]), "+f"((c)[1]), "+f"((c)[2]), "+f"((c)[3]) \
                 : "r"((a)[0]), "r"((a)[1]), "r"((a)[2]), "r"((a)[3]), "r"(b0), "r"(b1))
#define CPA16(dst, src, pb) \
    asm volatile("cp.async.cg.shared.global [%0], [%1], 16, %2;" \
                 :: "r"(dst), "l"(src), "r"(pb) : "memory")
#define CPA_COMMIT() asm volatile("cp.async.commit_group;" ::: "memory")
#define CPA_WAIT0() asm volatile("cp.async.wait_group 0;" ::: "memory")
#define CPA_WAIT1() asm volatile("cp.async.wait_group 1;" ::: "memory")

__device__ __forceinline__ uint32_t pack_h2(float v0, float v1) {
    __half h0 = __float2half_rn(v0), h1 = __float2half_rn(v1);
    return (uint32_t)__half_as_ushort(h0) | ((uint32_t)__half_as_ushort(h1) << 16);
}

// ================= permutation machinery (known clean) =================
__global__ void zero_hist_kernel() {
    int t = blockIdx.x * blockDim.x + threadIdx.x;
    if (t < 65536) g_hist[t] = 0u;
}
__global__ void hist_kernel(uint32_t k0, uint32_t k1, int P) {
    int p = blockIdx.x * blockDim.x + threadIdx.x;
    if (p >= P) return;
    uint32_t b = rbits32(k0, k1, (uint32_t)p);
    g_bits[p] = b;
    atomicAdd(&g_hist[b >> 16], 1u);
}
__global__ void scan_kernel() {
    __shared__ uint32_t part[1024];
    int t = threadIdx.x;
    uint32_t s = 0;
    #pragma unroll 8
    for (int i = 0; i < 64; i++) s += g_hist[t * 64 + i];
    part[t] = s;
    __syncthreads();
    for (int off = 1; off < 1024; off <<= 1) {
        uint32_t v = part[t];
        uint32_t add = (t >= off) ? part[t - off] : 0u;
        __syncthreads();
        part[t] = v + add;
        __syncthreads();
    }
    uint32_t run = (t == 0) ? 0u : part[t - 1];
    for (int i = 0; i < 64; i++) {
        int idx = t * 64 + i;
        g_bstart[idx] = run;
        g_cursor[idx] = run;
        run += g_hist[idx];
    }
    if (t == 1023) g_bstart[65536] = run;
}
__global__ void scatter_kernel(int P) {
    int p = blockIdx.x * blockDim.x + threadIdx.x;
    if (p >= P) return;
    uint32_t b = g_bits[p];
    uint32_t slot = atomicAdd(&g_cursor[b >> 16], 1u);
    g_slot[slot] = (((unsigned long long)(b & 0xFFFFu)) << 17) | (unsigned long long)p;
}
__global__ void rank_kernel(int P, int round) {
    int p = blockIdx.x * blockDim.x + threadIdx.x;
    if (p >= P) return;
    uint32_t b = g_bits[p];
    uint32_t hi = b >> 16;
    uint32_t s0 = g_bstart[hi], s1 = g_bstart[hi + 1];
    unsigned long long my = (((unsigned long long)(b & 0xFFFFu)) << 17) | (unsigned long long)p;
    uint32_t c = 0;
    for (uint32_t s = s0; s < s1; s++) c += (g_slot[s] < my) ? 1u : 0u;
    uint32_t rk = s0 + c;
    if (round == 0) g_rank1[p] = rk; else g_rank2[p] = rk;
}

// ================= gather + normalize -> fp16 (stride 64) =================
__global__ void gather_kernel(const float* __restrict__ obs, const float* __restrict__ act,
                              const float* __restrict__ mu, const float* __restrict__ sd,
                              int n, int P) {
    int i = blockIdx.x * blockDim.x + threadIdx.x;
    if (i >= P) return;
    uint32_t q = g_rank2[g_rank1[i]];
    g_src[q] = (uint32_t)i;
    uint32_t* oh = reinterpret_cast<uint32_t*>(g_A + (size_t)q * 64);
    if (i < n) {
        #pragma unroll
        for (int c = 0; c < CIN; c += 2) {
            float x0 = (c < OBS) ? obs[(size_t)i * OBS + c] : act[(size_t)i * ACTD + (c - OBS)];
            float x1 = (c + 1 < OBS) ? obs[(size_t)i * OBS + c + 1]
                                     : act[(size_t)i * ACTD + (c + 1 - OBS)];
            float v0 = (x0 - mu[c]) / sd[c];
            float v1 = (x1 - mu[c + 1]) / sd[c + 1];
            oh[c >> 1] = pack_h2(v0, v1);
        }
        #pragma unroll
        for (int c = CIN; c < 64; c += 2) oh[c >> 1] = 0u;
    } else {
        #pragma unroll
        for (int c = 0; c < 64; c += 2) oh[c >> 1] = 0u;
    }
}

// ====== weight transpose/convert: W[m][k][n] -> Wt[m][n_pad][k_pad] fp16 ======
__global__ void prep_w(const float* __restrict__ W, int which,
                       int K, int N, int Nrows, int Kpad, int total) {
    int t = blockIdx.x * blockDim.x + threadIdx.x;
    if (t >= total) return;
    __half* Wd;
    if (which == 0)      Wd = g_W1;
    else if (which == 1) Wd = g_W2;
    else if (which == 2) Wd = g_W3;
    else                 Wd = g_W4;
    int kp = t % Kpad;
    int rest = t / Kpad;
    int nn = rest % Nrows;
    int mm = rest / Nrows;
    float v = 0.0f;
    if (nn < N && kp < K) v = W[((size_t)mm * K + kp) * N + nn];
    Wd[t] = __float2half_rn(v);
}

// stride of smem tile rows (bytes): 64 fp16 = 128B + 16B pad
#define ASTR 144
#define ABYTES (128 * ASTR)

// ======== hidden-layer GEMM, CTA tile 128 x (NT*16), 2-stage cp.async pipeline ========
// layer 0: g_A(64) x W1 -> g_B ; layer 1: g_B(256) x W2 -> g_A ; layer 2: g_A(256) x W3 -> g_B
template <int NT>
__global__ void __launch_bounds__(256, 2) gemm128(
    int layer, int col00, const float* __restrict__ bias, const int* __restrict__ elites,
    int r, int K, int N)
{
    constexpr int BROWS = NT * 16;
    constexpr int BBYTES = BROWS * ASTR;
    constexpr int STG = ABYTES + BBYTES;

    const __half* Ain;
    const __half* Wt;
    __half* Cout;
    int strideA, wKpad;
    if (layer == 0)      { Ain = g_A; Wt = g_W1; Cout = g_B; strideA = 64;  wKpad = 64;  }
    else if (layer == 1) { Ain = g_B; Wt = g_W2; Cout = g_A; strideA = 256; wKpad = 256; }
    else                 { Ain = g_A; Wt = g_W3; Cout = g_B; strideA = 256; wKpad = 256; }

    extern __shared__ __align__(16) char sm[];
    uint32_t sb = smem_u32(sm);
    int tid = threadIdx.x, lane = tid & 31, wid = tid >> 5;
    int warp_m = wid >> 1, warp_n = wid & 1;
    int row0 = blockIdx.x * 128;
    int c0col = col00 + blockIdx.y * 64;
    int m = blockIdx.z;
    int ev = elites[m];
    size_t qbase = (size_t)m * r;
    size_t wbase = (size_t)ev * 256 * wKpad;
    const float* biasm = bias + (size_t)ev * N;

    float acc[2][NT][4];
    #pragma unroll
    for (int i = 0; i < 2; i++)
        #pragma unroll
        for (int j = 0; j < NT; j++)
            #pragma unroll
            for (int x = 0; x < 4; x++) acc[i][j][x] = 0.0f;

    uint32_t a_addr0 = sb + (uint32_t)((warp_m * 32 + (lane & 15)) * ASTR + (lane >> 4) * 16);
    uint32_t b_addr0;
    if (NT == 4) {
        b_addr0 = sb + (uint32_t)ABYTES +
            (uint32_t)((warp_n * 32 + (lane & 7) + ((lane >> 4) << 3)) * ASTR +
                       ((lane >> 3) & 1) * 16);
    } else {
        b_addr0 = sb + (uint32_t)ABYTES +
            (uint32_t)((warp_n * 8 + (lane & 7)) * ASTR + ((lane >> 3) & 1) * 16);
    }

    int chunks = (K + 63) >> 6;

#define ISSUE_CHUNK(c_, stg_) do { \
    uint32_t sbase = sb + (uint32_t)(stg_) * STG; \
    int ccol = (c_) * 64; \
    _Pragma("unroll") \
    for (int i = 0; i < 4; i++) { \
        int idx = tid + i * 256; \
        int rr = idx >> 3, u = idx & 7; \
        int grow = row0 + rr; \
        uint32_t pb = (grow < r) ? 16u : 0u; \
        size_t gix = (qbase + (grow < r ? grow : 0)) * (size_t)strideA + ccol + u * 8; \
        uint32_t d = sbase + (uint32_t)(rr * ASTR + u * 16); \
        CPA16(d, Ain + gix, pb); \
    } \
    _Pragma("unroll") \
    for (int i = 0; i < (BROWS * 8 + 255) / 256; i++) { \
        int idx = tid + i * 256; \
        if (idx < BROWS * 8) { \
            int nr = idx >> 3, u = idx & 7; \
            size_t gix = wbase + (size_t)(c0col + nr) * wKpad + ccol + u * 8; \
            uint32_t d = sbase + (uint32_t)ABYTES + (uint32_t)(nr * ASTR + u * 16); \
            CPA16(d, Wt + gix, 16u); \
        } \
    } \
    CPA_COMMIT(); \
} while (0)

    ISSUE_CHUNK(0, 0);

    for (int c = 0; c < chunks; c++) {
        int stg = c & 1;
        if (c + 1 < chunks) {
            ISSUE_CHUNK(c + 1, (c + 1) & 1);
            CPA_WAIT1();
        } else {
            CPA_WAIT0();
        }
        __syncthreads();

        uint32_t soff = (uint32_t)stg * STG;
        uint32_t a_addr = a_addr0 + soff;
        uint32_t b_addr = b_addr0 + soff;

        int steps = (K - c * 64 + 15) >> 4;
        if (steps > 4) steps = 4;
        for (int s = 0; s < steps; s++) {
            uint32_t ko = (uint32_t)(s * 32);
            uint32_t ah[2][4];
            LDSM4A(ah[0], a_addr + ko);
            LDSM4A(ah[1], a_addr + 16u * ASTR + ko);
            if (NT == 4) {
                uint32_t bh[2][4];
                LDSM4A(bh[0], b_addr + ko);
                LDSM4A(bh[1], b_addr + 16u * ASTR + ko);
                #pragma unroll
                for (int mi = 0; mi < 2; mi++)
                    #pragma unroll
                    for (int nn = 0; nn < 4; nn++)
                        MMA4(acc[mi][nn], ah[mi], bh[nn >> 1][(nn & 1) * 2],
                             bh[nn >> 1][(nn & 1) * 2 + 1]);
            } else {
                uint32_t bh0, bh1;
                LDSM2(bh0, bh1, b_addr + ko);
                #pragma unroll
                for (int mi = 0; mi < 2; mi++)
                    MMA4(acc[mi][0], ah[mi], bh0, bh1);
            }
        }
        __syncthreads();
    }
#undef ISSUE_CHUNK

    // epilogue: bias + swish, fp16 store (zeros for cols >= N)
    #pragma unroll
    for (int mi = 0; mi < 2; mi++) {
        int rlo = row0 + warp_m * 32 + mi * 16 + (lane >> 2);
        #pragma unroll
        for (int nn = 0; nn < NT; nn++) {
            int col = c0col + warp_n * (NT * 8) + nn * 8 + (lane & 3) * 2;
            if (rlo < r) {
                float v0 = 0.0f, v1 = 0.0f;
                if (col < N) {
                    float d0 = acc[mi][nn][0] + biasm[col];
                    float d1 = acc[mi][nn][1] + biasm[col + 1];
                    v0 = d0 / (1.0f + expf(-d0));
                    v1 = d1 / (1.0f + expf(-d1));
                }
                reinterpret_cast<uint32_t*>(Cout)[((qbase + rlo) * 256 + col) >> 1] =
                    pack_h2(v0, v1);
            }
            if (rlo + 8 < r) {
                float v0 = 0.0f, v1 = 0.0f;
                if (col < N) {
                    float d0 = acc[mi][nn][2] + biasm[col];
                    float d1 = acc[mi][nn][3] + biasm[col + 1];
                    v0 = d0 / (1.0f + expf(-d0));
                    v1 = d1 / (1.0f + expf(-d1));
                }
                reinterpret_cast<uint32_t*>(Cout)[((qbase + rlo + 8) * 256 + col) >> 1] =
                    pack_h2(v0, v1);
            }
        }
    }
}

// ======== layer-4 GEMM (N=66 padded 80) fused with sampling epilogue ========
__global__ void __launch_bounds__(256, 1) gemm_l4(
    const float* __restrict__ b4, const int* __restrict__ elites,
    int r, int K,
    const float* __restrict__ obs, float* __restrict__ out, int n)
{
    const __half* Ain = g_B;
    const __half* Wt  = g_W4;

    // smem: A [0,9216), B [9216,20736); epilogue staging f32[64][80] = 20480 fits
    __shared__ __align__(16) char sm[20736];
    uint32_t sb = smem_u32(sm);
    int tid = threadIdx.x, lane = tid & 31, wid = tid >> 5;
    int warp_m = wid >> 1, warp_n = wid & 1;
    int row0 = blockIdx.x * 64;
    int m = blockIdx.y;
    int ev = elites[m];
    size_t qbase = (size_t)m * r;
    size_t wbase = (size_t)ev * 80 * 256;

    float d00 = 0.f, d01 = 0.f, d02 = 0.f, d03 = 0.f;
    float d10 = 0.f, d11 = 0.f, d12 = 0.f, d13 = 0.f;
    float d20 = 0.f, d21 = 0.f, d22 = 0.f, d23 = 0.f;
    float d30 = 0.f, d31 = 0.f, d32 = 0.f, d33 = 0.f;
    float d40 = 0.f, d41 = 0.f, d42 = 0.f, d43 = 0.f;

    uint32_t a_addr = sb + (uint32_t)((warp_m * 16 + (lane & 15)) * ASTR + (lane >> 4) * 16);
    uint32_t b_addr = sb + 9216u +
        (uint32_t)((warp_n * 40 + (lane & 7) + ((lane >> 4) << 3)) * ASTR + ((lane >> 3) & 1) * 16);
    uint32_t b2_addr = sb + 9216u +
        (uint32_t)((warp_n * 40 + 32 + (lane & 7)) * ASTR + ((lane >> 3) & 1) * 16);

    int chunks = (K + 63) >> 6;
    for (int c = 0; c < chunks; c++) {
        int ccol = c * 64;
        #pragma unroll
        for (int i = 0; i < 2; i++) {
            int idx = tid + i * 256;
            int rr = idx >> 3, u = idx & 7;
            int grow = row0 + rr;
            uint4 vh = make_uint4(0, 0, 0, 0);
            if (grow < r)
                vh = *reinterpret_cast<const uint4*>(Ain + (qbase + grow) * 256 + ccol + u * 8);
            *reinterpret_cast<uint4*>(sm + rr * ASTR + u * 16) = vh;
        }
        #pragma unroll
        for (int i = 0; i < 3; i++) {
            int idx = tid + i * 256;
            if (idx < 640) {
                int nr = idx >> 3, u = idx & 7;
                *reinterpret_cast<uint4*>(sm + 9216 + nr * ASTR + u * 16) =
                    *reinterpret_cast<const uint4*>(Wt + wbase + (size_t)nr * 256 + ccol + u * 8);
            }
        }
        __syncthreads();

        int steps = (K - ccol + 15) >> 4;
        if (steps > 4) steps = 4;
        for (int s = 0; s < steps; s++) {
            uint32_t ko = (uint32_t)(s * 32);
            uint32_t ah0, ah1, ah2, ah3;
            uint32_t bh0, bh1, bh2, bh3, bh4, bh5, bh6, bh7;
            uint32_t p0, p1;
            LDSM4(ah0, ah1, ah2, ah3, a_addr + ko);
            LDSM4(bh0, bh1, bh2, bh3, b_addr + ko);
            LDSM4(bh4, bh5, bh6, bh7, b_addr + 16u * ASTR + ko);
            LDSM2(p0, p1, b2_addr + ko);
            MMAQ(d0, ah0, ah1, ah2, ah3, bh0, bh1);
            MMAQ(d1, ah0, ah1, ah2, ah3, bh2, bh3);
            MMAQ(d2, ah0, ah1, ah2, ah3, bh4, bh5);
            MMAQ(d3, ah0, ah1, ah2, ah3, bh6, bh7);
            MMAQ(d4, ah0, ah1, ah2, ah3, p0, p1);
        }
        __syncthreads();
    }

    // stage accumulators to smem [64][80] f32
    float* stg = reinterpret_cast<float*>(sm);
    {
        int rlo = warp_m * 16 + (lane >> 2);
        int colb = warp_n * 40 + (lane & 3) * 2;
#define STG4(cp, toff) do { \
        int col = colb + (toff); \
        stg[rlo * 80 + col]           = cp##0; \
        stg[rlo * 80 + col + 1]       = cp##1; \
        stg[(rlo + 8) * 80 + col]     = cp##2; \
        stg[(rlo + 8) * 80 + col + 1] = cp##3; \
} while (0)
        STG4(d0, 0);
        STG4(d1, 8);
        STG4(d2, 16);
        STG4(d3, 24);
        STG4(d4, 32);
#undef STG4
    }
    __syncthreads();

    // per-row sampling / scatter / reward / terminal
    if (tid < 64) {
        int j = row0 + tid;
        if (j < r) {
            size_t q = qbase + j;
            int i = (int)g_src[q];
            if (i < n) {
                const float* bm = b4 + (size_t)ev * 66;
                const float* row = stg + tid * 80;
                uint32_t fbase = ((uint32_t)ev * (uint32_t)r + (uint32_t)j) * 33u;
                float sumsq = 0.0f;
                for (int d = 0; d < 33; d++) {
                    float mean = row[d] + bm[d];
                    float lv = row[33 + d] + bm[33 + d];
                    lv = 0.5f - softplusf(0.5f - lv);
                    lv = -10.0f + softplusf(lv + 10.0f);
                    float sd = expf(0.5f * lv);
                    float nz = normal_from_bits(rbits32(0u, 0u, fbase + (uint32_t)d));
                    float s = fmaf(nz, sd, mean);
                    if (d < 32) {
                        float no = s + obs[(size_t)i * OBS + d];
                        out[(size_t)i * OBS + d] = no;
                        sumsq += no * no;
                    } else {
                        out[(size_t)n * OBS + i] = s;
                    }
                }
                out[(size_t)n * (OBS + 1) + i] = (sqrtf(sumsq) > 50.0f) ? 1.0f : 0.0f;
            }
        }
    }
}

// ================= launch =================
extern "C" void kernel_launch(void* const* d_in, const int* in_sizes, int n_in,
                              void* d_out, int out_size) {
    const float* obs = (const float*)d_in[0];
    const float* act = (const float*)d_in[1];
    const float* mu  = (const float*)d_in[2];
    const float* sdv = (const float*)d_in[3];
    const float* W1  = (const float*)d_in[4];
    const float* b1  = (const float*)d_in[5];
    const float* W2  = (const float*)d_in[6];
    const float* b2  = (const float*)d_in[7];
    const float* W3  = (const float*)d_in[8];
    const float* b3  = (const float*)d_in[9];
    const float* W4  = (const float*)d_in[10];
    const float* b4  = (const float*)d_in[11];
    const int* elites = (const int*)d_in[12];

    int n = in_sizes[0] / OBS;
    int e = in_sizes[12];
    int r = (n - 1) / e + 1;
    int P = e * r;
    if (P > PMAX) P = PMAX;
    int Mm = in_sizes[4] / (CIN * HID);
    if (Mm > MMAX) Mm = MMAX;

    uint32_t nk0, nk1, s1a, s1b, s2a, s2b;
    threefry2x32(0u, 0u, 0u, 0u, nk0, nk1);
    threefry2x32(0u, 0u, 0u, 1u, s1a, s1b);
    threefry2x32(nk0, nk1, 0u, 1u, s2a, s2b);

    const int TB = 256;
    int gb = (P + TB - 1) / TB;

    // weight transpose/convert (device-side target selection)
    {
        int t1 = Mm * 256 * 64;
        prep_w<<<(t1 + 255) / 256, 256>>>(W1, 0, CIN, HID, 256, 64, t1);
        int t2 = Mm * 256 * 256;
        prep_w<<<(t2 + 255) / 256, 256>>>(W2, 1, HID, HID, 256, 256, t2);
        prep_w<<<(t2 + 255) / 256, 256>>>(W3, 2, HID, HID, 256, 256, t2);
        int t4 = Mm * 80 * 256;
        prep_w<<<(t4 + 255) / 256, 256>>>(W4, 3, HID, 2 * DOUTD, 80, 256, t4);
    }

    // permutation (two stable-rank rounds)
    zero_hist_kernel<<<256, 256>>>();
    hist_kernel<<<gb, TB>>>(s1a, s1b, P);
    scan_kernel<<<1, 1024>>>();
    scatter_kernel<<<gb, TB>>>(P);
    rank_kernel<<<gb, TB>>>(P, 0);
    zero_hist_kernel<<<256, 256>>>();
    hist_kernel<<<gb, TB>>>(s2a, s2b, P);
    scan_kernel<<<1, 1024>>>();
    scatter_kernel<<<gb, TB>>>(P);
    rank_kernel<<<gb, TB>>>(P, 1);

    gather_kernel<<<gb, TB>>>(obs, act, mu, sdv, n, P);

    // smem opt-in: NT=4 stage = 18432 + 9216 = 27648; x2 = 55296
    //              NT=1 stage = 18432 + 2304 = 20736; x2 = 41472
    cudaFuncSetAttribute(gemm128<4>, cudaFuncAttributeMaxDynamicSharedMemorySize, 55296);
    cudaFuncSetAttribute(gemm128<1>, cudaFuncAttributeMaxDynamicSharedMemorySize, 41472);

    int mt = (r + 127) / 128;
    dim3 gridF(mt, 3, e);   // full tiles: cols 0..191
    dim3 gridT(mt, 1, e);   // tail tile:  cols 192..199 (stores zeros for 200..207)
    gemm128<4><<<gridF, 256, 55296>>>(0, 0,   b1, elites, r, CIN, HID);
    gemm128<1><<<gridT, 256, 41472>>>(0, 192, b1, elites, r, CIN, HID);
    gemm128<4><<<gridF, 256, 55296>>>(1, 0,   b2, elites, r, HID, HID);
    gemm128<1><<<gridT, 256, 41472>>>(1, 192, b2, elites, r, HID, HID);
    gemm128<4><<<gridF, 256, 55296>>>(2, 0,   b3, elites, r, HID, HID);
    gemm128<1><<<gridT, 256, 41472>>>(2, 192, b3, elites, r, HID, HID);

    int mt4 = (r + 63) / 64;
    dim3 gridL4(mt4, e);
    gemm_l4<<<gridL4, 256>>>(b4, elites, r, HID, obs, (float*)d_out, n);
}

// round 12
// speedup vs baseline: 2.4551x; 1.0054x over previous
#include <cuda_runtime.h>
#include <cuda_fp16.h>
#include <stdint.h>

#define OBS   32
#define ACTD  8
#define CIN   40
#define HID   200
#define DOUTD 33
#define PMAX  100352
#define MMAX  8

// ================= scratch (device globals; referenced ONLY from device code) =========
__device__ uint32_t g_bits[PMAX];
__device__ unsigned long long g_slot[PMAX];
__device__ uint32_t g_hist[65536];
__device__ uint32_t g_bstart[65537];
__device__ uint32_t g_cursor[65536];
__device__ uint32_t g_rank1[PMAX];
__device__ uint32_t g_rank2[PMAX];
__device__ uint32_t g_src[PMAX];
// activations, fp16. L1 input lives in g_A at stride 64; hidden activations stride 256.
__device__ __half g_A[(size_t)PMAX * 256];
__device__ __half g_B[(size_t)PMAX * 256];
// transposed fp16 weights: [m][n_pad][k_pad]
__device__ __half g_W1[MMAX * 256 * 64];
__device__ __half g_W2[MMAX * 256 * 256];
__device__ __half g_W3[MMAX * 256 * 256];
__device__ __half g_W4[MMAX * 80 * 256];

// ================= threefry (JAX partitionable) =================
__host__ __device__ __forceinline__ uint32_t rotl32(uint32_t v, int d) {
    return (v << d) | (v >> (32 - d));
}
__host__ __device__ __forceinline__ void threefry2x32(uint32_t k0, uint32_t k1,
                                                      uint32_t x0, uint32_t x1,
                                                      uint32_t& o0, uint32_t& o1) {
    uint32_t ks2 = k0 ^ k1 ^ 0x1BD11BDAu;
    x0 += k0; x1 += k1;
#define TFR(a) x0 += x1; x1 = rotl32(x1, a); x1 ^= x0;
    TFR(13) TFR(15) TFR(26) TFR(6)
    x0 += k1;  x1 += ks2 + 1u;
    TFR(17) TFR(29) TFR(16) TFR(24)
    x0 += ks2; x1 += k0 + 2u;
    TFR(13) TFR(15) TFR(26) TFR(6)
    x0 += k0;  x1 += k1 + 3u;
    TFR(17) TFR(29) TFR(16) TFR(24)
    x0 += k1;  x1 += ks2 + 4u;
    TFR(13) TFR(15) TFR(26) TFR(6)
    x0 += ks2; x1 += k0 + 5u;
#undef TFR
    o0 = x0; o1 = x1;
}
__device__ __forceinline__ uint32_t rbits32(uint32_t k0, uint32_t k1, uint32_t idx) {
    uint32_t a, b;
    threefry2x32(k0, k1, 0u, idx, a, b);
    return a ^ b;
}
__device__ __forceinline__ float softplusf(float x) {
    return fmaxf(x, 0.0f) + log1pf(expf(-fabsf(x)));
}
__device__ __forceinline__ float normal_from_bits(uint32_t bits) {
    float f = __uint_as_float((bits >> 9) | 0x3F800000u) - 1.0f;
    const float lo = -0.99999994f;
    float val = fmaf(f, 2.0f, lo);
    val = fmaxf(lo, val);
    return 1.41421354f * erfinvf(val);
}

// ================= asm macros =================
__device__ __forceinline__ uint32_t smem_u32(const void* p) {
    uint32_t a;
    asm("{ .reg .u64 t; cvta.to.shared.u64 t, %1; cvt.u32.u64 %0, t; }" : "=r"(a) : "l"(p));
    return a;
}
#define LDSM4(r0, r1, r2, r3, addr) \
    asm volatile("ldmatrix.sync.aligned.m8n8.x4.shared.b16 {%0,%1,%2,%3}, [%4];" \
                 : "=r"(r0), "=r"(r1), "=r"(r2), "=r"(r3) : "r"(addr))
#define LDSM4A(rr, addr) LDSM4((rr)[0], (rr)[1], (rr)[2], (rr)[3], addr)
#define LDSM2(r0, r1, addr) \
    asm volatile("ldmatrix.sync.aligned.m8n8.x2.shared.b16 {%0,%1}, [%2];" \
                 : "=r"(r0), "=r"(r1) : "r"(addr))
#define MMAQ(cp, a0, a1, a2, a3, b0, b1) \
    asm volatile("mma.sync.aligned.m16n8k16.row.col.f32.f16.f16.f32 " \
                 "{%0,%1,%2,%3}, {%4,%5,%6,%7}, {%8,%9}, {%0,%1,%2,%3};" \
                 : "+f"(cp##0), "+f"(cp##1), "+f"(cp##2), "+f"(cp##3) \
                 : "r"(a0), "r"(a1), "r"(a2), "r"(a3), "r"(b0), "r"(b1))
#define MMA4(c, a, b0, b1) \
    asm volatile("mma.sync.aligned.m16n8k16.row.col.f32.f16.f16.f32 " \
                 "{%0,%1,%2,%3}, {%4,%5,%6,%7}, {%8,%9}, {%0,%1,%2,%3};" \
                 : "+f"((c)[0]), "+f"((c)[1]), "+f"((c)[2]), "+f"((c)[3]) \
                 : "r"((a)[0]), "r"((a)[1]), "r"((a)[2]), "r"((a)[3]), "r"(b0), "r"(b1))
#define CPA16(dst, src, pb) \
    asm volatile("cp.async.cg.shared.global [%0], [%1], 16, %2;" \
                 :: "r"(dst), "l"(src), "r"(pb) : "memory")
#define CPA_COMMIT() asm volatile("cp.async.commit_group;" ::: "memory")
#define CPA_WAIT0() asm volatile("cp.async.wait_group 0;" ::: "memory")
#define CPA_WAIT1() asm volatile("cp.async.wait_group 1;" ::: "memory")

__device__ __forceinline__ uint32_t pack_h2(float v0, float v1) {
    __half h0 = __float2half_rn(v0), h1 = __float2half_rn(v1);
    return (uint32_t)__half_as_ushort(h0) | ((uint32_t)__half_as_ushort(h1) << 16);
}

// ================= permutation machinery (known clean) =================
__global__ void zero_hist_kernel() {
    int t = blockIdx.x * blockDim.x + threadIdx.x;
    if (t < 65536) g_hist[t] = 0u;
}
__global__ void hist_kernel(uint32_t k0, uint32_t k1, int P) {
    int p = blockIdx.x * blockDim.x + threadIdx.x;
    if (p >= P) return;
    uint32_t b = rbits32(k0, k1, (uint32_t)p);
    g_bits[p] = b;
    atomicAdd(&g_hist[b >> 16], 1u);
}
__global__ void scan_kernel() {
    __shared__ uint32_t part[1024];
    int t = threadIdx.x;
    uint32_t s = 0;
    #pragma unroll 8
    for (int i = 0; i < 64; i++) s += g_hist[t * 64 + i];
    part[t] = s;
    __syncthreads();
    for (int off = 1; off < 1024; off <<= 1) {
        uint32_t v = part[t];
        uint32_t add = (t >= off) ? part[t - off] : 0u;
        __syncthreads();
        part[t] = v + add;
        __syncthreads();
    }
    uint32_t run = (t == 0) ? 0u : part[t - 1];
    for (int i = 0; i < 64; i++) {
        int idx = t * 64 + i;
        g_bstart[idx] = run;
        g_cursor[idx] = run;
        run += g_hist[idx];
    }
    if (t == 1023) g_bstart[65536] = run;
}
__global__ void scatter_kernel(int P) {
    int p = blockIdx.x * blockDim.x + threadIdx.x;
    if (p >= P) return;
    uint32_t b = g_bits[p];
    uint32_t slot = atomicAdd(&g_cursor[b >> 16], 1u);
    g_slot[slot] = (((unsigned long long)(b & 0xFFFFu)) << 17) | (unsigned long long)p;
}
__global__ void rank_kernel(int P, int round) {
    int p = blockIdx.x * blockDim.x + threadIdx.x;
    if (p >= P) return;
    uint32_t b = g_bits[p];
    uint32_t hi = b >> 16;
    uint32_t s0 = g_bstart[hi], s1 = g_bstart[hi + 1];
    unsigned long long my = (((unsigned long long)(b & 0xFFFFu)) << 17) | (unsigned long long)p;
    uint32_t c = 0;
    for (uint32_t s = s0; s < s1; s++) c += (g_slot[s] < my) ? 1u : 0u;
    uint32_t rk = s0 + c;
    if (round == 0) g_rank1[p] = rk; else g_rank2[p] = rk;
}

// ================= gather + normalize -> fp16 (stride 64) =================
__global__ void gather_kernel(const float* __restrict__ obs, const float* __restrict__ act,
                              const float* __restrict__ mu, const float* __restrict__ sd,
                              int n, int P) {
    int i = blockIdx.x * blockDim.x + threadIdx.x;
    if (i >= P) return;
    uint32_t q = g_rank2[g_rank1[i]];
    g_src[q] = (uint32_t)i;
    uint32_t* oh = reinterpret_cast<uint32_t*>(g_A + (size_t)q * 64);
    if (i < n) {
        #pragma unroll
        for (int c = 0; c < CIN; c += 2) {
            float x0 = (c < OBS) ? obs[(size_t)i * OBS + c] : act[(size_t)i * ACTD + (c - OBS)];
            float x1 = (c + 1 < OBS) ? obs[(size_t)i * OBS + c + 1]
                                     : act[(size_t)i * ACTD + (c + 1 - OBS)];
            float v0 = (x0 - mu[c]) / sd[c];
            float v1 = (x1 - mu[c + 1]) / sd[c + 1];
            oh[c >> 1] = pack_h2(v0, v1);
        }
        #pragma unroll
        for (int c = CIN; c < 64; c += 2) oh[c >> 1] = 0u;
    } else {
        #pragma unroll
        for (int c = 0; c < 64; c += 2) oh[c >> 1] = 0u;
    }
}

// ====== weight transpose/convert: W[m][k][n] -> Wt[m][n_pad][k_pad] fp16 ======
__global__ void prep_w(const float* __restrict__ W, int which,
                       int K, int N, int Nrows, int Kpad, int total) {
    int t = blockIdx.x * blockDim.x + threadIdx.x;
    if (t >= total) return;
    __half* Wd;
    if (which == 0)      Wd = g_W1;
    else if (which == 1) Wd = g_W2;
    else if (which == 2) Wd = g_W3;
    else                 Wd = g_W4;
    int kp = t % Kpad;
    int rest = t / Kpad;
    int nn = rest % Nrows;
    int mm = rest / Nrows;
    float v = 0.0f;
    if (nn < N && kp < K) v = W[((size_t)mm * K + kp) * N + nn];
    Wd[t] = __float2half_rn(v);
}

// stride of smem tile rows (bytes): 64 fp16 = 128B + 16B pad
#define ASTR 144
#define ABYTES (128 * ASTR)

// ======== hidden-layer GEMM, CTA tile 128 x (NT*16), 2-stage cp.async pipeline,
// ======== register-level fragment software pipelining inside each chunk ========
template <int NT>
__global__ void __launch_bounds__(256, 2) gemm128(
    int layer, int col00, const float* __restrict__ bias, const int* __restrict__ elites,
    int r, int K, int N)
{
    constexpr int BROWS = NT * 16;
    constexpr int BBYTES = BROWS * ASTR;
    constexpr int STG = ABYTES + BBYTES;

    const __half* Ain;
    const __half* Wt;
    __half* Cout;
    int strideA, wKpad;
    if (layer == 0)      { Ain = g_A; Wt = g_W1; Cout = g_B; strideA = 64;  wKpad = 64;  }
    else if (layer == 1) { Ain = g_B; Wt = g_W2; Cout = g_A; strideA = 256; wKpad = 256; }
    else                 { Ain = g_A; Wt = g_W3; Cout = g_B; strideA = 256; wKpad = 256; }

    extern __shared__ __align__(16) char sm[];
    uint32_t sb = smem_u32(sm);
    int tid = threadIdx.x, lane = tid & 31, wid = tid >> 5;
    int warp_m = wid >> 1, warp_n = wid & 1;
    int row0 = blockIdx.x * 128;
    int c0col = col00 + blockIdx.y * 64;
    int m = blockIdx.z;
    int ev = elites[m];
    size_t qbase = (size_t)m * r;
    size_t wbase = (size_t)ev * 256 * wKpad;
    const float* biasm = bias + (size_t)ev * N;

    float acc[2][NT][4];
    #pragma unroll
    for (int i = 0; i < 2; i++)
        #pragma unroll
        for (int j = 0; j < NT; j++)
            #pragma unroll
            for (int x = 0; x < 4; x++) acc[i][j][x] = 0.0f;

    uint32_t a_addr0 = sb + (uint32_t)((warp_m * 32 + (lane & 15)) * ASTR + (lane >> 4) * 16);
    uint32_t b_addr0;
    if (NT == 4) {
        b_addr0 = sb + (uint32_t)ABYTES +
            (uint32_t)((warp_n * 32 + (lane & 7) + ((lane >> 4) << 3)) * ASTR +
                       ((lane >> 3) & 1) * 16);
    } else {
        b_addr0 = sb + (uint32_t)ABYTES +
            (uint32_t)((warp_n * 8 + (lane & 7)) * ASTR + ((lane >> 3) & 1) * 16);
    }

    int chunks = (K + 63) >> 6;

#define ISSUE_CHUNK(c_, stg_) do { \
    uint32_t sbase = sb + (uint32_t)(stg_) * STG; \
    int ccol = (c_) * 64; \
    _Pragma("unroll") \
    for (int i = 0; i < 4; i++) { \
        int idx = tid + i * 256; \
        int rr = idx >> 3, u = idx & 7; \
        int grow = row0 + rr; \
        uint32_t pb = (grow < r) ? 16u : 0u; \
        size_t gix = (qbase + (grow < r ? grow : 0)) * (size_t)strideA + ccol + u * 8; \
        uint32_t d = sbase + (uint32_t)(rr * ASTR + u * 16); \
        CPA16(d, Ain + gix, pb); \
    } \
    _Pragma("unroll") \
    for (int i = 0; i < (BROWS * 8 + 255) / 256; i++) { \
        int idx = tid + i * 256; \
        if (idx < BROWS * 8) { \
            int nr = idx >> 3, u = idx & 7; \
            size_t gix = wbase + (size_t)(c0col + nr) * wKpad + ccol + u * 8; \
            uint32_t d = sbase + (uint32_t)ABYTES + (uint32_t)(nr * ASTR + u * 16); \
            CPA16(d, Wt + gix, 16u); \
        } \
    } \
    CPA_COMMIT(); \
} while (0)

    ISSUE_CHUNK(0, 0);

    for (int c = 0; c < chunks; c++) {
        int stg = c & 1;
        if (c + 1 < chunks) {
            ISSUE_CHUNK(c + 1, (c + 1) & 1);
            CPA_WAIT1();
        } else {
            CPA_WAIT0();
        }
        __syncthreads();

        uint32_t soff = (uint32_t)stg * STG;
        uint32_t a_addr = a_addr0 + soff;
        uint32_t b_addr = b_addr0 + soff;

        int steps = (K - c * 64 + 15) >> 4;
        if (steps > 4) steps = 4;

        // double-buffered fragment registers: [buf][...]
        uint32_t ah[2][2][4];
        if (NT == 4) {
            uint32_t bh[2][2][4];
            // preload step 0 into buf 0
            LDSM4A(ah[0][0], a_addr);
            LDSM4A(ah[0][1], a_addr + 16u * ASTR);
            LDSM4A(bh[0][0], b_addr);
            LDSM4A(bh[0][1], b_addr + 16u * ASTR);
            #pragma unroll
            for (int s = 0; s < 4; s++) {
                if (s >= steps) break;
                int cur = s & 1, nxt = cur ^ 1;
                if (s + 1 < steps) {
                    uint32_t ko = (uint32_t)((s + 1) * 32);
                    LDSM4A(ah[nxt][0], a_addr + ko);
                    LDSM4A(ah[nxt][1], a_addr + 16u * ASTR + ko);
                    LDSM4A(bh[nxt][0], b_addr + ko);
                    LDSM4A(bh[nxt][1], b_addr + 16u * ASTR + ko);
                }
                #pragma unroll
                for (int mi = 0; mi < 2; mi++)
                    #pragma unroll
                    for (int nn = 0; nn < 4; nn++)
                        MMA4(acc[mi][nn], ah[cur][mi], bh[cur][nn >> 1][(nn & 1) * 2],
                             bh[cur][nn >> 1][(nn & 1) * 2 + 1]);
            }
        } else {
            uint32_t b0[2], b1[2];
            LDSM4A(ah[0][0], a_addr);
            LDSM4A(ah[0][1], a_addr + 16u * ASTR);
            LDSM2(b0[0], b1[0], b_addr);
            #pragma unroll
            for (int s = 0; s < 4; s++) {
                if (s >= steps) break;
                int cur = s & 1, nxt = cur ^ 1;
                if (s + 1 < steps) {
                    uint32_t ko = (uint32_t)((s + 1) * 32);
                    LDSM4A(ah[nxt][0], a_addr + ko);
                    LDSM4A(ah[nxt][1], a_addr + 16u * ASTR + ko);
                    LDSM2(b0[nxt], b1[nxt], b_addr + ko);
                }
                #pragma unroll
                for (int mi = 0; mi < 2; mi++)
                    MMA4(acc[mi][0], ah[cur][mi], b0[cur], b1[cur]);
            }
        }
        __syncthreads();
    }
#undef ISSUE_CHUNK

    // epilogue: bias + swish, fp16 store (zeros for cols >= N)
    #pragma unroll
    for (int mi = 0; mi < 2; mi++) {
        int rlo = row0 + warp_m * 32 + mi * 16 + (lane >> 2);
        #pragma unroll
        for (int nn = 0; nn < NT; nn++) {
            int col = c0col + warp_n * (NT * 8) + nn * 8 + (lane & 3) * 2;
            if (rlo < r) {
                float v0 = 0.0f, v1 = 0.0f;
                if (col < N) {
                    float d0 = acc[mi][nn][0] + biasm[col];
                    float d1 = acc[mi][nn][1] + biasm[col + 1];
                    v0 = d0 / (1.0f + expf(-d0));
                    v1 = d1 / (1.0f + expf(-d1));
                }
                reinterpret_cast<uint32_t*>(Cout)[((qbase + rlo) * 256 + col) >> 1] =
                    pack_h2(v0, v1);
            }
            if (rlo + 8 < r) {
                float v0 = 0.0f, v1 = 0.0f;
                if (col < N) {
                    float d0 = acc[mi][nn][2] + biasm[col];
                    float d1 = acc[mi][nn][3] + biasm[col + 1];
                    v0 = d0 / (1.0f + expf(-d0));
                    v1 = d1 / (1.0f + expf(-d1));
                }
                reinterpret_cast<uint32_t*>(Cout)[((qbase + rlo + 8) * 256 + col) >> 1] =
                    pack_h2(v0, v1);
            }
        }
    }
}

// ======== layer-4 GEMM (N=66 padded 80) fused with sampling epilogue ========
__global__ void __launch_bounds__(256, 1) gemm_l4(
    const float* __restrict__ b4, const int* __restrict__ elites,
    int r, int K,
    const float* __restrict__ obs, float* __restrict__ out, int n)
{
    const __half* Ain = g_B;
    const __half* Wt  = g_W4;

    __shared__ __align__(16) char sm[20736];
    uint32_t sb = smem_u32(sm);
    int tid = threadIdx.x, lane = tid & 31, wid = tid >> 5;
    int warp_m = wid >> 1, warp_n = wid & 1;
    int row0 = blockIdx.x * 64;
    int m = blockIdx.y;
    int ev = elites[m];
    size_t qbase = (size_t)m * r;
    size_t wbase = (size_t)ev * 80 * 256;

    float d00 = 0.f, d01 = 0.f, d02 = 0.f, d03 = 0.f;
    float d10 = 0.f, d11 = 0.f, d12 = 0.f, d13 = 0.f;
    float d20 = 0.f, d21 = 0.f, d22 = 0.f, d23 = 0.f;
    float d30 = 0.f, d31 = 0.f, d32 = 0.f, d33 = 0.f;
    float d40 = 0.f, d41 = 0.f, d42 = 0.f, d43 = 0.f;

    uint32_t a_addr = sb + (uint32_t)((warp_m * 16 + (lane & 15)) * ASTR + (lane >> 4) * 16);
    uint32_t b_addr = sb + 9216u +
        (uint32_t)((warp_n * 40 + (lane & 7) + ((lane >> 4) << 3)) * ASTR + ((lane >> 3) & 1) * 16);
    uint32_t b2_addr = sb + 9216u +
        (uint32_t)((warp_n * 40 + 32 + (lane & 7)) * ASTR + ((lane >> 3) & 1) * 16);

    int chunks = (K + 63) >> 6;
    for (int c = 0; c < chunks; c++) {
        int ccol = c * 64;
        #pragma unroll
        for (int i = 0; i < 2; i++) {
            int idx = tid + i * 256;
            int rr = idx >> 3, u = idx & 7;
            int grow = row0 + rr;
            uint4 vh = make_uint4(0, 0, 0, 0);
            if (grow < r)
                vh = *reinterpret_cast<const uint4*>(Ain + (qbase + grow) * 256 + ccol + u * 8);
            *reinterpret_cast<uint4*>(sm + rr * ASTR + u * 16) = vh;
        }
        #pragma unroll
        for (int i = 0; i < 3; i++) {
            int idx = tid + i * 256;
            if (idx < 640) {
                int nr = idx >> 3, u = idx & 7;
                *reinterpret_cast<uint4*>(sm + 9216 + nr * ASTR + u * 16) =
                    *reinterpret_cast<const uint4*>(Wt + wbase + (size_t)nr * 256 + ccol + u * 8);
            }
        }
        __syncthreads();

        int steps = (K - ccol + 15) >> 4;
        if (steps > 4) steps = 4;
        for (int s = 0; s < steps; s++) {
            uint32_t ko = (uint32_t)(s * 32);
            uint32_t ah0, ah1, ah2, ah3;
            uint32_t bh0, bh1, bh2, bh3, bh4, bh5, bh6, bh7;
            uint32_t p0, p1;
            LDSM4(ah0, ah1, ah2, ah3, a_addr + ko);
            LDSM4(bh0, bh1, bh2, bh3, b_addr + ko);
            LDSM4(bh4, bh5, bh6, bh7, b_addr + 16u * ASTR + ko);
            LDSM2(p0, p1, b2_addr + ko);
            MMAQ(d0, ah0, ah1, ah2, ah3, bh0, bh1);
            MMAQ(d1, ah0, ah1, ah2, ah3, bh2, bh3);
            MMAQ(d2, ah0, ah1, ah2, ah3, bh4, bh5);
            MMAQ(d3, ah0, ah1, ah2, ah3, bh6, bh7);
            MMAQ(d4, ah0, ah1, ah2, ah3, p0, p1);
        }
        __syncthreads();
    }

    // stage accumulators to smem [64][80] f32
    float* stg = reinterpret_cast<float*>(sm);
    {
        int rlo = warp_m * 16 + (lane >> 2);
        int colb = warp_n * 40 + (lane & 3) * 2;
#define STG4(cp, toff) do { \
        int col = colb + (toff); \
        stg[rlo * 80 + col]           = cp##0; \
        stg[rlo * 80 + col + 1]       = cp##1; \
        stg[(rlo + 8) * 80 + col]     = cp##2; \
        stg[(rlo + 8) * 80 + col + 1] = cp##3; \
} while (0)
        STG4(d0, 0);
        STG4(d1, 8);
        STG4(d2, 16);
        STG4(d3, 24);
        STG4(d4, 32);
#undef STG4
    }
    __syncthreads();

    // per-row sampling / scatter / reward / terminal
    if (tid < 64) {
        int j = row0 + tid;
        if (j < r) {
            size_t q = qbase + j;
            int i = (int)g_src[q];
            if (i < n) {
                const float* bm = b4 + (size_t)ev * 66;
                const float* row = stg + tid * 80;
                uint32_t fbase = ((uint32_t)ev * (uint32_t)r + (uint32_t)j) * 33u;
                float sumsq = 0.0f;
                for (int d = 0; d < 33; d++) {
                    float mean = row[d] + bm[d];
                    float lv = row[33 + d] + bm[33 + d];
                    lv = 0.5f - softplusf(0.5f - lv);
                    lv = -10.0f + softplusf(lv + 10.0f);
                    float sd = expf(0.5f * lv);
                    float nz = normal_from_bits(rbits32(0u, 0u, fbase + (uint32_t)d));
                    float s = fmaf(nz, sd, mean);
                    if (d < 32) {
                        float no = s + obs[(size_t)i * OBS + d];
                        out[(size_t)i * OBS + d] = no;
                        sumsq += no * no;
                    } else {
                        out[(size_t)n * OBS + i] = s;
                    }
                }
                out[(size_t)n * (OBS + 1) + i] = (sqrtf(sumsq) > 50.0f) ? 1.0f : 0.0f;
            }
        }
    }
}

// ================= launch =================
extern "C" void kernel_launch(void* const* d_in, const int* in_sizes, int n_in,
                              void* d_out, int out_size) {
    const float* obs = (const float*)d_in[0];
    const float* act = (const float*)d_in[1];
    const float* mu  = (const float*)d_in[2];
    const float* sdv = (const float*)d_in[3];
    const float* W1  = (const float*)d_in[4];
    const float* b1  = (const float*)d_in[5];
    const float* W2  = (const float*)d_in[6];
    const float* b2  = (const float*)d_in[7];
    const float* W3  = (const float*)d_in[8];
    const float* b3  = (const float*)d_in[9];
    const float* W4  = (const float*)d_in[10];
    const float* b4  = (const float*)d_in[11];
    const int* elites = (const int*)d_in[12];

    int n = in_sizes[0] / OBS;
    int e = in_sizes[12];
    int r = (n - 1) / e + 1;
    int P = e * r;
    if (P > PMAX) P = PMAX;
    int Mm = in_sizes[4] / (CIN * HID);
    if (Mm > MMAX) Mm = MMAX;

    uint32_t nk0, nk1, s1a, s1b, s2a, s2b;
    threefry2x32(0u, 0u, 0u, 0u, nk0, nk1);
    threefry2x32(0u, 0u, 0u, 1u, s1a, s1b);
    threefry2x32(nk0, nk1, 0u, 1u, s2a, s2b);

    const int TB = 256;
    int gb = (P + TB - 1) / TB;

    // weight transpose/convert (device-side target selection)
    {
        int t1 = Mm * 256 * 64;
        prep_w<<<(t1 + 255) / 256, 256>>>(W1, 0, CIN, HID, 256, 64, t1);
        int t2 = Mm * 256 * 256;
        prep_w<<<(t2 + 255) / 256, 256>>>(W2, 1, HID, HID, 256, 256, t2);
        prep_w<<<(t2 + 255) / 256, 256>>>(W3, 2, HID, HID, 256, 256, t2);
        int t4 = Mm * 80 * 256;
        prep_w<<<(t4 + 255) / 256, 256>>>(W4, 3, HID, 2 * DOUTD, 80, 256, t4);
    }

    // permutation (two stable-rank rounds)
    zero_hist_kernel<<<256, 256>>>();
    hist_kernel<<<gb, TB>>>(s1a, s1b, P);
    scan_kernel<<<1, 1024>>>();
    scatter_kernel<<<gb, TB>>>(P);
    rank_kernel<<<gb, TB>>>(P, 0);
    zero_hist_kernel<<<256, 256>>>();
    hist_kernel<<<gb, TB>>>(s2a, s2b, P);
    scan_kernel<<<1, 1024>>>();
    scatter_kernel<<<gb, TB>>>(P);
    rank_kernel<<<gb, TB>>>(P, 1);

    gather_kernel<<<gb, TB>>>(obs, act, mu, sdv, n, P);

    // smem opt-in: NT=4 stage = 18432 + 9216 = 27648; x2 = 55296
    //              NT=1 stage = 18432 + 2304 = 20736; x2 = 41472
    cudaFuncSetAttribute(gemm128<4>, cudaFuncAttributeMaxDynamicSharedMemorySize, 55296);
    cudaFuncSetAttribute(gemm128<1>, cudaFuncAttributeMaxDynamicSharedMemorySize, 41472);

    int mt = (r + 127) / 128;
    dim3 gridF(mt, 3, e);   // full tiles: cols 0..191
    dim3 gridT(mt, 1, e);   // tail tile:  cols 192..199 (stores zeros for 200..207)
    gemm128<4><<<gridF, 256, 55296>>>(0, 0,   b1, elites, r, CIN, HID);
    gemm128<1><<<gridT, 256, 41472>>>(0, 192, b1, elites, r, CIN, HID);
    gemm128<4><<<gridF, 256, 55296>>>(1, 0,   b2, elites, r, HID, HID);
    gemm128<1><<<gridT, 256, 41472>>>(1, 192, b2, elites, r, HID, HID);
    gemm128<4><<<gridF, 256, 55296>>>(2, 0,   b3, elites, r, HID, HID);
    gemm128<1><<<gridT, 256, 41472>>>(2, 192, b3, elites, r, HID, HID);

    int mt4 = (r + 63) / 64;
    dim3 gridL4(mt4, e);
    gemm_l4<<<gridL4, 256>>>(b4, elites, r, HID, obs, (float*)d_out, n);
}

// round 13
// speedup vs baseline: 2.4860x; 1.0126x over previous
#include <cuda_runtime.h>
#include <cuda_fp16.h>
#include <stdint.h>

#define OBS   32
#define ACTD  8
#define CIN   40
#define HID   200
#define DOUTD 33
#define PMAX  100352
#define MMAX  8
#define OST   208   // activation row stride (fp16 elements) for hidden layers

// ================= scratch (device globals; referenced ONLY from device code) =========
__device__ uint32_t g_bits[PMAX];
__device__ unsigned long long g_slot[PMAX];
__device__ uint32_t g_hist[65536];
__device__ uint32_t g_bstart[65537];
__device__ uint32_t g_cursor[65536];
__device__ uint32_t g_rank1[PMAX];
__device__ uint32_t g_rank2[PMAX];
__device__ uint32_t g_src[PMAX];
// activations: L1 input at stride 64 in g_A; hidden activations stride OST=208.
__device__ __half g_A[(size_t)PMAX * OST];
__device__ __half g_B[(size_t)PMAX * OST];
// transposed fp16 weights: [m][n_pad][k_pad]
__device__ __half g_W1[MMAX * 256 * 64];
__device__ __half g_W2[MMAX * 256 * OST];
__device__ __half g_W3[MMAX * 256 * OST];
__device__ __half g_W4[MMAX * 80 * OST];

// ================= threefry (JAX partitionable) =================
__host__ __device__ __forceinline__ uint32_t rotl32(uint32_t v, int d) {
    return (v << d) | (v >> (32 - d));
}
__host__ __device__ __forceinline__ void threefry2x32(uint32_t k0, uint32_t k1,
                                                      uint32_t x0, uint32_t x1,
                                                      uint32_t& o0, uint32_t& o1) {
    uint32_t ks2 = k0 ^ k1 ^ 0x1BD11BDAu;
    x0 += k0; x1 += k1;
#define TFR(a) x0 += x1; x1 = rotl32(x1, a); x1 ^= x0;
    TFR(13) TFR(15) TFR(26) TFR(6)
    x0 += k1;  x1 += ks2 + 1u;
    TFR(17) TFR(29) TFR(16) TFR(24)
    x0 += ks2; x1 += k0 + 2u;
    TFR(13) TFR(15) TFR(26) TFR(6)
    x0 += k0;  x1 += k1 + 3u;
    TFR(17) TFR(29) TFR(16) TFR(24)
    x0 += k1;  x1 += ks2 + 4u;
    TFR(13) TFR(15) TFR(26) TFR(6)
    x0 += ks2; x1 += k0 + 5u;
#undef TFR
    o0 = x0; o1 = x1;
}
__device__ __forceinline__ uint32_t rbits32(uint32_t k0, uint32_t k1, uint32_t idx) {
    uint32_t a, b;
    threefry2x32(k0, k1, 0u, idx, a, b);
    return a ^ b;
}
__device__ __forceinline__ float softplusf(float x) {
    return fmaxf(x, 0.0f) + log1pf(expf(-fabsf(x)));
}
__device__ __forceinline__ float normal_from_bits(uint32_t bits) {
    float f = __uint_as_float((bits >> 9) | 0x3F800000u) - 1.0f;
    const float lo = -0.99999994f;
    float val = fmaf(f, 2.0f, lo);
    val = fmaxf(lo, val);
    return 1.41421354f * erfinvf(val);
}

// ================= asm macros =================
__device__ __forceinline__ uint32_t smem_u32(const void* p) {
    uint32_t a;
    asm("{ .reg .u64 t; cvta.to.shared.u64 t, %1; cvt.u32.u64 %0, t; }" : "=r"(a) : "l"(p));
    return a;
}
#define LDSM4(r0, r1, r2, r3, addr) \
    asm volatile("ldmatrix.sync.aligned.m8n8.x4.shared.b16 {%0,%1,%2,%3}, [%4];" \
                 : "=r"(r0), "=r"(r1), "=r"(r2), "=r"(r3) : "r"(addr))
#define LDSM4A(rr, addr) LDSM4((rr)[0], (rr)[1], (rr)[2], (rr)[3], addr)
#define LDSM2(r0, r1, addr) \
    asm volatile("ldmatrix.sync.aligned.m8n8.x2.shared.b16 {%0,%1}, [%2];" \
                 : "=r"(r0), "=r"(r1) : "r"(addr))
#define MMAQ(cp, a0, a1, a2, a3, b0, b1) \
    asm volatile("mma.sync.aligned.m16n8k16.row.col.f32.f16.f16.f32 " \
                 "{%0,%1,%2,%3}, {%4,%5,%6,%7}, {%8,%9}, {%0,%1,%2,%3};" \
                 : "+f"(cp##0), "+f"(cp##1), "+f"(cp##2), "+f"(cp##3) \
                 : "r"(a0), "r"(a1), "r"(a2), "r"(a3), "r"(b0), "r"(b1))
#define MMA4(c, a, b0, b1) \
    asm volatile("mma.sync.aligned.m16n8k16.row.col.f32.f16.f16.f32 " \
                 "{%0,%1,%2,%3}, {%4,%5,%6,%7}, {%8,%9}, {%0,%1,%2,%3};" \
                 : "+f"((c)[0]), "+f"((c)[1]), "+f"((c)[2]), "+f"((c)[3]) \
                 : "r"((a)[0]), "r"((a)[1]), "r"((a)[2]), "r"((a)[3]), "r"(b0), "r"(b1))
#define CPA16(dst, src, pb) \
    asm volatile("cp.async.cg.shared.global [%0], [%1], 16, %2;" \
                 :: "r"(dst), "l"(src), "r"(pb) : "memory")
#define CPA_COMMIT() asm volatile("cp.async.commit_group;" ::: "memory")
#define CPA_WAIT0() asm volatile("cp.async.wait_group 0;" ::: "memory")
#define CPA_WAIT1() asm volatile("cp.async.wait_group 1;" ::: "memory")

__device__ __forceinline__ uint32_t pack_h2(float v0, float v1) {
    __half h0 = __float2half_rn(v0), h1 = __float2half_rn(v1);
    return (uint32_t)__half_as_ushort(h0) | ((uint32_t)__half_as_ushort(h1) << 16);
}

// ================= permutation machinery (known clean) =================
__global__ void zero_hist_kernel() {
    int t = blockIdx.x * blockDim.x + threadIdx.x;
    if (t < 65536) g_hist[t] = 0u;
}
__global__ void hist_kernel(uint32_t k0, uint32_t k1, int P) {
    int p = blockIdx.x * blockDim.x + threadIdx.x;
    if (p >= P) return;
    uint32_t b = rbits32(k0, k1, (uint32_t)p);
    g_bits[p] = b;
    atomicAdd(&g_hist[b >> 16], 1u);
}
__global__ void scan_kernel() {
    __shared__ uint32_t part[1024];
    int t = threadIdx.x;
    uint32_t s = 0;
    #pragma unroll 8
    for (int i = 0; i < 64; i++) s += g_hist[t * 64 + i];
    part[t] = s;
    __syncthreads();
    for (int off = 1; off < 1024; off <<= 1) {
        uint32_t v = part[t];
        uint32_t add = (t >= off) ? part[t - off] : 0u;
        __syncthreads();
        part[t] = v + add;
        __syncthreads();
    }
    uint32_t run = (t == 0) ? 0u : part[t - 1];
    for (int i = 0; i < 64; i++) {
        int idx = t * 64 + i;
        g_bstart[idx] = run;
        g_cursor[idx] = run;
        run += g_hist[idx];
    }
    if (t == 1023) g_bstart[65536] = run;
}
__global__ void scatter_kernel(int P) {
    int p = blockIdx.x * blockDim.x + threadIdx.x;
    if (p >= P) return;
    uint32_t b = g_bits[p];
    uint32_t slot = atomicAdd(&g_cursor[b >> 16], 1u);
    g_slot[slot] = (((unsigned long long)(b & 0xFFFFu)) << 17) | (unsigned long long)p;
}
__global__ void rank_kernel(int P, int round) {
    int p = blockIdx.x * blockDim.x + threadIdx.x;
    if (p >= P) return;
    uint32_t b = g_bits[p];
    uint32_t hi = b >> 16;
    uint32_t s0 = g_bstart[hi], s1 = g_bstart[hi + 1];
    unsigned long long my = (((unsigned long long)(b & 0xFFFFu)) << 17) | (unsigned long long)p;
    uint32_t c = 0;
    for (uint32_t s = s0; s < s1; s++) c += (g_slot[s] < my) ? 1u : 0u;
    uint32_t rk = s0 + c;
    if (round == 0) g_rank1[p] = rk; else g_rank2[p] = rk;
}

// ================= gather + normalize -> fp16 (stride 64 in g_A) =================
__global__ void gather_kernel(const float* __restrict__ obs, const float* __restrict__ act,
                              const float* __restrict__ mu, const float* __restrict__ sd,
                              int n, int P) {
    int i = blockIdx.x * blockDim.x + threadIdx.x;
    if (i >= P) return;
    uint32_t q = g_rank2[g_rank1[i]];
    g_src[q] = (uint32_t)i;
    uint32_t* oh = reinterpret_cast<uint32_t*>(g_A + (size_t)q * 64);
    if (i < n) {
        #pragma unroll
        for (int c = 0; c < CIN; c += 2) {
            float x0 = (c < OBS) ? obs[(size_t)i * OBS + c] : act[(size_t)i * ACTD + (c - OBS)];
            float x1 = (c + 1 < OBS) ? obs[(size_t)i * OBS + c + 1]
                                     : act[(size_t)i * ACTD + (c + 1 - OBS)];
            float v0 = (x0 - mu[c]) / sd[c];
            float v1 = (x1 - mu[c + 1]) / sd[c + 1];
            oh[c >> 1] = pack_h2(v0, v1);
        }
        #pragma unroll
        for (int c = CIN; c < 64; c += 2) oh[c >> 1] = 0u;
    } else {
        #pragma unroll
        for (int c = 0; c < 64; c += 2) oh[c >> 1] = 0u;
    }
}

// ====== weight transpose/convert: W[m][k][n] -> Wt[m][n_pad][k_pad] fp16 ======
__global__ void prep_w(const float* __restrict__ W, int which,
                       int K, int N, int Nrows, int Kpad, int total) {
    int t = blockIdx.x * blockDim.x + threadIdx.x;
    if (t >= total) return;
    __half* Wd;
    if (which == 0)      Wd = g_W1;
    else if (which == 1) Wd = g_W2;
    else if (which == 2) Wd = g_W3;
    else                 Wd = g_W4;
    int kp = t % Kpad;
    int rest = t / Kpad;
    int nn = rest % Nrows;
    int mm = rest / Nrows;
    float v = 0.0f;
    if (nn < N && kp < K) v = W[((size_t)mm * K + kp) * N + nn];
    Wd[t] = __float2half_rn(v);
}

// ======== persistent-A hidden-layer GEMM: one CTA = 128 rows x ALL 200 cols ========
// KSEG = 16B segments per input row: 8 (stride 64, layer 0) or 26 (stride 208).
// A loaded to smem ONCE; 4 W tiles (64 n-cols each) double-buffered + prefetched.
template <int KSEG>
__global__ void __launch_bounds__(256, 2) gemm_full(
    int layer, const float* __restrict__ bias, const int* __restrict__ elites,
    int r, int K, int N)
{
    constexpr int SA   = KSEG * 8;          // input row stride (elements)
    constexpr int AROW = KSEG * 16 + 16;    // smem row stride (bytes), conflict-free
    constexpr int ASM  = 128 * AROW;
    constexpr int WSM  = 64 * AROW;

    const __half* Ain;
    const __half* Wt;
    __half* Cout;
    if (layer == 0)      { Ain = g_A; Wt = g_W1; Cout = g_B; }
    else if (layer == 1) { Ain = g_B; Wt = g_W2; Cout = g_A; }
    else                 { Ain = g_A; Wt = g_W3; Cout = g_B; }

    extern __shared__ __align__(16) char sm[];
    uint32_t sb = smem_u32(sm);
    int tid = threadIdx.x, lane = tid & 31, wid = tid >> 5;
    int warp_m = wid >> 1, warp_n = wid & 1;
    int row0 = blockIdx.x * 128;
    int m = blockIdx.y;
    int ev = elites[m];
    size_t qbase = (size_t)m * r;
    size_t wbase = (size_t)ev * 256 * SA;
    const float* biasm = bias + (size_t)ev * N;

    int steps = (K + 15) >> 4;

    // ---- issue A load (once) ----
    #pragma unroll
    for (int it = 0; it < (128 * KSEG + 255) / 256; it++) {
        int idx = tid + it * 256;
        if (idx < 128 * KSEG) {
            int rr = idx / KSEG, u = idx % KSEG;
            int grow = row0 + rr;
            uint32_t pb = (grow < r) ? 16u : 0u;
            size_t gix = (qbase + (grow < r ? grow : 0)) * (size_t)SA + (size_t)(u * 8);
            CPA16(sb + (uint32_t)(rr * AROW + u * 16), Ain + gix, pb);
        }
    }
    CPA_COMMIT();

#define LOAD_W(t_, buf_) do { \
    uint32_t wb = sb + (uint32_t)ASM + (uint32_t)(buf_) * (uint32_t)WSM; \
    _Pragma("unroll") \
    for (int it = 0; it < (64 * KSEG + 255) / 256; it++) { \
        int idx = tid + it * 256; \
        if (idx < 64 * KSEG) { \
            int nr = idx / KSEG, u = idx % KSEG; \
            size_t gix = wbase + (size_t)((t_) * 64 + nr) * (size_t)SA + (size_t)(u * 8); \
            CPA16(wb + (uint32_t)(nr * AROW + u * 16), Wt + gix, 16u); \
        } \
    } \
    CPA_COMMIT(); \
} while (0)

    LOAD_W(0, 0);

    uint32_t a_addr = sb + (uint32_t)((warp_m * 32 + (lane & 15)) * AROW + (lane >> 4) * 16);

    for (int t = 0; t < 4; t++) {
        if (t + 1 < 4) { LOAD_W(t + 1, (t + 1) & 1); CPA_WAIT1(); }
        else CPA_WAIT0();
        __syncthreads();

        uint32_t wb = sb + (uint32_t)ASM + (uint32_t)(t & 1) * (uint32_t)WSM;
        uint32_t b_addr = wb +
            (uint32_t)((warp_n * 32 + (lane & 7) + ((lane >> 4) << 3)) * AROW +
                       ((lane >> 3) & 1) * 16);

        float acc[2][4][4];
        #pragma unroll
        for (int i = 0; i < 2; i++)
            #pragma unroll
            for (int j = 0; j < 4; j++)
                #pragma unroll
                for (int x = 0; x < 4; x++) acc[i][j][x] = 0.0f;

        for (int s = 0; s < steps; s++) {
            uint32_t ko = (uint32_t)(s * 32);
            uint32_t ah[2][4], bh[2][4];
            LDSM4A(ah[0], a_addr + ko);
            LDSM4A(ah[1], a_addr + 16u * AROW + ko);
            LDSM4A(bh[0], b_addr + ko);
            LDSM4A(bh[1], b_addr + 16u * AROW + ko);
            #pragma unroll
            for (int mi = 0; mi < 2; mi++)
                #pragma unroll
                for (int nn = 0; nn < 4; nn++)
                    MMA4(acc[mi][nn], ah[mi], bh[nn >> 1][(nn & 1) * 2],
                         bh[nn >> 1][(nn & 1) * 2 + 1]);
        }

        // epilogue: bias + swish, fp16 store at stride OST (zeros for N<=col<OST)
        #pragma unroll
        for (int mi = 0; mi < 2; mi++) {
            int rlo = row0 + warp_m * 32 + mi * 16 + (lane >> 2);
            #pragma unroll
            for (int nn = 0; nn < 4; nn++) {
                int col = t * 64 + warp_n * 32 + nn * 8 + (lane & 3) * 2;
                if (col < OST) {
                    if (rlo < r) {
                        float v0 = 0.0f, v1 = 0.0f;
                        if (col < N) {
                            float d0 = acc[mi][nn][0] + biasm[col];
                            float d1 = acc[mi][nn][1] + biasm[col + 1];
                            v0 = d0 / (1.0f + expf(-d0));
                            v1 = d1 / (1.0f + expf(-d1));
                        }
                        reinterpret_cast<uint32_t*>(Cout)[((qbase + rlo) * OST + col) >> 1] =
                            pack_h2(v0, v1);
                    }
                    if (rlo + 8 < r) {
                        float v0 = 0.0f, v1 = 0.0f;
                        if (col < N) {
                            float d0 = acc[mi][nn][2] + biasm[col];
                            float d1 = acc[mi][nn][3] + biasm[col + 1];
                            v0 = d0 / (1.0f + expf(-d0));
                            v1 = d1 / (1.0f + expf(-d1));
                        }
                        reinterpret_cast<uint32_t*>(Cout)[((qbase + rlo + 8) * OST + col) >> 1] =
                            pack_h2(v0, v1);
                    }
                }
            }
        }
        __syncthreads();
    }
#undef LOAD_W
}

// ======== layer-4 GEMM (N=66 padded 80) fused with sampling epilogue ========
__global__ void __launch_bounds__(256, 1) gemm_l4(
    const float* __restrict__ b4, const int* __restrict__ elites,
    int r, int K,
    const float* __restrict__ obs, float* __restrict__ out, int n)
{
    const __half* Ain = g_B;
    const __half* Wt  = g_W4;

    // smem: A [0,9216) stride 144, B [9216,20736) stride 144; f32[64][80]=20480 fits
    __shared__ __align__(16) char sm[20736];
    uint32_t sb = smem_u32(sm);
    int tid = threadIdx.x, lane = tid & 31, wid = tid >> 5;
    int warp_m = wid >> 1, warp_n = wid & 1;
    int row0 = blockIdx.x * 64;
    int m = blockIdx.y;
    int ev = elites[m];
    size_t qbase = (size_t)m * r;
    size_t wbase = (size_t)ev * 80 * OST;

    float d00 = 0.f, d01 = 0.f, d02 = 0.f, d03 = 0.f;
    float d10 = 0.f, d11 = 0.f, d12 = 0.f, d13 = 0.f;
    float d20 = 0.f, d21 = 0.f, d22 = 0.f, d23 = 0.f;
    float d30 = 0.f, d31 = 0.f, d32 = 0.f, d33 = 0.f;
    float d40 = 0.f, d41 = 0.f, d42 = 0.f, d43 = 0.f;

    uint32_t a_addr = sb + (uint32_t)((warp_m * 16 + (lane & 15)) * 144 + (lane >> 4) * 16);
    uint32_t b_addr = sb + 9216u +
        (uint32_t)((warp_n * 40 + (lane & 7) + ((lane >> 4) << 3)) * 144 + ((lane >> 3) & 1) * 16);
    uint32_t b2_addr = sb + 9216u +
        (uint32_t)((warp_n * 40 + 32 + (lane & 7)) * 144 + ((lane >> 3) & 1) * 16);

    int chunks = (K + 63) >> 6;
    for (int c = 0; c < chunks; c++) {
        int ccol = c * 64;
        #pragma unroll
        for (int i = 0; i < 2; i++) {
            int idx = tid + i * 256;
            int rr = idx >> 3, u = idx & 7;
            int grow = row0 + rr;
            int kc = ccol + u * 8;
            uint4 vh = make_uint4(0, 0, 0, 0);
            if (grow < r && kc < OST)
                vh = *reinterpret_cast<const uint4*>(Ain + (qbase + grow) * OST + kc);
            *reinterpret_cast<uint4*>(sm + rr * 144 + u * 16) = vh;
        }
        #pragma unroll
        for (int i = 0; i < 3; i++) {
            int idx = tid + i * 256;
            if (idx < 640) {
                int nr = idx >> 3, u = idx & 7;
                int kc = ccol + u * 8;
                uint4 wv = make_uint4(0, 0, 0, 0);
                if (kc < OST)
                    wv = *reinterpret_cast<const uint4*>(Wt + wbase + (size_t)nr * OST + kc);
                *reinterpret_cast<uint4*>(sm + 9216 + nr * 144 + u * 16) = wv;
            }
        }
        __syncthreads();

        int steps = (K - ccol + 15) >> 4;
        if (steps > 4) steps = 4;
        for (int s = 0; s < steps; s++) {
            uint32_t ko = (uint32_t)(s * 32);
            uint32_t ah0, ah1, ah2, ah3;
            uint32_t bh0, bh1, bh2, bh3, bh4, bh5, bh6, bh7;
            uint32_t p0, p1;
            LDSM4(ah0, ah1, ah2, ah3, a_addr + ko);
            LDSM4(bh0, bh1, bh2, bh3, b_addr + ko);
            LDSM4(bh4, bh5, bh6, bh7, b_addr + 16u * 144 + ko);
            LDSM2(p0, p1, b2_addr + ko);
            MMAQ(d0, ah0, ah1, ah2, ah3, bh0, bh1);
            MMAQ(d1, ah0, ah1, ah2, ah3, bh2, bh3);
            MMAQ(d2, ah0, ah1, ah2, ah3, bh4, bh5);
            MMAQ(d3, ah0, ah1, ah2, ah3, bh6, bh7);
            MMAQ(d4, ah0, ah1, ah2, ah3, p0, p1);
        }
        __syncthreads();
    }

    // stage accumulators to smem [64][80] f32
    float* stg = reinterpret_cast<float*>(sm);
    {
        int rlo = warp_m * 16 + (lane >> 2);
        int colb = warp_n * 40 + (lane & 3) * 2;
#define STG4(cp, toff) do { \
        int col = colb + (toff); \
        stg[rlo * 80 + col]           = cp##0; \
        stg[rlo * 80 + col + 1]       = cp##1; \
        stg[(rlo + 8) * 80 + col]     = cp##2; \
        stg[(rlo + 8) * 80 + col + 1] = cp##3; \
} while (0)
        STG4(d0, 0);
        STG4(d1, 8);
        STG4(d2, 16);
        STG4(d3, 24);
        STG4(d4, 32);
#undef STG4
    }
    __syncthreads();

    // per-row sampling / scatter / reward / terminal
    if (tid < 64) {
        int j = row0 + tid;
        if (j < r) {
            size_t q = qbase + j;
            int i = (int)g_src[q];
            if (i < n) {
                const float* bm = b4 + (size_t)ev * 66;
                const float* row = stg + tid * 80;
                uint32_t fbase = ((uint32_t)ev * (uint32_t)r + (uint32_t)j) * 33u;
                float sumsq = 0.0f;
                for (int d = 0; d < 33; d++) {
                    float mean = row[d] + bm[d];
                    float lv = row[33 + d] + bm[33 + d];
                    lv = 0.5f - softplusf(0.5f - lv);
                    lv = -10.0f + softplusf(lv + 10.0f);
                    float sd = expf(0.5f * lv);
                    float nz = normal_from_bits(rbits32(0u, 0u, fbase + (uint32_t)d));
                    float s = fmaf(nz, sd, mean);
                    if (d < 32) {
                        float no = s + obs[(size_t)i * OBS + d];
                        out[(size_t)i * OBS + d] = no;
                        sumsq += no * no;
                    } else {
                        out[(size_t)n * OBS + i] = s;
                    }
                }
                out[(size_t)n * (OBS + 1) + i] = (sqrtf(sumsq) > 50.0f) ? 1.0f : 0.0f;
            }
        }
    }
}

// ================= launch =================
extern "C" void kernel_launch(void* const* d_in, const int* in_sizes, int n_in,
                              void* d_out, int out_size) {
    const float* obs = (const float*)d_in[0];
    const float* act = (const float*)d_in[1];
    const float* mu  = (const float*)d_in[2];
    const float* sdv = (const float*)d_in[3];
    const float* W1  = (const float*)d_in[4];
    const float* b1  = (const float*)d_in[5];
    const float* W2  = (const float*)d_in[6];
    const float* b2  = (const float*)d_in[7];
    const float* W3  = (const float*)d_in[8];
    const float* b3  = (const float*)d_in[9];
    const float* W4  = (const float*)d_in[10];
    const float* b4  = (const float*)d_in[11];
    const int* elites = (const int*)d_in[12];

    int n = in_sizes[0] / OBS;
    int e = in_sizes[12];
    int r = (n - 1) / e + 1;
    int P = e * r;
    if (P > PMAX) P = PMAX;
    int Mm = in_sizes[4] / (CIN * HID);
    if (Mm > MMAX) Mm = MMAX;

    uint32_t nk0, nk1, s1a, s1b, s2a, s2b;
    threefry2x32(0u, 0u, 0u, 0u, nk0, nk1);
    threefry2x32(0u, 0u, 0u, 1u, s1a, s1b);
    threefry2x32(nk0, nk1, 0u, 1u, s2a, s2b);

    const int TB = 256;
    int gb = (P + TB - 1) / TB;

    // weight transpose/convert (device-side target selection)
    {
        int t1 = Mm * 256 * 64;
        prep_w<<<(t1 + 255) / 256, 256>>>(W1, 0, CIN, HID, 256, 64, t1);
        int t2 = Mm * 256 * OST;
        prep_w<<<(t2 + 255) / 256, 256>>>(W2, 1, HID, HID, 256, OST, t2);
        prep_w<<<(t2 + 255) / 256, 256>>>(W3, 2, HID, HID, 256, OST, t2);
        int t4 = Mm * 80 * OST;
        prep_w<<<(t4 + 255) / 256, 256>>>(W4, 3, HID, 2 * DOUTD, 80, OST, t4);
    }

    // permutation (two stable-rank rounds)
    zero_hist_kernel<<<256, 256>>>();
    hist_kernel<<<gb, TB>>>(s1a, s1b, P);
    scan_kernel<<<1, 1024>>>();
    scatter_kernel<<<gb, TB>>>(P);
    rank_kernel<<<gb, TB>>>(P, 0);
    zero_hist_kernel<<<256, 256>>>();
    hist_kernel<<<gb, TB>>>(s2a, s2b, P);
    scan_kernel<<<1, 1024>>>();
    scatter_kernel<<<gb, TB>>>(P);
    rank_kernel<<<gb, TB>>>(P, 1);

    gather_kernel<<<gb, TB>>>(obs, act, mu, sdv, n, P);

    // smem: KSEG=8  -> ASM 18432 + 2*WSM 9216  = 36864
    //       KSEG=26 -> ASM 55296 + 2*WSM 27648 = 110592
    cudaFuncSetAttribute(gemm_full<8>,  cudaFuncAttributeMaxDynamicSharedMemorySize, 36864);
    cudaFuncSetAttribute(gemm_full<26>, cudaFuncAttributeMaxDynamicSharedMemorySize, 110592);

    int mt = (r + 127) / 128;
    dim3 gridH(mt, e);
    gemm_full<8><<<gridH, 256, 36864>>>(0, b1, elites, r, CIN, HID);
    gemm_full<26><<<gridH, 256, 110592>>>(1, b2, elites, r, HID, HID);
    gemm_full<26><<<gridH, 256, 110592>>>(2, b3, elites, r, HID, HID);

    int mt4 = (r + 63) / 64;
    dim3 gridL4(mt4, e);
    gemm_l4<<<gridL4, 256>>>(b4, elites, r, HID, obs, (float*)d_out, n);
}

// round 14
// speedup vs baseline: 4.4437x; 1.7875x over previous
#include <cuda_runtime.h>
#include <cuda_fp16.h>
#include <stdint.h>

#define OBS   32
#define ACTD  8
#define CIN   40
#define HID   200
#define DOUTD 33
#define PMAX  100352
#define MMAX  8
#define OST   208   // activation row stride (fp16 elements) for hidden layers
#define NB    4096  // rank buckets (top 12 bits)

// ================= scratch (device globals; referenced ONLY from device code) =========
__device__ uint32_t g_bits[PMAX];
__device__ uint32_t g_bits2[PMAX];
__device__ unsigned long long g_slot[PMAX];
__device__ unsigned long long g_slot2[PMAX];
__device__ uint32_t g_hist[2 * NB];
__device__ uint32_t g_bstart[2 * (NB + 1)];
__device__ uint32_t g_cursor[2 * NB];
__device__ uint32_t g_rank1[PMAX];
__device__ uint32_t g_rank2[PMAX];
__device__ uint32_t g_src[PMAX];
// activations: L1 input at stride 64 in g_A; hidden activations stride OST=208.
__device__ __half g_A[(size_t)PMAX * OST];
__device__ __half g_B[(size_t)PMAX * OST];
// transposed fp16 weights: [m][n_pad][k_pad]
__device__ __half g_W1[MMAX * 256 * 64];
__device__ __half g_W2[MMAX * 256 * OST];
__device__ __half g_W3[MMAX * 256 * OST];
__device__ __half g_W4[MMAX * 80 * OST];

// ================= threefry (JAX partitionable) =================
__host__ __device__ __forceinline__ uint32_t rotl32(uint32_t v, int d) {
    return (v << d) | (v >> (32 - d));
}
__host__ __device__ __forceinline__ void threefry2x32(uint32_t k0, uint32_t k1,
                                                      uint32_t x0, uint32_t x1,
                                                      uint32_t& o0, uint32_t& o1) {
    uint32_t ks2 = k0 ^ k1 ^ 0x1BD11BDAu;
    x0 += k0; x1 += k1;
#define TFR(a) x0 += x1; x1 = rotl32(x1, a); x1 ^= x0;
    TFR(13) TFR(15) TFR(26) TFR(6)
    x0 += k1;  x1 += ks2 + 1u;
    TFR(17) TFR(29) TFR(16) TFR(24)
    x0 += ks2; x1 += k0 + 2u;
    TFR(13) TFR(15) TFR(26) TFR(6)
    x0 += k0;  x1 += k1 + 3u;
    TFR(17) TFR(29) TFR(16) TFR(24)
    x0 += k1;  x1 += ks2 + 4u;
    TFR(13) TFR(15) TFR(26) TFR(6)
    x0 += ks2; x1 += k0 + 5u;
#undef TFR
    o0 = x0; o1 = x1;
}
__device__ __forceinline__ uint32_t rbits32(uint32_t k0, uint32_t k1, uint32_t idx) {
    uint32_t a, b;
    threefry2x32(k0, k1, 0u, idx, a, b);
    return a ^ b;
}
__device__ __forceinline__ float softplusf(float x) {
    return fmaxf(x, 0.0f) + log1pf(expf(-fabsf(x)));
}
__device__ __forceinline__ float normal_from_bits(uint32_t bits) {
    float f = __uint_as_float((bits >> 9) | 0x3F800000u) - 1.0f;
    const float lo = -0.99999994f;
    float val = fmaf(f, 2.0f, lo);
    val = fmaxf(lo, val);
    return 1.41421354f * erfinvf(val);
}

// ================= asm macros =================
__device__ __forceinline__ uint32_t smem_u32(const void* p) {
    uint32_t a;
    asm("{ .reg .u64 t; cvta.to.shared.u64 t, %1; cvt.u32.u64 %0, t; }" : "=r"(a) : "l"(p));
    return a;
}
#define LDSM4(r0, r1, r2, r3, addr) \
    asm volatile("ldmatrix.sync.aligned.m8n8.x4.shared.b16 {%0,%1,%2,%3}, [%4];" \
                 : "=r"(r0), "=r"(r1), "=r"(r2), "=r"(r3) : "r"(addr))
#define LDSM4A(rr, addr) LDSM4((rr)[0], (rr)[1], (rr)[2], (rr)[3], addr)
#define LDSM2(r0, r1, addr) \
    asm volatile("ldmatrix.sync.aligned.m8n8.x2.shared.b16 {%0,%1}, [%2];" \
                 : "=r"(r0), "=r"(r1) : "r"(addr))
#define MMAQ(cp, a0, a1, a2, a3, b0, b1) \
    asm volatile("mma.sync.aligned.m16n8k16.row.col.f32.f16.f16.f32 " \
                 "{%0,%1,%2,%3}, {%4,%5,%6,%7}, {%8,%9}, {%0,%1,%2,%3};" \
                 : "+f"(cp##0), "+f"(cp##1), "+f"(cp##2), "+f"(cp##3) \
                 : "r"(a0), "r"(a1), "r"(a2), "r"(a3), "r"(b0), "r"(b1))
#define MMA4(c, a, b0, b1) \
    asm volatile("mma.sync.aligned.m16n8k16.row.col.f32.f16.f16.f32 " \
                 "{%0,%1,%2,%3}, {%4,%5,%6,%7}, {%8,%9}, {%0,%1,%2,%3};" \
                 : "+f"((c)[0]), "+f"((c)[1]), "+f"((c)[2]), "+f"((c)[3]) \
                 : "r"((a)[0]), "r"((a)[1]), "r"((a)[2]), "r"((a)[3]), "r"(b0), "r"(b1))
#define CPA16(dst, src, pb) \
    asm volatile("cp.async.cg.shared.global [%0], [%1], 16, %2;" \
                 :: "r"(dst), "l"(src), "r"(pb) : "memory")
#define CPA_COMMIT() asm volatile("cp.async.commit_group;" ::: "memory")
#define CPA_WAIT0() asm volatile("cp.async.wait_group 0;" ::: "memory")
#define CPA_WAIT1() asm volatile("cp.async.wait_group 1;" ::: "memory")

__device__ __forceinline__ uint32_t pack_h2(float v0, float v1) {
    __half h0 = __float2half_rn(v0), h1 = __float2half_rn(v1);
    return (uint32_t)__half_as_ushort(h0) | ((uint32_t)__half_as_ushort(h1) << 16);
}

// ================= merged permutation machinery =================
__global__ void zero_hist_kernel() {
    int t = blockIdx.x * blockDim.x + threadIdx.x;
    if (t < 2 * NB) g_hist[t] = 0u;
}
// both rounds' bits + histograms in one pass
__global__ void hist2_kernel(uint32_t k1a, uint32_t k1b, uint32_t k2a, uint32_t k2b, int P) {
    int p = blockIdx.x * blockDim.x + threadIdx.x;
    if (p >= P) return;
    uint32_t b1 = rbits32(k1a, k1b, (uint32_t)p);
    uint32_t b2 = rbits32(k2a, k2b, (uint32_t)p);
    g_bits[p] = b1;
    g_bits2[p] = b2;
    atomicAdd(&g_hist[b1 >> 20], 1u);
    atomicAdd(&g_hist[NB + (b2 >> 20)], 1u);
}
// scan both 4096-bucket histograms (one block, 1024 threads: halves of 512)
__global__ void scan2_kernel() {
    __shared__ uint32_t part[1024];
    int t = threadIdx.x;
    int half = t >> 9;       // 0 or 1
    int lt = t & 511;
    uint32_t hbase = (uint32_t)half * NB;
    uint32_t s = 0;
    #pragma unroll
    for (int i = 0; i < 8; i++) s += g_hist[hbase + lt * 8 + i];
    part[t] = s;
    __syncthreads();
    for (int off = 1; off < 512; off <<= 1) {
        uint32_t v = part[t];
        uint32_t add = (lt >= off) ? part[t - off] : 0u;
        __syncthreads();
        part[t] = v + add;
        __syncthreads();
    }
    uint32_t run = (lt == 0) ? 0u : part[t - 1];
    uint32_t bb = (uint32_t)half * (NB + 1);
    for (int i = 0; i < 8; i++) {
        int idx = lt * 8 + i;
        g_bstart[bb + idx] = run;
        g_cursor[hbase + idx] = run;
        run += g_hist[hbase + idx];
    }
    if (lt == 511) g_bstart[bb + NB] = run;
}
__global__ void scatter2_kernel(int P) {
    int p = blockIdx.x * blockDim.x + threadIdx.x;
    if (p >= P) return;
    uint32_t b1 = g_bits[p];
    uint32_t s1 = atomicAdd(&g_cursor[b1 >> 20], 1u);
    g_slot[s1] = (((unsigned long long)(b1 & 0xFFFFFu)) << 17) | (unsigned long long)p;
    uint32_t b2 = g_bits2[p];
    uint32_t s2 = atomicAdd(&g_cursor[NB + (b2 >> 20)], 1u);
    g_slot2[s2] = (((unsigned long long)(b2 & 0xFFFFFu)) << 17) | (unsigned long long)p;
}
__global__ void rank2_kernel(int P) {
    int p = blockIdx.x * blockDim.x + threadIdx.x;
    if (p >= P) return;
    {
        uint32_t b = g_bits[p];
        uint32_t hi = b >> 20;
        uint32_t s0 = g_bstart[hi], s1 = g_bstart[hi + 1];
        unsigned long long my = (((unsigned long long)(b & 0xFFFFFu)) << 17) | (unsigned long long)p;
        uint32_t c = 0;
        for (uint32_t s = s0; s < s1; s++) c += (g_slot[s] < my) ? 1u : 0u;
        g_rank1[p] = s0 + c;
    }
    {
        uint32_t b = g_bits2[p];
        uint32_t hi = b >> 20;
        uint32_t s0 = g_bstart[(NB + 1) + hi], s1 = g_bstart[(NB + 1) + hi + 1];
        unsigned long long my = (((unsigned long long)(b & 0xFFFFFu)) << 17) | (unsigned long long)p;
        uint32_t c = 0;
        for (uint32_t s = s0; s < s1; s++) c += (g_slot2[s] < my) ? 1u : 0u;
        g_rank2[p] = s0 + c;
    }
}

// ================= gather + normalize -> fp16 (stride 64 in g_A) =================
__global__ void gather_kernel(const float* __restrict__ obs, const float* __restrict__ act,
                              const float* __restrict__ mu, const float* __restrict__ sd,
                              int n, int P) {
    int i = blockIdx.x * blockDim.x + threadIdx.x;
    if (i >= P) return;
    uint32_t q = g_rank2[g_rank1[i]];
    g_src[q] = (uint32_t)i;
    uint32_t* oh = reinterpret_cast<uint32_t*>(g_A + (size_t)q * 64);
    if (i < n) {
        #pragma unroll
        for (int c = 0; c < CIN; c += 2) {
            float x0 = (c < OBS) ? obs[(size_t)i * OBS + c] : act[(size_t)i * ACTD + (c - OBS)];
            float x1 = (c + 1 < OBS) ? obs[(size_t)i * OBS + c + 1]
                                     : act[(size_t)i * ACTD + (c + 1 - OBS)];
            float v0 = (x0 - mu[c]) / sd[c];
            float v1 = (x1 - mu[c + 1]) / sd[c + 1];
            oh[c >> 1] = pack_h2(v0, v1);
        }
        #pragma unroll
        for (int c = CIN; c < 64; c += 2) oh[c >> 1] = 0u;
    } else {
        #pragma unroll
        for (int c = 0; c < 64; c += 2) oh[c >> 1] = 0u;
    }
}

// ====== ALL weight transposes/conversions in ONE kernel ======
__global__ void prep_w_all(const float* __restrict__ W1, const float* __restrict__ W2,
                           const float* __restrict__ W3, const float* __restrict__ W4,
                           int Mm, int t1, int t2, int t4) {
    int t = blockIdx.x * blockDim.x + threadIdx.x;
    const float* W;
    __half* Wd;
    int K, N, Nrows, Kpad, loc;
    if (t < t1)                { W = W1; Wd = g_W1; K = CIN; N = HID; Nrows = 256; Kpad = 64;  loc = t; }
    else if (t < t1 + t2)      { W = W2; Wd = g_W2; K = HID; N = HID; Nrows = 256; Kpad = OST; loc = t - t1; }
    else if (t < t1 + 2 * t2)  { W = W3; Wd = g_W3; K = HID; N = HID; Nrows = 256; Kpad = OST; loc = t - t1 - t2; }
    else if (t < t1 + 2 * t2 + t4) { W = W4; Wd = g_W4; K = HID; N = 2 * DOUTD; Nrows = 80; Kpad = OST; loc = t - t1 - 2 * t2; }
    else return;
    int kp = loc % Kpad;
    int rest = loc / Kpad;
    int nn = rest % Nrows;
    int mm = rest / Nrows;
    float v = 0.0f;
    if (nn < N && kp < K) v = W[((size_t)mm * K + kp) * N + nn];
    Wd[loc] = __float2half_rn(v);
}

// ======== persistent-A hidden-layer GEMM (unchanged from R12) ========
template <int KSEG>
__global__ void __launch_bounds__(256, 2) gemm_full(
    int layer, const float* __restrict__ bias, const int* __restrict__ elites,
    int r, int K, int N)
{
    constexpr int SA   = KSEG * 8;
    constexpr int AROW = KSEG * 16 + 16;
    constexpr int ASM  = 128 * AROW;
    constexpr int WSM  = 64 * AROW;

    const __half* Ain;
    const __half* Wt;
    __half* Cout;
    if (layer == 0)      { Ain = g_A; Wt = g_W1; Cout = g_B; }
    else if (layer == 1) { Ain = g_B; Wt = g_W2; Cout = g_A; }
    else                 { Ain = g_A; Wt = g_W3; Cout = g_B; }

    extern __shared__ __align__(16) char sm[];
    uint32_t sb = smem_u32(sm);
    int tid = threadIdx.x, lane = tid & 31, wid = tid >> 5;
    int warp_m = wid >> 1, warp_n = wid & 1;
    int row0 = blockIdx.x * 128;
    int m = blockIdx.y;
    int ev = elites[m];
    size_t qbase = (size_t)m * r;
    size_t wbase = (size_t)ev * 256 * SA;
    const float* biasm = bias + (size_t)ev * N;

    int steps = (K + 15) >> 4;

    #pragma unroll
    for (int it = 0; it < (128 * KSEG + 255) / 256; it++) {
        int idx = tid + it * 256;
        if (idx < 128 * KSEG) {
            int rr = idx / KSEG, u = idx % KSEG;
            int grow = row0 + rr;
            uint32_t pb = (grow < r) ? 16u : 0u;
            size_t gix = (qbase + (grow < r ? grow : 0)) * (size_t)SA + (size_t)(u * 8);
            CPA16(sb + (uint32_t)(rr * AROW + u * 16), Ain + gix, pb);
        }
    }
    CPA_COMMIT();

#define LOAD_W(t_, buf_) do { \
    uint32_t wb = sb + (uint32_t)ASM + (uint32_t)(buf_) * (uint32_t)WSM; \
    _Pragma("unroll") \
    for (int it = 0; it < (64 * KSEG + 255) / 256; it++) { \
        int idx = tid + it * 256; \
        if (idx < 64 * KSEG) { \
            int nr = idx / KSEG, u = idx % KSEG; \
            size_t gix = wbase + (size_t)((t_) * 64 + nr) * (size_t)SA + (size_t)(u * 8); \
            CPA16(wb + (uint32_t)(nr * AROW + u * 16), Wt + gix, 16u); \
        } \
    } \
    CPA_COMMIT(); \
} while (0)

    LOAD_W(0, 0);

    uint32_t a_addr = sb + (uint32_t)((warp_m * 32 + (lane & 15)) * AROW + (lane >> 4) * 16);

    for (int t = 0; t < 4; t++) {
        if (t + 1 < 4) { LOAD_W(t + 1, (t + 1) & 1); CPA_WAIT1(); }
        else CPA_WAIT0();
        __syncthreads();

        uint32_t wb = sb + (uint32_t)ASM + (uint32_t)(t & 1) * (uint32_t)WSM;
        uint32_t b_addr = wb +
            (uint32_t)((warp_n * 32 + (lane & 7) + ((lane >> 4) << 3)) * AROW +
                       ((lane >> 3) & 1) * 16);

        float acc[2][4][4];
        #pragma unroll
        for (int i = 0; i < 2; i++)
            #pragma unroll
            for (int j = 0; j < 4; j++)
                #pragma unroll
                for (int x = 0; x < 4; x++) acc[i][j][x] = 0.0f;

        for (int s = 0; s < steps; s++) {
            uint32_t ko = (uint32_t)(s * 32);
            uint32_t ah[2][4], bh[2][4];
            LDSM4A(ah[0], a_addr + ko);
            LDSM4A(ah[1], a_addr + 16u * AROW + ko);
            LDSM4A(bh[0], b_addr + ko);
            LDSM4A(bh[1], b_addr + 16u * AROW + ko);
            #pragma unroll
            for (int mi = 0; mi < 2; mi++)
                #pragma unroll
                for (int nn = 0; nn < 4; nn++)
                    MMA4(acc[mi][nn], ah[mi], bh[nn >> 1][(nn & 1) * 2],
                         bh[nn >> 1][(nn & 1) * 2 + 1]);
        }

        #pragma unroll
        for (int mi = 0; mi < 2; mi++) {
            int rlo = row0 + warp_m * 32 + mi * 16 + (lane >> 2);
            #pragma unroll
            for (int nn = 0; nn < 4; nn++) {
                int col = t * 64 + warp_n * 32 + nn * 8 + (lane & 3) * 2;
                if (col < OST) {
                    if (rlo < r) {
                        float v0 = 0.0f, v1 = 0.0f;
                        if (col < N) {
                            float d0 = acc[mi][nn][0] + biasm[col];
                            float d1 = acc[mi][nn][1] + biasm[col + 1];
                            v0 = d0 / (1.0f + expf(-d0));
                            v1 = d1 / (1.0f + expf(-d1));
                        }
                        reinterpret_cast<uint32_t*>(Cout)[((qbase + rlo) * OST + col) >> 1] =
                            pack_h2(v0, v1);
                    }
                    if (rlo + 8 < r) {
                        float v0 = 0.0f, v1 = 0.0f;
                        if (col < N) {
                            float d0 = acc[mi][nn][2] + biasm[col];
                            float d1 = acc[mi][nn][3] + biasm[col + 1];
                            v0 = d0 / (1.0f + expf(-d0));
                            v1 = d1 / (1.0f + expf(-d1));
                        }
                        reinterpret_cast<uint32_t*>(Cout)[((qbase + rlo + 8) * OST + col) >> 1] =
                            pack_h2(v0, v1);
                    }
                }
            }
        }
        __syncthreads();
    }
#undef LOAD_W
}

// ======== layer-4 GEMM (N=66 padded 80) fused with sampling epilogue ========
__global__ void __launch_bounds__(256, 1) gemm_l4(
    const float* __restrict__ b4, const int* __restrict__ elites,
    int r, int K,
    const float* __restrict__ obs, float* __restrict__ out, int n)
{
    const __half* Ain = g_B;
    const __half* Wt  = g_W4;

    __shared__ __align__(16) char sm[20736];
    uint32_t sb = smem_u32(sm);
    int tid = threadIdx.x, lane = tid & 31, wid = tid >> 5;
    int warp_m = wid >> 1, warp_n = wid & 1;
    int row0 = blockIdx.x * 64;
    int m = blockIdx.y;
    int ev = elites[m];
    size_t qbase = (size_t)m * r;
    size_t wbase = (size_t)ev * 80 * OST;

    float d00 = 0.f, d01 = 0.f, d02 = 0.f, d03 = 0.f;
    float d10 = 0.f, d11 = 0.f, d12 = 0.f, d13 = 0.f;
    float d20 = 0.f, d21 = 0.f, d22 = 0.f, d23 = 0.f;
    float d30 = 0.f, d31 = 0.f, d32 = 0.f, d33 = 0.f;
    float d40 = 0.f, d41 = 0.f, d42 = 0.f, d43 = 0.f;

    uint32_t a_addr = sb + (uint32_t)((warp_m * 16 + (lane & 15)) * 144 + (lane >> 4) * 16);
    uint32_t b_addr = sb + 9216u +
        (uint32_t)((warp_n * 40 + (lane & 7) + ((lane >> 4) << 3)) * 144 + ((lane >> 3) & 1) * 16);
    uint32_t b2_addr = sb + 9216u +
        (uint32_t)((warp_n * 40 + 32 + (lane & 7)) * 144 + ((lane >> 3) & 1) * 16);

    int chunks = (K + 63) >> 6;
    for (int c = 0; c < chunks; c++) {
        int ccol = c * 64;
        #pragma unroll
        for (int i = 0; i < 2; i++) {
            int idx = tid + i * 256;
            int rr = idx >> 3, u = idx & 7;
            int grow = row0 + rr;
            int kc = ccol + u * 8;
            uint4 vh = make_uint4(0, 0, 0, 0);
            if (grow < r && kc < OST)
                vh = *reinterpret_cast<const uint4*>(Ain + (qbase + grow) * OST + kc);
            *reinterpret_cast<uint4*>(sm + rr * 144 + u * 16) = vh;
        }
        #pragma unroll
        for (int i = 0; i < 3; i++) {
            int idx = tid + i * 256;
            if (idx < 640) {
                int nr = idx >> 3, u = idx & 7;
                int kc = ccol + u * 8;
                uint4 wv = make_uint4(0, 0, 0, 0);
                if (kc < OST)
                    wv = *reinterpret_cast<const uint4*>(Wt + wbase + (size_t)nr * OST + kc);
                *reinterpret_cast<uint4*>(sm + 9216 + nr * 144 + u * 16) = wv;
            }
        }
        __syncthreads();

        int steps = (K - ccol + 15) >> 4;
        if (steps > 4) steps = 4;
        for (int s = 0; s < steps; s++) {
            uint32_t ko = (uint32_t)(s * 32);
            uint32_t ah0, ah1, ah2, ah3;
            uint32_t bh0, bh1, bh2, bh3, bh4, bh5, bh6, bh7;
            uint32_t p0, p1;
            LDSM4(ah0, ah1, ah2, ah3, a_addr + ko);
            LDSM4(bh0, bh1, bh2, bh3, b_addr + ko);
            LDSM4(bh4, bh5, bh6, bh7, b_addr + 16u * 144 + ko);
            LDSM2(p0, p1, b2_addr + ko);
            MMAQ(d0, ah0, ah1, ah2, ah3, bh0, bh1);
            MMAQ(d1, ah0, ah1, ah2, ah3, bh2, bh3);
            MMAQ(d2, ah0, ah1, ah2, ah3, bh4, bh5);
            MMAQ(d3, ah0, ah1, ah2, ah3, bh6, bh7);
            MMAQ(d4, ah0, ah1, ah2, ah3, p0, p1);
        }
        __syncthreads();
    }

    float* stg = reinterpret_cast<float*>(sm);
    {
        int rlo = warp_m * 16 + (lane >> 2);
        int colb = warp_n * 40 + (lane & 3) * 2;
#define STG4(cp, toff) do { \
        int col = colb + (toff); \
        stg[rlo * 80 + col]           = cp##0; \
        stg[rlo * 80 + col + 1]       = cp##1; \
        stg[(rlo + 8) * 80 + col]     = cp##2; \
        stg[(rlo + 8) * 80 + col + 1] = cp##3; \
} while (0)
        STG4(d0, 0);
        STG4(d1, 8);
        STG4(d2, 16);
        STG4(d3, 24);
        STG4(d4, 32);
#undef STG4
    }
    __syncthreads();

    if (tid < 64) {
        int j = row0 + tid;
        if (j < r) {
            size_t q = qbase + j;
            int i = (int)g_src[q];
            if (i < n) {
                const float* bm = b4 + (size_t)ev * 66;
                const float* row = stg + tid * 80;
                uint32_t fbase = ((uint32_t)ev * (uint32_t)r + (uint32_t)j) * 33u;
                float sumsq = 0.0f;
                for (int d = 0; d < 33; d++) {
                    float mean = row[d] + bm[d];
                    float lv = row[33 + d] + bm[33 + d];
                    lv = 0.5f - softplusf(0.5f - lv);
                    lv = -10.0f + softplusf(lv + 10.0f);
                    float sd = expf(0.5f * lv);
                    float nz = normal_from_bits(rbits32(0u, 0u, fbase + (uint32_t)d));
                    float s = fmaf(nz, sd, mean);
                    if (d < 32) {
                        float no = s + obs[(size_t)i * OBS + d];
                        out[(size_t)i * OBS + d] = no;
                        sumsq += no * no;
                    } else {
                        out[(size_t)n * OBS + i] = s;
                    }
                }
                out[(size_t)n * (OBS + 1) + i] = (sqrtf(sumsq) > 50.0f) ? 1.0f : 0.0f;
            }
        }
    }
}

// ================= launch =================
extern "C" void kernel_launch(void* const* d_in, const int* in_sizes, int n_in,
                              void* d_out, int out_size) {
    const float* obs = (const float*)d_in[0];
    const float* act = (const float*)d_in[1];
    const float* mu  = (const float*)d_in[2];
    const float* sdv = (const float*)d_in[3];
    const float* W1  = (const float*)d_in[4];
    const float* b1  = (const float*)d_in[5];
    const float* W2  = (const float*)d_in[6];
    const float* b2  = (const float*)d_in[7];
    const float* W3  = (const float*)d_in[8];
    const float* b3  = (const float*)d_in[9];
    const float* W4  = (const float*)d_in[10];
    const float* b4  = (const float*)d_in[11];
    const int* elites = (const int*)d_in[12];

    int n = in_sizes[0] / OBS;
    int e = in_sizes[12];
    int r = (n - 1) / e + 1;
    int P = e * r;
    if (P > PMAX) P = PMAX;
    int Mm = in_sizes[4] / (CIN * HID);
    if (Mm > MMAX) Mm = MMAX;

    uint32_t nk0, nk1, s1a, s1b, s2a, s2b;
    threefry2x32(0u, 0u, 0u, 0u, nk0, nk1);
    threefry2x32(0u, 0u, 0u, 1u, s1a, s1b);
    threefry2x32(nk0, nk1, 0u, 1u, s2a, s2b);

    const int TB = 256;
    int gb = (P + TB - 1) / TB;

    // merged weight prep
    int t1 = Mm * 256 * 64;
    int t2 = Mm * 256 * OST;
    int t4 = Mm * 80 * OST;
    int ttot = t1 + 2 * t2 + t4;
    prep_w_all<<<(ttot + 255) / 256, 256>>>(W1, W2, W3, W4, Mm, t1, t2, t4);

    // merged permutation (both rounds in one pass each stage)
    zero_hist_kernel<<<(2 * NB + 255) / 256, 256>>>();
    hist2_kernel<<<gb, TB>>>(s1a, s1b, s2a, s2b, P);
    scan2_kernel<<<1, 1024>>>();
    scatter2_kernel<<<gb, TB>>>(P);
    rank2_kernel<<<gb, TB>>>(P);

    gather_kernel<<<gb, TB>>>(obs, act, mu, sdv, n, P);

    cudaFuncSetAttribute(gemm_full<8>,  cudaFuncAttributeMaxDynamicSharedMemorySize, 36864);
    cudaFuncSetAttribute(gemm_full<26>, cudaFuncAttributeMaxDynamicSharedMemorySize, 110592);

    int mt = (r + 127) / 128;
    dim3 gridH(mt, e);
    gemm_full<8><<<gridH, 256, 36864>>>(0, b1, elites, r, CIN, HID);
    gemm_full<26><<<gridH, 256, 110592>>>(1, b2, elites, r, HID, HID);
    gemm_full<26><<<gridH, 256, 110592>>>(2, b3, elites, r, HID, HID);

    int mt4 = (r + 63) / 64;
    dim3 gridL4(mt4, e);
    gemm_l4<<<gridL4, 256>>>(b4, elites, r, HID, obs, (float*)d_out, n);
}

// round 15
// speedup vs baseline: 4.6903x; 1.0555x over previous
#include <cuda_runtime.h>
#include <cuda_fp16.h>
#include <stdint.h>

#define OBS   32
#define ACTD  8
#define CIN   40
#define HID   200
#define DOUTD 33
#define PMAX  100352
#define MMAX  8
#define OST   208   // activation row stride (fp16 elements) for hidden layers
#define NB    4096  // rank buckets (top 12 bits)

// ================= scratch (device globals; referenced ONLY from device code) =========
__device__ uint32_t g_bits[PMAX];
__device__ uint32_t g_bits2[PMAX];
__device__ unsigned long long g_slot[PMAX];
__device__ unsigned long long g_slot2[PMAX];
__device__ uint32_t g_hist[2 * NB];
__device__ uint32_t g_bstart[2 * (NB + 1)];
__device__ uint32_t g_cursor[2 * NB];
__device__ uint32_t g_rank1[PMAX];
__device__ uint32_t g_rank2[PMAX];
__device__ uint32_t g_src[PMAX];
// activations: L1 input at stride 64 in g_A; hidden activations stride OST=208.
__device__ __half g_A[(size_t)PMAX * OST];
__device__ __half g_B[(size_t)PMAX * OST];
// transposed fp16 weights: [m][n_pad][k_pad]
__device__ __half g_W1[MMAX * 256 * 64];
__device__ __half g_W2[MMAX * 256 * OST];
__device__ __half g_W3[MMAX * 256 * OST];
__device__ __half g_W4[MMAX * 80 * OST];

// ================= threefry (JAX partitionable) =================
__host__ __device__ __forceinline__ uint32_t rotl32(uint32_t v, int d) {
    return (v << d) | (v >> (32 - d));
}
__host__ __device__ __forceinline__ void threefry2x32(uint32_t k0, uint32_t k1,
                                                      uint32_t x0, uint32_t x1,
                                                      uint32_t& o0, uint32_t& o1) {
    uint32_t ks2 = k0 ^ k1 ^ 0x1BD11BDAu;
    x0 += k0; x1 += k1;
#define TFR(a) x0 += x1; x1 = rotl32(x1, a); x1 ^= x0;
    TFR(13) TFR(15) TFR(26) TFR(6)
    x0 += k1;  x1 += ks2 + 1u;
    TFR(17) TFR(29) TFR(16) TFR(24)
    x0 += ks2; x1 += k0 + 2u;
    TFR(13) TFR(15) TFR(26) TFR(6)
    x0 += k0;  x1 += k1 + 3u;
    TFR(17) TFR(29) TFR(16) TFR(24)
    x0 += k1;  x1 += ks2 + 4u;
    TFR(13) TFR(15) TFR(26) TFR(6)
    x0 += ks2; x1 += k0 + 5u;
#undef TFR
    o0 = x0; o1 = x1;
}
__device__ __forceinline__ uint32_t rbits32(uint32_t k0, uint32_t k1, uint32_t idx) {
    uint32_t a, b;
    threefry2x32(k0, k1, 0u, idx, a, b);
    return a ^ b;
}
__device__ __forceinline__ float softplusf(float x) {
    return fmaxf(x, 0.0f) + log1pf(expf(-fabsf(x)));
}
__device__ __forceinline__ float normal_from_bits(uint32_t bits) {
    float f = __uint_as_float((bits >> 9) | 0x3F800000u) - 1.0f;
    const float lo = -0.99999994f;
    float val = fmaf(f, 2.0f, lo);
    val = fmaxf(lo, val);
    return 1.41421354f * erfinvf(val);
}

// ================= asm macros =================
__device__ __forceinline__ uint32_t smem_u32(const void* p) {
    uint32_t a;
    asm("{ .reg .u64 t; cvta.to.shared.u64 t, %1; cvt.u32.u64 %0, t; }" : "=r"(a) : "l"(p));
    return a;
}
#define LDSM4(r0, r1, r2, r3, addr) \
    asm volatile("ldmatrix.sync.aligned.m8n8.x4.shared.b16 {%0,%1,%2,%3}, [%4];" \
                 : "=r"(r0), "=r"(r1), "=r"(r2), "=r"(r3) : "r"(addr))
#define LDSM4A(rr, addr) LDSM4((rr)[0], (rr)[1], (rr)[2], (rr)[3], addr)
#define LDSM2(r0, r1, addr) \
    asm volatile("ldmatrix.sync.aligned.m8n8.x2.shared.b16 {%0,%1}, [%2];" \
                 : "=r"(r0), "=r"(r1) : "r"(addr))
#define MMAQ(cp, a0, a1, a2, a3, b0, b1) \
    asm volatile("mma.sync.aligned.m16n8k16.row.col.f32.f16.f16.f32 " \
                 "{%0,%1,%2,%3}, {%4,%5,%6,%7}, {%8,%9}, {%0,%1,%2,%3};" \
                 : "+f"(cp##0), "+f"(cp##1), "+f"(cp##2), "+f"(cp##3) \
                 : "r"(a0), "r"(a1), "r"(a2), "r"(a3), "r"(b0), "r"(b1))
#define MMA4(c, a, b0, b1) \
    asm volatile("mma.sync.aligned.m16n8k16.row.col.f32.f16.f16.f32 " \
                 "{%0,%1,%2,%3}, {%4,%5,%6,%7}, {%8,%9}, {%0,%1,%2,%3};" \
                 : "+f"((c)[0]), "+f"((c)[1]), "+f"((c)[2]), "+f"((c)[3]) \
                 : "r"((a)[0]), "r"((a)[1]), "r"((a)[2]), "r"((a)[3]), "r"(b0), "r"(b1))
#define CPA16(dst, src, pb) \
    asm volatile("cp.async.cg.shared.global [%0], [%1], 16, %2;" \
                 :: "r"(dst), "l"(src), "r"(pb) : "memory")
#define CPA_COMMIT() asm volatile("cp.async.commit_group;" ::: "memory")
#define CPA_WAIT0() asm volatile("cp.async.wait_group 0;" ::: "memory")
#define CPA_WAIT1() asm volatile("cp.async.wait_group 1;" ::: "memory")

__device__ __forceinline__ uint32_t pack_h2(float v0, float v1) {
    __half h0 = __float2half_rn(v0), h1 = __float2half_rn(v1);
    return (uint32_t)__half_as_ushort(h0) | ((uint32_t)__half_as_ushort(h1) << 16);
}

// ================= merged permutation machinery =================
__global__ void zero_hist_kernel() {
    int t = blockIdx.x * blockDim.x + threadIdx.x;
    if (t < 2 * NB) g_hist[t] = 0u;
}
__global__ void hist2_kernel(uint32_t k1a, uint32_t k1b, uint32_t k2a, uint32_t k2b, int P) {
    int p = blockIdx.x * blockDim.x + threadIdx.x;
    if (p >= P) return;
    uint32_t b1 = rbits32(k1a, k1b, (uint32_t)p);
    uint32_t b2 = rbits32(k2a, k2b, (uint32_t)p);
    g_bits[p] = b1;
    g_bits2[p] = b2;
    atomicAdd(&g_hist[b1 >> 20], 1u);
    atomicAdd(&g_hist[NB + (b2 >> 20)], 1u);
}
__global__ void scan2_kernel() {
    __shared__ uint32_t part[1024];
    int t = threadIdx.x;
    int half = t >> 9;
    int lt = t & 511;
    uint32_t hbase = (uint32_t)half * NB;
    uint32_t s = 0;
    #pragma unroll
    for (int i = 0; i < 8; i++) s += g_hist[hbase + lt * 8 + i];
    part[t] = s;
    __syncthreads();
    for (int off = 1; off < 512; off <<= 1) {
        uint32_t v = part[t];
        uint32_t add = (lt >= off) ? part[t - off] : 0u;
        __syncthreads();
        part[t] = v + add;
        __syncthreads();
    }
    uint32_t run = (lt == 0) ? 0u : part[t - 1];
    uint32_t bb = (uint32_t)half * (NB + 1);
    for (int i = 0; i < 8; i++) {
        int idx = lt * 8 + i;
        g_bstart[bb + idx] = run;
        g_cursor[hbase + idx] = run;
        run += g_hist[hbase + idx];
    }
    if (lt == 511) g_bstart[bb + NB] = run;
}
__global__ void scatter2_kernel(int P) {
    int p = blockIdx.x * blockDim.x + threadIdx.x;
    if (p >= P) return;
    uint32_t b1 = g_bits[p];
    uint32_t s1 = atomicAdd(&g_cursor[b1 >> 20], 1u);
    g_slot[s1] = (((unsigned long long)(b1 & 0xFFFFFu)) << 17) | (unsigned long long)p;
    uint32_t b2 = g_bits2[p];
    uint32_t s2 = atomicAdd(&g_cursor[NB + (b2 >> 20)], 1u);
    g_slot2[s2] = (((unsigned long long)(b2 & 0xFFFFFu)) << 17) | (unsigned long long)p;
}
__global__ void rank2_kernel(int P) {
    int p = blockIdx.x * blockDim.x + threadIdx.x;
    if (p >= P) return;
    {
        uint32_t b = g_bits[p];
        uint32_t hi = b >> 20;
        uint32_t s0 = g_bstart[hi], s1 = g_bstart[hi + 1];
        unsigned long long my = (((unsigned long long)(b & 0xFFFFFu)) << 17) | (unsigned long long)p;
        uint32_t c = 0;
        for (uint32_t s = s0; s < s1; s++) c += (g_slot[s] < my) ? 1u : 0u;
        g_rank1[p] = s0 + c;
    }
    {
        uint32_t b = g_bits2[p];
        uint32_t hi = b >> 20;
        uint32_t s0 = g_bstart[(NB + 1) + hi], s1 = g_bstart[(NB + 1) + hi + 1];
        unsigned long long my = (((unsigned long long)(b & 0xFFFFFu)) << 17) | (unsigned long long)p;
        uint32_t c = 0;
        for (uint32_t s = s0; s < s1; s++) c += (g_slot2[s] < my) ? 1u : 0u;
        g_rank2[p] = s0 + c;
    }
}

// ================= gather + normalize -> fp16 (stride 64 in g_A) =================
__global__ void gather_kernel(const float* __restrict__ obs, const float* __restrict__ act,
                              const float* __restrict__ mu, const float* __restrict__ sd,
                              int n, int P) {
    int i = blockIdx.x * blockDim.x + threadIdx.x;
    if (i >= P) return;
    uint32_t q = g_rank2[g_rank1[i]];
    g_src[q] = (uint32_t)i;
    uint32_t* oh = reinterpret_cast<uint32_t*>(g_A + (size_t)q * 64);
    if (i < n) {
        #pragma unroll
        for (int c = 0; c < CIN; c += 2) {
            float x0 = (c < OBS) ? obs[(size_t)i * OBS + c] : act[(size_t)i * ACTD + (c - OBS)];
            float x1 = (c + 1 < OBS) ? obs[(size_t)i * OBS + c + 1]
                                     : act[(size_t)i * ACTD + (c + 1 - OBS)];
            float v0 = (x0 - mu[c]) / sd[c];
            float v1 = (x1 - mu[c + 1]) / sd[c + 1];
            oh[c >> 1] = pack_h2(v0, v1);
        }
        #pragma unroll
        for (int c = CIN; c < 64; c += 2) oh[c >> 1] = 0u;
    } else {
        #pragma unroll
        for (int c = 0; c < 64; c += 2) oh[c >> 1] = 0u;
    }
}

// ====== ALL weight transposes/conversions in ONE kernel ======
__global__ void prep_w_all(const float* __restrict__ W1, const float* __restrict__ W2,
                           const float* __restrict__ W3, const float* __restrict__ W4,
                           int Mm, int t1, int t2, int t4) {
    int t = blockIdx.x * blockDim.x + threadIdx.x;
    const float* W;
    __half* Wd;
    int K, N, Nrows, Kpad, loc;
    if (t < t1)                { W = W1; Wd = g_W1; K = CIN; N = HID; Nrows = 256; Kpad = 64;  loc = t; }
    else if (t < t1 + t2)      { W = W2; Wd = g_W2; K = HID; N = HID; Nrows = 256; Kpad = OST; loc = t - t1; }
    else if (t < t1 + 2 * t2)  { W = W3; Wd = g_W3; K = HID; N = HID; Nrows = 256; Kpad = OST; loc = t - t1 - t2; }
    else if (t < t1 + 2 * t2 + t4) { W = W4; Wd = g_W4; K = HID; N = 2 * DOUTD; Nrows = 80; Kpad = OST; loc = t - t1 - 2 * t2; }
    else return;
    int kp = loc % Kpad;
    int rest = loc / Kpad;
    int nn = rest % Nrows;
    int mm = rest / Nrows;
    float v = 0.0f;
    if (nn < N && kp < K) v = W[((size_t)mm * K + kp) * N + nn];
    Wd[loc] = __float2half_rn(v);
}

// ======== persistent-A hidden-layer GEMM: 3 full 64-col tiles + 16-col tail ========
template <int KSEG>
__global__ void __launch_bounds__(256, 2) gemm_full(
    int layer, const float* __restrict__ bias, const int* __restrict__ elites,
    int r, int K, int N)
{
    constexpr int SA   = KSEG * 8;
    constexpr int AROW = KSEG * 16 + 16;
    constexpr int ASM  = 128 * AROW;
    constexpr int WSM  = 64 * AROW;

    const __half* Ain;
    const __half* Wt;
    __half* Cout;
    if (layer == 0)      { Ain = g_A; Wt = g_W1; Cout = g_B; }
    else if (layer == 1) { Ain = g_B; Wt = g_W2; Cout = g_A; }
    else                 { Ain = g_A; Wt = g_W3; Cout = g_B; }

    extern __shared__ __align__(16) char sm[];
    uint32_t sb = smem_u32(sm);
    int tid = threadIdx.x, lane = tid & 31, wid = tid >> 5;
    int warp_m = wid >> 1, warp_n = wid & 1;
    int row0 = blockIdx.x * 128;
    int m = blockIdx.y;
    int ev = elites[m];
    size_t qbase = (size_t)m * r;
    size_t wbase = (size_t)ev * 256 * SA;
    const float* biasm = bias + (size_t)ev * N;

    int steps = (K + 15) >> 4;

    // A load (once)
    #pragma unroll
    for (int it = 0; it < (128 * KSEG + 255) / 256; it++) {
        int idx = tid + it * 256;
        if (idx < 128 * KSEG) {
            int rr = idx / KSEG, u = idx % KSEG;
            int grow = row0 + rr;
            uint32_t pb = (grow < r) ? 16u : 0u;
            size_t gix = (qbase + (grow < r ? grow : 0)) * (size_t)SA + (size_t)(u * 8);
            CPA16(sb + (uint32_t)(rr * AROW + u * 16), Ain + gix, pb);
        }
    }
    CPA_COMMIT();

#define LOAD_W(t_, buf_, rows_) do { \
    uint32_t wb = sb + (uint32_t)ASM + (uint32_t)(buf_) * (uint32_t)WSM; \
    _Pragma("unroll") \
    for (int it = 0; it < (64 * KSEG + 255) / 256; it++) { \
        int idx = tid + it * 256; \
        if (idx < (rows_) * KSEG) { \
            int nr = idx / KSEG, u = idx % KSEG; \
            size_t gix = wbase + (size_t)((t_) * 64 + nr) * (size_t)SA + (size_t)(u * 8); \
            CPA16(wb + (uint32_t)(nr * AROW + u * 16), Wt + gix, 16u); \
        } \
    } \
    CPA_COMMIT(); \
} while (0)

    LOAD_W(0, 0, 64);

    uint32_t a_addr = sb + (uint32_t)((warp_m * 32 + (lane & 15)) * AROW + (lane >> 4) * 16);

    // ---- 3 full tiles (cols 0..191, all < N=200: unconditional stores) ----
    for (int t = 0; t < 3; t++) {
        if (t < 2) LOAD_W(t + 1, (t + 1) & 1, 64);
        else       LOAD_W(3, 1, 16);          // tail: W rows 192..207 into buf 1
        CPA_WAIT1();
        __syncthreads();

        uint32_t wb = sb + (uint32_t)ASM + (uint32_t)(t & 1) * (uint32_t)WSM;
        uint32_t b_addr = wb +
            (uint32_t)((warp_n * 32 + (lane & 7) + ((lane >> 4) << 3)) * AROW +
                       ((lane >> 3) & 1) * 16);

        float acc[2][4][4];
        #pragma unroll
        for (int i = 0; i < 2; i++)
            #pragma unroll
            for (int j = 0; j < 4; j++)
                #pragma unroll
                for (int x = 0; x < 4; x++) acc[i][j][x] = 0.0f;

        for (int s = 0; s < steps; s++) {
            uint32_t ko = (uint32_t)(s * 32);
            uint32_t ah[2][4], bh[2][4];
            LDSM4A(ah[0], a_addr + ko);
            LDSM4A(ah[1], a_addr + 16u * AROW + ko);
            LDSM4A(bh[0], b_addr + ko);
            LDSM4A(bh[1], b_addr + 16u * AROW + ko);
            #pragma unroll
            for (int mi = 0; mi < 2; mi++)
                #pragma unroll
                for (int nn = 0; nn < 4; nn++)
                    MMA4(acc[mi][nn], ah[mi], bh[nn >> 1][(nn & 1) * 2],
                         bh[nn >> 1][(nn & 1) * 2 + 1]);
        }

        #pragma unroll
        for (int mi = 0; mi < 2; mi++) {
            int rlo = row0 + warp_m * 32 + mi * 16 + (lane >> 2);
            #pragma unroll
            for (int nn = 0; nn < 4; nn++) {
                int col = t * 64 + warp_n * 32 + nn * 8 + (lane & 3) * 2;
                if (rlo < r) {
                    float d0 = acc[mi][nn][0] + biasm[col];
                    float d1 = acc[mi][nn][1] + biasm[col + 1];
                    reinterpret_cast<uint32_t*>(Cout)[((qbase + rlo) * OST + col) >> 1] =
                        pack_h2(d0 / (1.0f + expf(-d0)), d1 / (1.0f + expf(-d1)));
                }
                if (rlo + 8 < r) {
                    float d0 = acc[mi][nn][2] + biasm[col];
                    float d1 = acc[mi][nn][3] + biasm[col + 1];
                    reinterpret_cast<uint32_t*>(Cout)[((qbase + rlo + 8) * OST + col) >> 1] =
                        pack_h2(d0 / (1.0f + expf(-d0)), d1 / (1.0f + expf(-d1)));
                }
            }
        }
        __syncthreads();
    }

    // ---- tail tile: cols 192..207 (16 W rows in buf 1) ----
    {
        CPA_WAIT0();
        __syncthreads();
        uint32_t wb = sb + (uint32_t)ASM + (uint32_t)WSM;
        uint32_t b_addr = wb +
            (uint32_t)((warp_n * 8 + (lane & 7)) * AROW + ((lane >> 3) & 1) * 16);

        float acc[2][4];
        #pragma unroll
        for (int i = 0; i < 2; i++)
            #pragma unroll
            for (int x = 0; x < 4; x++) acc[i][x] = 0.0f;

        for (int s = 0; s < steps; s++) {
            uint32_t ko = (uint32_t)(s * 32);
            uint32_t ah[2][4], b0, b1;
            LDSM4A(ah[0], a_addr + ko);
            LDSM4A(ah[1], a_addr + 16u * AROW + ko);
            LDSM2(b0, b1, b_addr + ko);
            #pragma unroll
            for (int mi = 0; mi < 2; mi++)
                MMA4(acc[mi], ah[mi], b0, b1);
        }

        #pragma unroll
        for (int mi = 0; mi < 2; mi++) {
            int rlo = row0 + warp_m * 32 + mi * 16 + (lane >> 2);
            int col = 192 + warp_n * 8 + (lane & 3) * 2;
            if (rlo < r) {
                float v0 = 0.0f, v1 = 0.0f;
                if (col < N) {
                    float d0 = acc[mi][0] + biasm[col];
                    float d1 = acc[mi][1] + biasm[col + 1];
                    v0 = d0 / (1.0f + expf(-d0));
                    v1 = d1 / (1.0f + expf(-d1));
                }
                reinterpret_cast<uint32_t*>(Cout)[((qbase + rlo) * OST + col) >> 1] =
                    pack_h2(v0, v1);
            }
            if (rlo + 8 < r) {
                float v0 = 0.0f, v1 = 0.0f;
                if (col < N) {
                    float d0 = acc[mi][2] + biasm[col];
                    float d1 = acc[mi][3] + biasm[col + 1];
                    v0 = d0 / (1.0f + expf(-d0));
                    v1 = d1 / (1.0f + expf(-d1));
                }
                reinterpret_cast<uint32_t*>(Cout)[((qbase + rlo + 8) * OST + col) >> 1] =
                    pack_h2(v0, v1);
            }
        }
    }
#undef LOAD_W
}

// ======== layer-4 GEMM (N=66 padded 80) fused with sampling epilogue ========
__global__ void __launch_bounds__(256, 1) gemm_l4(
    const float* __restrict__ b4, const int* __restrict__ elites,
    int r, int K,
    const float* __restrict__ obs, float* __restrict__ out, int n)
{
    const __half* Ain = g_B;
    const __half* Wt  = g_W4;

    __shared__ __align__(16) char sm[20736];
    uint32_t sb = smem_u32(sm);
    int tid = threadIdx.x, lane = tid & 31, wid = tid >> 5;
    int warp_m = wid >> 1, warp_n = wid & 1;
    int row0 = blockIdx.x * 64;
    int m = blockIdx.y;
    int ev = elites[m];
    size_t qbase = (size_t)m * r;
    size_t wbase = (size_t)ev * 80 * OST;

    float d00 = 0.f, d01 = 0.f, d02 = 0.f, d03 = 0.f;
    float d10 = 0.f, d11 = 0.f, d12 = 0.f, d13 = 0.f;
    float d20 = 0.f, d21 = 0.f, d22 = 0.f, d23 = 0.f;
    float d30 = 0.f, d31 = 0.f, d32 = 0.f, d33 = 0.f;
    float d40 = 0.f, d41 = 0.f, d42 = 0.f, d43 = 0.f;

    uint32_t a_addr = sb + (uint32_t)((warp_m * 16 + (lane & 15)) * 144 + (lane >> 4) * 16);
    uint32_t b_addr = sb + 9216u +
        (uint32_t)((warp_n * 40 + (lane & 7) + ((lane >> 4) << 3)) * 144 + ((lane >> 3) & 1) * 16);
    uint32_t b2_addr = sb + 9216u +
        (uint32_t)((warp_n * 40 + 32 + (lane & 7)) * 144 + ((lane >> 3) & 1) * 16);

    int chunks = (K + 63) >> 6;
    for (int c = 0; c < chunks; c++) {
        int ccol = c * 64;
        #pragma unroll
        for (int i = 0; i < 2; i++) {
            int idx = tid + i * 256;
            int rr = idx >> 3, u = idx & 7;
            int grow = row0 + rr;
            int kc = ccol + u * 8;
            uint4 vh = make_uint4(0, 0, 0, 0);
            if (grow < r && kc < OST)
                vh = *reinterpret_cast<const uint4*>(Ain + (qbase + grow) * OST + kc);
            *reinterpret_cast<uint4*>(sm + rr * 144 + u * 16) = vh;
        }
        #pragma unroll
        for (int i = 0; i < 3; i++) {
            int idx = tid + i * 256;
            if (idx < 640) {
                int nr = idx >> 3, u = idx & 7;
                int kc = ccol + u * 8;
                uint4 wv = make_uint4(0, 0, 0, 0);
                if (kc < OST)
                    wv = *reinterpret_cast<const uint4*>(Wt + wbase + (size_t)nr * OST + kc);
                *reinterpret_cast<uint4*>(sm + 9216 + nr * 144 + u * 16) = wv;
            }
        }
        __syncthreads();

        int steps = (K - ccol + 15) >> 4;
        if (steps > 4) steps = 4;
        for (int s = 0; s < steps; s++) {
            uint32_t ko = (uint32_t)(s * 32);
            uint32_t ah0, ah1, ah2, ah3;
            uint32_t bh0, bh1, bh2, bh3, bh4, bh5, bh6, bh7;
            uint32_t p0, p1;
            LDSM4(ah0, ah1, ah2, ah3, a_addr + ko);
            LDSM4(bh0, bh1, bh2, bh3, b_addr + ko);
            LDSM4(bh4, bh5, bh6, bh7, b_addr + 16u * 144 + ko);
            LDSM2(p0, p1, b2_addr + ko);
            MMAQ(d0, ah0, ah1, ah2, ah3, bh0, bh1);
            MMAQ(d1, ah0, ah1, ah2, ah3, bh2, bh3);
            MMAQ(d2, ah0, ah1, ah2, ah3, bh4, bh5);
            MMAQ(d3, ah0, ah1, ah2, ah3, bh6, bh7);
            MMAQ(d4, ah0, ah1, ah2, ah3, p0, p1);
        }
        __syncthreads();
    }

    float* stg = reinterpret_cast<float*>(sm);
    {
        int rlo = warp_m * 16 + (lane >> 2);
        int colb = warp_n * 40 + (lane & 3) * 2;
#define STG4(cp, toff) do { \
        int col = colb + (toff); \
        stg[rlo * 80 + col]           = cp##0; \
        stg[rlo * 80 + col + 1]       = cp##1; \
        stg[(rlo + 8) * 80 + col]     = cp##2; \
        stg[(rlo + 8) * 80 + col + 1] = cp##3; \
} while (0)
        STG4(d0, 0);
        STG4(d1, 8);
        STG4(d2, 16);
        STG4(d3, 24);
        STG4(d4, 32);
#undef STG4
    }
    __syncthreads();

    if (tid < 64) {
        int j = row0 + tid;
        if (j < r) {
            size_t q = qbase + j;
            int i = (int)g_src[q];
            if (i < n) {
                const float* bm = b4 + (size_t)ev * 66;
                const float* row = stg + tid * 80;
                uint32_t fbase = ((uint32_t)ev * (uint32_t)r + (uint32_t)j) * 33u;
                float sumsq = 0.0f;
                for (int d = 0; d < 33; d++) {
                    float mean = row[d] + bm[d];
                    float lv = row[33 + d] + bm[33 + d];
                    lv = 0.5f - softplusf(0.5f - lv);
                    lv = -10.0f + softplusf(lv + 10.0f);
                    float sd = expf(0.5f * lv);
                    float nz = normal_from_bits(rbits32(0u, 0u, fbase + (uint32_t)d));
                    float s = fmaf(nz, sd, mean);
                    if (d < 32) {
                        float no = s + obs[(size_t)i * OBS + d];
                        out[(size_t)i * OBS + d] = no;
                        sumsq += no * no;
                    } else {
                        out[(size_t)n * OBS + i] = s;
                    }
                }
                out[(size_t)n * (OBS + 1) + i] = (sqrtf(sumsq) > 50.0f) ? 1.0f : 0.0f;
            }
        }
    }
}

// ================= launch =================
extern "C" void kernel_launch(void* const* d_in, const int* in_sizes, int n_in,
                              void* d_out, int out_size) {
    const float* obs = (const float*)d_in[0];
    const float* act = (const float*)d_in[1];
    const float* mu  = (const float*)d_in[2];
    const float* sdv = (const float*)d_in[3];
    const float* W1  = (const float*)d_in[4];
    const float* b1  = (const float*)d_in[5];
    const float* W2  = (const float*)d_in[6];
    const float* b2  = (const float*)d_in[7];
    const float* W3  = (const float*)d_in[8];
    const float* b3  = (const float*)d_in[9];
    const float* W4  = (const float*)d_in[10];
    const float* b4  = (const float*)d_in[11];
    const int* elites = (const int*)d_in[12];

    int n = in_sizes[0] / OBS;
    int e = in_sizes[12];
    int r = (n - 1) / e + 1;
    int P = e * r;
    if (P > PMAX) P = PMAX;
    int Mm = in_sizes[4] / (CIN * HID);
    if (Mm > MMAX) Mm = MMAX;

    uint32_t nk0, nk1, s1a, s1b, s2a, s2b;
    threefry2x32(0u, 0u, 0u, 0u, nk0, nk1);
    threefry2x32(0u, 0u, 0u, 1u, s1a, s1b);
    threefry2x32(nk0, nk1, 0u, 1u, s2a, s2b);

    const int TB = 256;
    int gb = (P + TB - 1) / TB;

    int t1 = Mm * 256 * 64;
    int t2 = Mm * 256 * OST;
    int t4 = Mm * 80 * OST;
    int ttot = t1 + 2 * t2 + t4;
    prep_w_all<<<(ttot + 255) / 256, 256>>>(W1, W2, W3, W4, Mm, t1, t2, t4);

    zero_hist_kernel<<<(2 * NB + 255) / 256, 256>>>();
    hist2_kernel<<<gb, TB>>>(s1a, s1b, s2a, s2b, P);
    scan2_kernel<<<1, 1024>>>();
    scatter2_kernel<<<gb, TB>>>(P);
    rank2_kernel<<<gb, TB>>>(P);

    gather_kernel<<<gb, TB>>>(obs, act, mu, sdv, n, P);

    cudaFuncSetAttribute(gemm_full<8>,  cudaFuncAttributeMaxDynamicSharedMemorySize, 36864);
    cudaFuncSetAttribute(gemm_full<26>, cudaFuncAttributeMaxDynamicSharedMemorySize, 110592);

    int mt = (r + 127) / 128;
    dim3 gridH(mt, e);
    gemm_full<8><<<gridH, 256, 36864>>>(0, b1, elites, r, CIN, HID);
    gemm_full<26><<<gridH, 256, 110592>>>(1, b2, elites, r, HID, HID);
    gemm_full<26><<<gridH, 256, 110592>>>(2, b3, elites, r, HID, HID);

    int mt4 = (r + 63) / 64;
    dim3 gridL4(mt4, e);
    gemm_l4<<<gridL4, 256>>>(b4, elites, r, HID, obs, (float*)d_out, n);
}

// round 16
// speedup vs baseline: 4.7282x; 1.0081x over previous
#include <cuda_runtime.h>
#include <cuda_fp16.h>
#include <stdint.h>

#define OBS   32
#define ACTD  8
#define CIN   40
#define HID   200
#define DOUTD 33
#define PMAX  100352
#define MMAX  8
#define OST   208   // activation row stride (fp16 elements) for hidden layers
#define NB    4096  // rank buckets (top 12 bits)

// ================= scratch (device globals; referenced ONLY from device code,
// except g_hist whose address is taken via cudaGetSymbolAddress for memset) =========
__device__ uint32_t g_bits[PMAX];
__device__ uint32_t g_bits2[PMAX];
__device__ unsigned long long g_slot[PMAX];
__device__ unsigned long long g_slot2[PMAX];
__device__ uint32_t g_hist[2 * NB];
__device__ uint32_t g_bstart[2 * (NB + 1)];
__device__ uint32_t g_cursor[2 * NB];
__device__ uint32_t g_rank1[PMAX];
__device__ uint32_t g_rank2[PMAX];
__device__ uint32_t g_src[PMAX];
// activations: L1 input at stride 64 in g_A; hidden activations stride OST=208.
__device__ __half g_A[(size_t)PMAX * OST];
__device__ __half g_B[(size_t)PMAX * OST];
// transposed fp16 weights: [m][n_pad][k_pad]
__device__ __half g_W1[MMAX * 256 * 64];
__device__ __half g_W2[MMAX * 256 * OST];
__device__ __half g_W3[MMAX * 256 * OST];
__device__ __half g_W4[MMAX * 80 * OST];

// ================= threefry (JAX partitionable) =================
__host__ __device__ __forceinline__ uint32_t rotl32(uint32_t v, int d) {
    return (v << d) | (v >> (32 - d));
}
__host__ __device__ __forceinline__ void threefry2x32(uint32_t k0, uint32_t k1,
                                                      uint32_t x0, uint32_t x1,
                                                      uint32_t& o0, uint32_t& o1) {
    uint32_t ks2 = k0 ^ k1 ^ 0x1BD11BDAu;
    x0 += k0; x1 += k1;
#define TFR(a) x0 += x1; x1 = rotl32(x1, a); x1 ^= x0;
    TFR(13) TFR(15) TFR(26) TFR(6)
    x0 += k1;  x1 += ks2 + 1u;
    TFR(17) TFR(29) TFR(16) TFR(24)
    x0 += ks2; x1 += k0 + 2u;
    TFR(13) TFR(15) TFR(26) TFR(6)
    x0 += k0;  x1 += k1 + 3u;
    TFR(17) TFR(29) TFR(16) TFR(24)
    x0 += k1;  x1 += ks2 + 4u;
    TFR(13) TFR(15) TFR(26) TFR(6)
    x0 += ks2; x1 += k0 + 5u;
#undef TFR
    o0 = x0; o1 = x1;
}
__device__ __forceinline__ uint32_t rbits32(uint32_t k0, uint32_t k1, uint32_t idx) {
    uint32_t a, b;
    threefry2x32(k0, k1, 0u, idx, a, b);
    return a ^ b;
}
__device__ __forceinline__ float softplusf(float x) {
    return fmaxf(x, 0.0f) + log1pf(expf(-fabsf(x)));
}
__device__ __forceinline__ float normal_from_bits(uint32_t bits) {
    float f = __uint_as_float((bits >> 9) | 0x3F800000u) - 1.0f;
    const float lo = -0.99999994f;
    float val = fmaf(f, 2.0f, lo);
    val = fmaxf(lo, val);
    return 1.41421354f * erfinvf(val);
}

// ================= asm macros =================
__device__ __forceinline__ uint32_t smem_u32(const void* p) {
    uint32_t a;
    asm("{ .reg .u64 t; cvta.to.shared.u64 t, %1; cvt.u32.u64 %0, t; }" : "=r"(a) : "l"(p));
    return a;
}
#define LDSM4(r0, r1, r2, r3, addr) \
    asm volatile("ldmatrix.sync.aligned.m8n8.x4.shared.b16 {%0,%1,%2,%3}, [%4];" \
                 : "=r"(r0), "=r"(r1), "=r"(r2), "=r"(r3) : "r"(addr))
#define LDSM4A(rr, addr) LDSM4((rr)[0], (rr)[1], (rr)[2], (rr)[3], addr)
#define LDSM2(r0, r1, addr) \
    asm volatile("ldmatrix.sync.aligned.m8n8.x2.shared.b16 {%0,%1}, [%2];" \
                 : "=r"(r0), "=r"(r1) : "r"(addr))
#define MMAQ(cp, a0, a1, a2, a3, b0, b1) \
    asm volatile("mma.sync.aligned.m16n8k16.row.col.f32.f16.f16.f32 " \
                 "{%0,%1,%2,%3}, {%4,%5,%6,%7}, {%8,%9}, {%0,%1,%2,%3};" \
                 : "+f"(cp##0), "+f"(cp##1), "+f"(cp##2), "+f"(cp##3) \
                 : "r"(a0), "r"(a1), "r"(a2), "r"(a3), "r"(b0), "r"(b1))
#define MMA4(c, a, b0, b1) \
    asm volatile("mma.sync.aligned.m16n8k16.row.col.f32.f16.f16.f32 " \
                 "{%0,%1,%2,%3}, {%4,%5,%6,%7}, {%8,%9}, {%0,%1,%2,%3};" \
                 : "+f"((c)[0]), "+f"((c)[1]), "+f"((c)[2]), "+f"((c)[3]) \
                 : "r"((a)[0]), "r"((a)[1]), "r"((a)[2]), "r"((a)[3]), "r"(b0), "r"(b1))
#define CPA16(dst, src, pb) \
    asm volatile("cp.async.cg.shared.global [%0], [%1], 16, %2;" \
                 :: "r"(dst), "l"(src), "r"(pb) : "memory")
#define CPA_COMMIT() asm volatile("cp.async.commit_group;" ::: "memory")
#define CPA_WAIT0() asm volatile("cp.async.wait_group 0;" ::: "memory")
#define CPA_WAIT1() asm volatile("cp.async.wait_group 1;" ::: "memory")

__device__ __forceinline__ uint32_t pack_h2(float v0, float v1) {
    __half h0 = __float2half_rn(v0), h1 = __float2half_rn(v1);
    return (uint32_t)__half_as_ushort(h0) | ((uint32_t)__half_as_ushort(h1) << 16);
}

// ====== merged prologue: weight transpose/convert + both-round bits/histograms ======
// (g_hist is zeroed by a cudaMemsetAsync before this kernel)
__global__ void prep_and_hist(const float* __restrict__ W1, const float* __restrict__ W2,
                              const float* __restrict__ W3, const float* __restrict__ W4,
                              int t1, int t2, int t4,
                              uint32_t k1a, uint32_t k1b, uint32_t k2a, uint32_t k2b, int P) {
    int t = blockIdx.x * blockDim.x + threadIdx.x;
    int ttot = t1 + 2 * t2 + t4;
    if (t < ttot) {
        const float* W;
        __half* Wd;
        int K, N, Nrows, Kpad, loc;
        if (t < t1)               { W = W1; Wd = g_W1; K = CIN; N = HID; Nrows = 256; Kpad = 64;  loc = t; }
        else if (t < t1 + t2)     { W = W2; Wd = g_W2; K = HID; N = HID; Nrows = 256; Kpad = OST; loc = t - t1; }
        else if (t < t1 + 2 * t2) { W = W3; Wd = g_W3; K = HID; N = HID; Nrows = 256; Kpad = OST; loc = t - t1 - t2; }
        else                      { W = W4; Wd = g_W4; K = HID; N = 2 * DOUTD; Nrows = 80; Kpad = OST; loc = t - t1 - 2 * t2; }
        int kp = loc % Kpad;
        int rest = loc / Kpad;
        int nn = rest % Nrows;
        int mm = rest / Nrows;
        float v = 0.0f;
        if (nn < N && kp < K) v = W[((size_t)mm * K + kp) * N + nn];
        Wd[loc] = __float2half_rn(v);
    } else {
        int p = t - ttot;
        if (p < P) {
            uint32_t b1 = rbits32(k1a, k1b, (uint32_t)p);
            uint32_t b2 = rbits32(k2a, k2b, (uint32_t)p);
            g_bits[p] = b1;
            g_bits2[p] = b2;
            atomicAdd(&g_hist[b1 >> 20], 1u);
            atomicAdd(&g_hist[NB + (b2 >> 20)], 1u);
        }
    }
}

__global__ void scan2_kernel() {
    __shared__ uint32_t part[1024];
    int t = threadIdx.x;
    int half = t >> 9;
    int lt = t & 511;
    uint32_t hbase = (uint32_t)half * NB;
    uint32_t s = 0;
    #pragma unroll
    for (int i = 0; i < 8; i++) s += g_hist[hbase + lt * 8 + i];
    part[t] = s;
    __syncthreads();
    for (int off = 1; off < 512; off <<= 1) {
        uint32_t v = part[t];
        uint32_t add = (lt >= off) ? part[t - off] : 0u;
        __syncthreads();
        part[t] = v + add;
        __syncthreads();
    }
    uint32_t run = (lt == 0) ? 0u : part[t - 1];
    uint32_t bb = (uint32_t)half * (NB + 1);
    for (int i = 0; i < 8; i++) {
        int idx = lt * 8 + i;
        g_bstart[bb + idx] = run;
        g_cursor[hbase + idx] = run;
        run += g_hist[hbase + idx];
    }
    if (lt == 511) g_bstart[bb + NB] = run;
}
__global__ void scatter2_kernel(int P) {
    int p = blockIdx.x * blockDim.x + threadIdx.x;
    if (p >= P) return;
    uint32_t b1 = g_bits[p];
    uint32_t s1 = atomicAdd(&g_cursor[b1 >> 20], 1u);
    g_slot[s1] = (((unsigned long long)(b1 & 0xFFFFFu)) << 17) | (unsigned long long)p;
    uint32_t b2 = g_bits2[p];
    uint32_t s2 = atomicAdd(&g_cursor[NB + (b2 >> 20)], 1u);
    g_slot2[s2] = (((unsigned long long)(b2 & 0xFFFFFu)) << 17) | (unsigned long long)p;
}
__global__ void rank2_kernel(int P) {
    int p = blockIdx.x * blockDim.x + threadIdx.x;
    if (p >= P) return;
    {
        uint32_t b = g_bits[p];
        uint32_t hi = b >> 20;
        uint32_t s0 = g_bstart[hi], s1 = g_bstart[hi + 1];
        unsigned long long my = (((unsigned long long)(b & 0xFFFFFu)) << 17) | (unsigned long long)p;
        uint32_t c = 0;
        for (uint32_t s = s0; s < s1; s++) c += (g_slot[s] < my) ? 1u : 0u;
        g_rank1[p] = s0 + c;
    }
    {
        uint32_t b = g_bits2[p];
        uint32_t hi = b >> 20;
        uint32_t s0 = g_bstart[(NB + 1) + hi], s1 = g_bstart[(NB + 1) + hi + 1];
        unsigned long long my = (((unsigned long long)(b & 0xFFFFFu)) << 17) | (unsigned long long)p;
        uint32_t c = 0;
        for (uint32_t s = s0; s < s1; s++) c += (g_slot2[s] < my) ? 1u : 0u;
        g_rank2[p] = s0 + c;
    }
}

// ================= gather + normalize -> fp16 (stride 64 in g_A) =================
__global__ void gather_kernel(const float* __restrict__ obs, const float* __restrict__ act,
                              const float* __restrict__ mu, const float* __restrict__ sd,
                              int n, int P) {
    int i = blockIdx.x * blockDim.x + threadIdx.x;
    if (i >= P) return;
    uint32_t q = g_rank2[g_rank1[i]];
    g_src[q] = (uint32_t)i;
    uint32_t* oh = reinterpret_cast<uint32_t*>(g_A + (size_t)q * 64);
    if (i < n) {
        #pragma unroll
        for (int c = 0; c < CIN; c += 2) {
            float x0 = (c < OBS) ? obs[(size_t)i * OBS + c] : act[(size_t)i * ACTD + (c - OBS)];
            float x1 = (c + 1 < OBS) ? obs[(size_t)i * OBS + c + 1]
                                     : act[(size_t)i * ACTD + (c + 1 - OBS)];
            float v0 = (x0 - mu[c]) / sd[c];
            float v1 = (x1 - mu[c + 1]) / sd[c + 1];
            oh[c >> 1] = pack_h2(v0, v1);
        }
        #pragma unroll
        for (int c = CIN; c < 64; c += 2) oh[c >> 1] = 0u;
    } else {
        #pragma unroll
        for (int c = 0; c < 64; c += 2) oh[c >> 1] = 0u;
    }
}

// ======== persistent-A hidden-layer GEMM: 3 full 64-col tiles + 16-col tail ========
template <int KSEG>
__global__ void __launch_bounds__(256, 2) gemm_full(
    int layer, const float* __restrict__ bias, const int* __restrict__ elites,
    int r, int K, int N)
{
    constexpr int SA   = KSEG * 8;
    constexpr int AROW = KSEG * 16 + 16;
    constexpr int ASM  = 128 * AROW;
    constexpr int WSM  = 64 * AROW;

    const __half* Ain;
    const __half* Wt;
    __half* Cout;
    if (layer == 0)      { Ain = g_A; Wt = g_W1; Cout = g_B; }
    else if (layer == 1) { Ain = g_B; Wt = g_W2; Cout = g_A; }
    else                 { Ain = g_A; Wt = g_W3; Cout = g_B; }

    extern __shared__ __align__(16) char sm[];
    uint32_t sb = smem_u32(sm);
    int tid = threadIdx.x, lane = tid & 31, wid = tid >> 5;
    int warp_m = wid >> 1, warp_n = wid & 1;
    int row0 = blockIdx.x * 128;
    int m = blockIdx.y;
    int ev = elites[m];
    size_t qbase = (size_t)m * r;
    size_t wbase = (size_t)ev * 256 * SA;
    const float* biasm = bias + (size_t)ev * N;

    int steps = (K + 15) >> 4;

    #pragma unroll
    for (int it = 0; it < (128 * KSEG + 255) / 256; it++) {
        int idx = tid + it * 256;
        if (idx < 128 * KSEG) {
            int rr = idx / KSEG, u = idx % KSEG;
            int grow = row0 + rr;
            uint32_t pb = (grow < r) ? 16u : 0u;
            size_t gix = (qbase + (grow < r ? grow : 0)) * (size_t)SA + (size_t)(u * 8);
            CPA16(sb + (uint32_t)(rr * AROW + u * 16), Ain + gix, pb);
        }
    }
    CPA_COMMIT();

#define LOAD_W(t_, buf_, rows_) do { \
    uint32_t wb = sb + (uint32_t)ASM + (uint32_t)(buf_) * (uint32_t)WSM; \
    _Pragma("unroll") \
    for (int it = 0; it < (64 * KSEG + 255) / 256; it++) { \
        int idx = tid + it * 256; \
        if (idx < (rows_) * KSEG) { \
            int nr = idx / KSEG, u = idx % KSEG; \
            size_t gix = wbase + (size_t)((t_) * 64 + nr) * (size_t)SA + (size_t)(u * 8); \
            CPA16(wb + (uint32_t)(nr * AROW + u * 16), Wt + gix, 16u); \
        } \
    } \
    CPA_COMMIT(); \
} while (0)

    LOAD_W(0, 0, 64);

    uint32_t a_addr = sb + (uint32_t)((warp_m * 32 + (lane & 15)) * AROW + (lane >> 4) * 16);

    for (int t = 0; t < 3; t++) {
        if (t < 2) LOAD_W(t + 1, (t + 1) & 1, 64);
        else       LOAD_W(3, 1, 16);
        CPA_WAIT1();
        __syncthreads();

        uint32_t wb = sb + (uint32_t)ASM + (uint32_t)(t & 1) * (uint32_t)WSM;
        uint32_t b_addr = wb +
            (uint32_t)((warp_n * 32 + (lane & 7) + ((lane >> 4) << 3)) * AROW +
                       ((lane >> 3) & 1) * 16);

        float acc[2][4][4];
        #pragma unroll
        for (int i = 0; i < 2; i++)
            #pragma unroll
            for (int j = 0; j < 4; j++)
                #pragma unroll
                for (int x = 0; x < 4; x++) acc[i][j][x] = 0.0f;

        for (int s = 0; s < steps; s++) {
            uint32_t ko = (uint32_t)(s * 32);
            uint32_t ah[2][4], bh[2][4];
            LDSM4A(ah[0], a_addr + ko);
            LDSM4A(ah[1], a_addr + 16u * AROW + ko);
            LDSM4A(bh[0], b_addr + ko);
            LDSM4A(bh[1], b_addr + 16u * AROW + ko);
            #pragma unroll
            for (int mi = 0; mi < 2; mi++)
                #pragma unroll
                for (int nn = 0; nn < 4; nn++)
                    MMA4(acc[mi][nn], ah[mi], bh[nn >> 1][(nn & 1) * 2],
                         bh[nn >> 1][(nn & 1) * 2 + 1]);
        }

        #pragma unroll
        for (int mi = 0; mi < 2; mi++) {
            int rlo = row0 + warp_m * 32 + mi * 16 + (lane >> 2);
            #pragma unroll
            for (int nn = 0; nn < 4; nn++) {
                int col = t * 64 + warp_n * 32 + nn * 8 + (lane & 3) * 2;
                if (rlo < r) {
                    float d0 = acc[mi][nn][0] + biasm[col];
                    float d1 = acc[mi][nn][1] + biasm[col + 1];
                    reinterpret_cast<uint32_t*>(Cout)[((qbase + rlo) * OST + col) >> 1] =
                        pack_h2(d0 / (1.0f + expf(-d0)), d1 / (1.0f + expf(-d1)));
                }
                if (rlo + 8 < r) {
                    float d0 = acc[mi][nn][2] + biasm[col];
                    float d1 = acc[mi][nn][3] + biasm[col + 1];
                    reinterpret_cast<uint32_t*>(Cout)[((qbase + rlo + 8) * OST + col) >> 1] =
                        pack_h2(d0 / (1.0f + expf(-d0)), d1 / (1.0f + expf(-d1)));
                }
            }
        }
        __syncthreads();
    }

    // tail tile: cols 192..207 (16 W rows in buf 1)
    {
        CPA_WAIT0();
        __syncthreads();
        uint32_t wb = sb + (uint32_t)ASM + (uint32_t)WSM;
        uint32_t b_addr = wb +
            (uint32_t)((warp_n * 8 + (lane & 7)) * AROW + ((lane >> 3) & 1) * 16);

        float acc[2][4];
        #pragma unroll
        for (int i = 0; i < 2; i++)
            #pragma unroll
            for (int x = 0; x < 4; x++) acc[i][x] = 0.0f;

        for (int s = 0; s < steps; s++) {
            uint32_t ko = (uint32_t)(s * 32);
            uint32_t ah[2][4], b0, b1;
            LDSM4A(ah[0], a_addr + ko);
            LDSM4A(ah[1], a_addr + 16u * AROW + ko);
            LDSM2(b0, b1, b_addr + ko);
            #pragma unroll
            for (int mi = 0; mi < 2; mi++)
                MMA4(acc[mi], ah[mi], b0, b1);
        }

        #pragma unroll
        for (int mi = 0; mi < 2; mi++) {
            int rlo = row0 + warp_m * 32 + mi * 16 + (lane >> 2);
            int col = 192 + warp_n * 8 + (lane & 3) * 2;
            if (rlo < r) {
                float v0 = 0.0f, v1 = 0.0f;
                if (col < N) {
                    float d0 = acc[mi][0] + biasm[col];
                    float d1 = acc[mi][1] + biasm[col + 1];
                    v0 = d0 / (1.0f + expf(-d0));
                    v1 = d1 / (1.0f + expf(-d1));
                }
                reinterpret_cast<uint32_t*>(Cout)[((qbase + rlo) * OST + col) >> 1] =
                    pack_h2(v0, v1);
            }
            if (rlo + 8 < r) {
                float v0 = 0.0f, v1 = 0.0f;
                if (col < N) {
                    float d0 = acc[mi][2] + biasm[col];
                    float d1 = acc[mi][3] + biasm[col + 1];
                    v0 = d0 / (1.0f + expf(-d0));
                    v1 = d1 / (1.0f + expf(-d1));
                }
                reinterpret_cast<uint32_t*>(Cout)[((qbase + rlo + 8) * OST + col) >> 1] =
                    pack_h2(v0, v1);
            }
        }
    }
#undef LOAD_W
}

// ======== layer-4 GEMM (N=66 padded 80) fused with sampling epilogue, 2 CTAs/SM ========
__global__ void __launch_bounds__(256, 2) gemm_l4(
    const float* __restrict__ b4, const int* __restrict__ elites,
    int r, int K,
    const float* __restrict__ obs, float* __restrict__ out, int n)
{
    const __half* Ain = g_B;
    const __half* Wt  = g_W4;

    __shared__ __align__(16) char sm[20736];
    uint32_t sb = smem_u32(sm);
    int tid = threadIdx.x, lane = tid & 31, wid = tid >> 5;
    int warp_m = wid >> 1, warp_n = wid & 1;
    int row0 = blockIdx.x * 64;
    int m = blockIdx.y;
    int ev = elites[m];
    size_t qbase = (size_t)m * r;
    size_t wbase = (size_t)ev * 80 * OST;

    float d00 = 0.f, d01 = 0.f, d02 = 0.f, d03 = 0.f;
    float d10 = 0.f, d11 = 0.f, d12 = 0.f, d13 = 0.f;
    float d20 = 0.f, d21 = 0.f, d22 = 0.f, d23 = 0.f;
    float d30 = 0.f, d31 = 0.f, d32 = 0.f, d33 = 0.f;
    float d40 = 0.f, d41 = 0.f, d42 = 0.f, d43 = 0.f;

    uint32_t a_addr = sb + (uint32_t)((warp_m * 16 + (lane & 15)) * 144 + (lane >> 4) * 16);
    uint32_t b_addr = sb + 9216u +
        (uint32_t)((warp_n * 40 + (lane & 7) + ((lane >> 4) << 3)) * 144 + ((lane >> 3) & 1) * 16);
    uint32_t b2_addr = sb + 9216u +
        (uint32_t)((warp_n * 40 + 32 + (lane & 7)) * 144 + ((lane >> 3) & 1) * 16);

    int chunks = (K + 63) >> 6;
    for (int c = 0; c < chunks; c++) {
        int ccol = c * 64;
        #pragma unroll
        for (int i = 0; i < 2; i++) {
            int idx = tid + i * 256;
            int rr = idx >> 3, u = idx & 7;
            int grow = row0 + rr;
            int kc = ccol + u * 8;
            uint4 vh = make_uint4(0, 0, 0, 0);
            if (grow < r && kc < OST)
                vh = *reinterpret_cast<const uint4*>(Ain + (qbase + grow) * OST + kc);
            *reinterpret_cast<uint4*>(sm + rr * 144 + u * 16) = vh;
        }
        #pragma unroll
        for (int i = 0; i < 3; i++) {
            int idx = tid + i * 256;
            if (idx < 640) {
                int nr = idx >> 3, u = idx & 7;
                int kc = ccol + u * 8;
                uint4 wv = make_uint4(0, 0, 0, 0);
                if (kc < OST)
                    wv = *reinterpret_cast<const uint4*>(Wt + wbase + (size_t)nr * OST + kc);
                *reinterpret_cast<uint4*>(sm + 9216 + nr * 144 + u * 16) = wv;
            }
        }
        __syncthreads();

        int steps = (K - ccol + 15) >> 4;
        if (steps > 4) steps = 4;
        for (int s = 0; s < steps; s++) {
            uint32_t ko = (uint32_t)(s * 32);
            uint32_t ah0, ah1, ah2, ah3;
            uint32_t bh0, bh1, bh2, bh3, bh4, bh5, bh6, bh7;
            uint32_t p0, p1;
            LDSM4(ah0, ah1, ah2, ah3, a_addr + ko);
            LDSM4(bh0, bh1, bh2, bh3, b_addr + ko);
            LDSM4(bh4, bh5, bh6, bh7, b_addr + 16u * 144 + ko);
            LDSM2(p0, p1, b2_addr + ko);
            MMAQ(d0, ah0, ah1, ah2, ah3, bh0, bh1);
            MMAQ(d1, ah0, ah1, ah2, ah3, bh2, bh3);
            MMAQ(d2, ah0, ah1, ah2, ah3, bh4, bh5);
            MMAQ(d3, ah0, ah1, ah2, ah3, bh6, bh7);
            MMAQ(d4, ah0, ah1, ah2, ah3, p0, p1);
        }
        __syncthreads();
    }

    float* stg = reinterpret_cast<float*>(sm);
    {
        int rlo = warp_m * 16 + (lane >> 2);
        int colb = warp_n * 40 + (lane & 3) * 2;
#define STG4(cp, toff) do { \
        int col = colb + (toff); \
        stg[rlo * 80 + col]           = cp##0; \
        stg[rlo * 80 + col + 1]       = cp##1; \
        stg[(rlo + 8) * 80 + col]     = cp##2; \
        stg[(rlo + 8) * 80 + col + 1] = cp##3; \
} while (0)
        STG4(d0, 0);
        STG4(d1, 8);
        STG4(d2, 16);
        STG4(d3, 24);
        STG4(d4, 32);
#undef STG4
    }
    __syncthreads();

    if (tid < 64) {
        int j = row0 + tid;
        if (j < r) {
            size_t q = qbase + j;
            int i = (int)g_src[q];
            if (i < n) {
                const float* bm = b4 + (size_t)ev * 66;
                const float* row = stg + tid * 80;
                uint32_t fbase = ((uint32_t)ev * (uint32_t)r + (uint32_t)j) * 33u;
                float sumsq = 0.0f;
                for (int d = 0; d < 33; d++) {
                    float mean = row[d] + bm[d];
                    float lv = row[33 + d] + bm[33 + d];
                    lv = 0.5f - softplusf(0.5f - lv);
                    lv = -10.0f + softplusf(lv + 10.0f);
                    float sd = expf(0.5f * lv);
                    float nz = normal_from_bits(rbits32(0u, 0u, fbase + (uint32_t)d));
                    float s = fmaf(nz, sd, mean);
                    if (d < 32) {
                        float no = s + obs[(size_t)i * OBS + d];
                        out[(size_t)i * OBS + d] = no;
                        sumsq += no * no;
                    } else {
                        out[(size_t)n * OBS + i] = s;
                    }
                }
                out[(size_t)n * (OBS + 1) + i] = (sqrtf(sumsq) > 50.0f) ? 1.0f : 0.0f;
            }
        }
    }
}

// ================= launch =================
extern "C" void kernel_launch(void* const* d_in, const int* in_sizes, int n_in,
                              void* d_out, int out_size) {
    const float* obs = (const float*)d_in[0];
    const float* act = (const float*)d_in[1];
    const float* mu  = (const float*)d_in[2];
    const float* sdv = (const float*)d_in[3];
    const float* W1  = (const float*)d_in[4];
    const float* b1  = (const float*)d_in[5];
    const float* W2  = (const float*)d_in[6];
    const float* b2  = (const float*)d_in[7];
    const float* W3  = (const float*)d_in[8];
    const float* b3  = (const float*)d_in[9];
    const float* W4  = (const float*)d_in[10];
    const float* b4  = (const float*)d_in[11];
    const int* elites = (const int*)d_in[12];

    int n = in_sizes[0] / OBS;
    int e = in_sizes[12];
    int r = (n - 1) / e + 1;
    int P = e * r;
    if (P > PMAX) P = PMAX;
    int Mm = in_sizes[4] / (CIN * HID);
    if (Mm > MMAX) Mm = MMAX;

    uint32_t nk0, nk1, s1a, s1b, s2a, s2b;
    threefry2x32(0u, 0u, 0u, 0u, nk0, nk1);
    threefry2x32(0u, 0u, 0u, 1u, s1a, s1b);
    threefry2x32(nk0, nk1, 0u, 1u, s2a, s2b);

    const int TB = 256;
    int gb = (P + TB - 1) / TB;

    // zero histograms via memset node (symbol address via proper API)
    void* histPtr = nullptr;
    cudaGetSymbolAddress(&histPtr, g_hist);
    cudaMemsetAsync(histPtr, 0, 2 * NB * sizeof(uint32_t));

    // merged prologue: weight prep + both-round bits/histograms
    int t1 = Mm * 256 * 64;
    int t2 = Mm * 256 * OST;
    int t4 = Mm * 80 * OST;
    int ttot = t1 + 2 * t2 + t4;
    int mtot = ttot + P;
    prep_and_hist<<<(mtot + 255) / 256, 256>>>(W1, W2, W3, W4, t1, t2, t4,
                                               s1a, s1b, s2a, s2b, P);

    scan2_kernel<<<1, 1024>>>();
    scatter2_kernel<<<gb, TB>>>(P);
    rank2_kernel<<<gb, TB>>>(P);

    gather_kernel<<<gb, TB>>>(obs, act, mu, sdv, n, P);

    cudaFuncSetAttribute(gemm_full<8>,  cudaFuncAttributeMaxDynamicSharedMemorySize, 36864);
    cudaFuncSetAttribute(gemm_full<26>, cudaFuncAttributeMaxDynamicSharedMemorySize, 110592);

    int mt = (r + 127) / 128;
    dim3 gridH(mt, e);
    gemm_full<8><<<gridH, 256, 36864>>>(0, b1, elites, r, CIN, HID);
    gemm_full<26><<<gridH, 256, 110592>>>(1, b2, elites, r, HID, HID);
    gemm_full<26><<<gridH, 256, 110592>>>(2, b3, elites, r, HID, HID);

    int mt4 = (r + 63) / 64;
    dim3 gridL4(mt4, e);
    gemm_l4<<<gridL4, 256>>>(b4, elites, r, HID, obs, (float*)d_out, n);
}

// round 17
// speedup vs baseline: 5.3032x; 1.1216x over previous
#include <cuda_runtime.h>
#include <cuda_fp16.h>
#include <stdint.h>

#define OBS   32
#define ACTD  8
#define CIN   40
#define HID   200
#define DOUTD 33
#define PMAX  100352
#define MMAX  8
#define OST   208   // activation row stride (fp16 elements) for hidden layers
#define NB    4096  // rank buckets (top 12 bits)

// ================= scratch (device globals; referenced ONLY from device code,
// except g_hist whose address is taken via cudaGetSymbolAddress for memset) =========
__device__ uint32_t g_bits[PMAX];
__device__ uint32_t g_bits2[PMAX];
__device__ unsigned long long g_slot[PMAX];
__device__ unsigned long long g_slot2[PMAX];
__device__ uint32_t g_hist[2 * NB];
__device__ uint32_t g_bstart[2 * (NB + 1)];
__device__ uint32_t g_cursor[2 * NB];
__device__ uint32_t g_rank1[PMAX];
__device__ uint32_t g_rank2[PMAX];
__device__ uint32_t g_src[PMAX];
// activations: L1 input at stride 64 in g_A; hidden activations stride OST=208.
__device__ __half g_A[(size_t)PMAX * OST];
__device__ __half g_B[(size_t)PMAX * OST];
// transposed fp16 weights: [m][n_pad][k_pad]
__device__ __half g_W1[MMAX * 256 * 64];
__device__ __half g_W2[MMAX * 256 * OST];
__device__ __half g_W3[MMAX * 256 * OST];
__device__ __half g_W4[MMAX * 80 * OST];

// ================= threefry (JAX partitionable) =================
__host__ __device__ __forceinline__ uint32_t rotl32(uint32_t v, int d) {
    return (v << d) | (v >> (32 - d));
}
__host__ __device__ __forceinline__ void threefry2x32(uint32_t k0, uint32_t k1,
                                                      uint32_t x0, uint32_t x1,
                                                      uint32_t& o0, uint32_t& o1) {
    uint32_t ks2 = k0 ^ k1 ^ 0x1BD11BDAu;
    x0 += k0; x1 += k1;
#define TFR(a) x0 += x1; x1 = rotl32(x1, a); x1 ^= x0;
    TFR(13) TFR(15) TFR(26) TFR(6)
    x0 += k1;  x1 += ks2 + 1u;
    TFR(17) TFR(29) TFR(16) TFR(24)
    x0 += ks2; x1 += k0 + 2u;
    TFR(13) TFR(15) TFR(26) TFR(6)
    x0 += k0;  x1 += k1 + 3u;
    TFR(17) TFR(29) TFR(16) TFR(24)
    x0 += k1;  x1 += ks2 + 4u;
    TFR(13) TFR(15) TFR(26) TFR(6)
    x0 += ks2; x1 += k0 + 5u;
#undef TFR
    o0 = x0; o1 = x1;
}
__device__ __forceinline__ uint32_t rbits32(uint32_t k0, uint32_t k1, uint32_t idx) {
    uint32_t a, b;
    threefry2x32(k0, k1, 0u, idx, a, b);
    return a ^ b;
}
__device__ __forceinline__ float softplusf(float x) {
    return fmaxf(x, 0.0f) + log1pf(expf(-fabsf(x)));
}
__device__ __forceinline__ float normal_from_bits(uint32_t bits) {
    float f = __uint_as_float((bits >> 9) | 0x3F800000u) - 1.0f;
    const float lo = -0.99999994f;
    float val = fmaf(f, 2.0f, lo);
    val = fmaxf(lo, val);
    return 1.41421354f * erfinvf(val);
}

// ================= asm macros =================
__device__ __forceinline__ uint32_t smem_u32(const void* p) {
    uint32_t a;
    asm("{ .reg .u64 t; cvta.to.shared.u64 t, %1; cvt.u32.u64 %0, t; }" : "=r"(a) : "l"(p));
    return a;
}
#define LDSM4(r0, r1, r2, r3, addr) \
    asm volatile("ldmatrix.sync.aligned.m8n8.x4.shared.b16 {%0,%1,%2,%3}, [%4];" \
                 : "=r"(r0), "=r"(r1), "=r"(r2), "=r"(r3) : "r"(addr))
#define LDSM4A(rr, addr) LDSM4((rr)[0], (rr)[1], (rr)[2], (rr)[3], addr)
#define LDSM2(r0, r1, addr) \
    asm volatile("ldmatrix.sync.aligned.m8n8.x2.shared.b16 {%0,%1}, [%2];" \
                 : "=r"(r0), "=r"(r1) : "r"(addr))
#define MMA4(c, a, b0, b1) \
    asm volatile("mma.sync.aligned.m16n8k16.row.col.f32.f16.f16.f32 " \
                 "{%0,%1,%2,%3}, {%4,%5,%6,%7}, {%8,%9}, {%0,%1,%2,%3};" \
                 : "+f"((c)[0]), "+f"((c)[1]), "+f"((c)[2]), "+f"((c)[3]) \
                 : "r"((a)[0]), "r"((a)[1]), "r"((a)[2]), "r"((a)[3]), "r"(b0), "r"(b1))
#define CPA16(dst, src, pb) \
    asm volatile("cp.async.cg.shared.global [%0], [%1], 16, %2;" \
                 :: "r"(dst), "l"(src), "r"(pb) : "memory")
#define CPA_COMMIT() asm volatile("cp.async.commit_group;" ::: "memory")
#define CPA_WAIT0() asm volatile("cp.async.wait_group 0;" ::: "memory")
#define CPA_WAIT1() asm volatile("cp.async.wait_group 1;" ::: "memory")

__device__ __forceinline__ uint32_t pack_h2(float v0, float v1) {
    __half h0 = __float2half_rn(v0), h1 = __float2half_rn(v1);
    return (uint32_t)__half_as_ushort(h0) | ((uint32_t)__half_as_ushort(h1) << 16);
}

// ====== merged prologue: weight transpose/convert + both-round bits/histograms ======
__global__ void prep_and_hist(const float* __restrict__ W1, const float* __restrict__ W2,
                              const float* __restrict__ W3, const float* __restrict__ W4,
                              int t1, int t2, int t4,
                              uint32_t k1a, uint32_t k1b, uint32_t k2a, uint32_t k2b, int P) {
    int t = blockIdx.x * blockDim.x + threadIdx.x;
    int ttot = t1 + 2 * t2 + t4;
    if (t < ttot) {
        const float* W;
        __half* Wd;
        int K, N, Nrows, Kpad, loc;
        if (t < t1)               { W = W1; Wd = g_W1; K = CIN; N = HID; Nrows = 256; Kpad = 64;  loc = t; }
        else if (t < t1 + t2)     { W = W2; Wd = g_W2; K = HID; N = HID; Nrows = 256; Kpad = OST; loc = t - t1; }
        else if (t < t1 + 2 * t2) { W = W3; Wd = g_W3; K = HID; N = HID; Nrows = 256; Kpad = OST; loc = t - t1 - t2; }
        else                      { W = W4; Wd = g_W4; K = HID; N = 2 * DOUTD; Nrows = 80; Kpad = OST; loc = t - t1 - 2 * t2; }
        int kp = loc % Kpad;
        int rest = loc / Kpad;
        int nn = rest % Nrows;
        int mm = rest / Nrows;
        float v = 0.0f;
        if (nn < N && kp < K) v = W[((size_t)mm * K + kp) * N + nn];
        Wd[loc] = __float2half_rn(v);
    } else {
        int p = t - ttot;
        if (p < P) {
            uint32_t b1 = rbits32(k1a, k1b, (uint32_t)p);
            uint32_t b2 = rbits32(k2a, k2b, (uint32_t)p);
            g_bits[p] = b1;
            g_bits2[p] = b2;
            atomicAdd(&g_hist[b1 >> 20], 1u);
            atomicAdd(&g_hist[NB + (b2 >> 20)], 1u);
        }
    }
}

// scan both 4096-bucket histograms; warp-shuffle scan, 2 barriers total
__global__ void scan2_kernel() {
    __shared__ uint32_t wsum[32];
    int t = threadIdx.x;
    int half = t >> 9;
    int lt = t & 511;
    uint32_t hbase = (uint32_t)half * NB;
    uint32_t v0, v1, v2, v3, v4, v5, v6, v7;
    v0 = g_hist[hbase + lt * 8 + 0]; v1 = g_hist[hbase + lt * 8 + 1];
    v2 = g_hist[hbase + lt * 8 + 2]; v3 = g_hist[hbase + lt * 8 + 3];
    v4 = g_hist[hbase + lt * 8 + 4]; v5 = g_hist[hbase + lt * 8 + 5];
    v6 = g_hist[hbase + lt * 8 + 6]; v7 = g_hist[hbase + lt * 8 + 7];
    uint32_t s = v0 + v1 + v2 + v3 + v4 + v5 + v6 + v7;
    int lane = t & 31, warp = t >> 5;
    // inclusive warp scan of s
    uint32_t x = s;
    #pragma unroll
    for (int off = 1; off < 32; off <<= 1) {
        uint32_t y = __shfl_up_sync(0xFFFFFFFFu, x, off);
        if (lane >= off) x += y;
    }
    if (lane == 31) wsum[warp] = x;
    __syncthreads();
    if (t < 32) {
        uint32_t w = wsum[t];
        uint32_t xx = w;
        // segmented scan: warps 0-15 = half 0, warps 16-31 = half 1
        #pragma unroll
        for (int off = 1; off < 16; off <<= 1) {
            uint32_t y = __shfl_up_sync(0xFFFFFFFFu, xx, off);
            if ((t & 15) >= off) xx += y;
        }
        wsum[t] = xx - w;   // exclusive offset of this warp within its half
    }
    __syncthreads();
    uint32_t run = wsum[warp] + (x - s);   // exclusive prefix for this thread
    uint32_t bb = (uint32_t)half * (NB + 1);
    int idx = lt * 8;
#define EMIT(vv) do { g_bstart[bb + idx] = run; g_cursor[hbase + idx] = run; run += (vv); idx++; } while (0)
    EMIT(v0); EMIT(v1); EMIT(v2); EMIT(v3); EMIT(v4); EMIT(v5); EMIT(v6); EMIT(v7);
#undef EMIT
    if (lt == 511) g_bstart[bb + NB] = run;
}
__global__ void scatter2_kernel(int P) {
    int p = blockIdx.x * blockDim.x + threadIdx.x;
    if (p >= P) return;
    uint32_t b1 = g_bits[p];
    uint32_t s1 = atomicAdd(&g_cursor[b1 >> 20], 1u);
    g_slot[s1] = (((unsigned long long)(b1 & 0xFFFFFu)) << 17) | (unsigned long long)p;
    uint32_t b2 = g_bits2[p];
    uint32_t s2 = atomicAdd(&g_cursor[NB + (b2 >> 20)], 1u);
    g_slot2[s2] = (((unsigned long long)(b2 & 0xFFFFFu)) << 17) | (unsigned long long)p;
}
__global__ void rank2_kernel(int P) {
    int p = blockIdx.x * blockDim.x + threadIdx.x;
    if (p >= P) return;
    {
        uint32_t b = g_bits[p];
        uint32_t hi = b >> 20;
        uint32_t s0 = g_bstart[hi], s1 = g_bstart[hi + 1];
        unsigned long long my = (((unsigned long long)(b & 0xFFFFFu)) << 17) | (unsigned long long)p;
        uint32_t c = 0;
        for (uint32_t s = s0; s < s1; s++) c += (g_slot[s] < my) ? 1u : 0u;
        g_rank1[p] = s0 + c;
    }
    {
        uint32_t b = g_bits2[p];
        uint32_t hi = b >> 20;
        uint32_t s0 = g_bstart[(NB + 1) + hi], s1 = g_bstart[(NB + 1) + hi + 1];
        unsigned long long my = (((unsigned long long)(b & 0xFFFFFu)) << 17) | (unsigned long long)p;
        uint32_t c = 0;
        for (uint32_t s = s0; s < s1; s++) c += (g_slot2[s] < my) ? 1u : 0u;
        g_rank2[p] = s0 + c;
    }
}

// ================= gather + normalize -> fp16 (stride 64 in g_A) =================
__global__ void gather_kernel(const float* __restrict__ obs, const float* __restrict__ act,
                              const float* __restrict__ mu, const float* __restrict__ sd,
                              int n, int P) {
    int i = blockIdx.x * blockDim.x + threadIdx.x;
    if (i >= P) return;
    uint32_t q = g_rank2[g_rank1[i]];
    g_src[q] = (uint32_t)i;
    uint32_t* oh = reinterpret_cast<uint32_t*>(g_A + (size_t)q * 64);
    if (i < n) {
        #pragma unroll
        for (int c = 0; c < CIN; c += 2) {
            float x0 = (c < OBS) ? obs[(size_t)i * OBS + c] : act[(size_t)i * ACTD + (c - OBS)];
            float x1 = (c + 1 < OBS) ? obs[(size_t)i * OBS + c + 1]
                                     : act[(size_t)i * ACTD + (c + 1 - OBS)];
            float v0 = (x0 - mu[c]) / sd[c];
            float v1 = (x1 - mu[c + 1]) / sd[c + 1];
            oh[c >> 1] = pack_h2(v0, v1);
        }
        #pragma unroll
        for (int c = CIN; c < 64; c += 2) oh[c >> 1] = 0u;
    } else {
        #pragma unroll
        for (int c = 0; c < 64; c += 2) oh[c >> 1] = 0u;
    }
}

// ======== persistent-A hidden-layer GEMM: 3 full 64-col tiles + 16-col tail ========
template <int KSEG>
__global__ void __launch_bounds__(256, 2) gemm_full(
    int layer, const float* __restrict__ bias, const int* __restrict__ elites,
    int r, int K, int N)
{
    constexpr int SA   = KSEG * 8;
    constexpr int AROW = KSEG * 16 + 16;
    constexpr int ASM  = 128 * AROW;
    constexpr int WSM  = 64 * AROW;

    const __half* Ain;
    const __half* Wt;
    __half* Cout;
    if (layer == 0)      { Ain = g_A; Wt = g_W1; Cout = g_B; }
    else if (layer == 1) { Ain = g_B; Wt = g_W2; Cout = g_A; }
    else                 { Ain = g_A; Wt = g_W3; Cout = g_B; }

    extern __shared__ __align__(16) char sm[];
    uint32_t sb = smem_u32(sm);
    int tid = threadIdx.x, lane = tid & 31, wid = tid >> 5;
    int warp_m = wid >> 1, warp_n = wid & 1;
    int row0 = blockIdx.x * 128;
    int m = blockIdx.y;
    int ev = elites[m];
    size_t qbase = (size_t)m * r;
    size_t wbase = (size_t)ev * 256 * SA;
    const float* biasm = bias + (size_t)ev * N;

    int steps = (K + 15) >> 4;

    #pragma unroll
    for (int it = 0; it < (128 * KSEG + 255) / 256; it++) {
        int idx = tid + it * 256;
        if (idx < 128 * KSEG) {
            int rr = idx / KSEG, u = idx % KSEG;
            int grow = row0 + rr;
            uint32_t pb = (grow < r) ? 16u : 0u;
            size_t gix = (qbase + (grow < r ? grow : 0)) * (size_t)SA + (size_t)(u * 8);
            CPA16(sb + (uint32_t)(rr * AROW + u * 16), Ain + gix, pb);
        }
    }
    CPA_COMMIT();

#define LOAD_W(t_, buf_, rows_) do { \
    uint32_t wb = sb + (uint32_t)ASM + (uint32_t)(buf_) * (uint32_t)WSM; \
    _Pragma("unroll") \
    for (int it = 0; it < (64 * KSEG + 255) / 256; it++) { \
        int idx = tid + it * 256; \
        if (idx < (rows_) * KSEG) { \
            int nr = idx / KSEG, u = idx % KSEG; \
            size_t gix = wbase + (size_t)((t_) * 64 + nr) * (size_t)SA + (size_t)(u * 8); \
            CPA16(wb + (uint32_t)(nr * AROW + u * 16), Wt + gix, 16u); \
        } \
    } \
    CPA_COMMIT(); \
} while (0)

    LOAD_W(0, 0, 64);

    uint32_t a_addr = sb + (uint32_t)((warp_m * 32 + (lane & 15)) * AROW + (lane >> 4) * 16);

    for (int t = 0; t < 3; t++) {
        if (t < 2) LOAD_W(t + 1, (t + 1) & 1, 64);
        else       LOAD_W(3, 1, 16);
        CPA_WAIT1();
        __syncthreads();

        uint32_t wb = sb + (uint32_t)ASM + (uint32_t)(t & 1) * (uint32_t)WSM;
        uint32_t b_addr = wb +
            (uint32_t)((warp_n * 32 + (lane & 7) + ((lane >> 4) << 3)) * AROW +
                       ((lane >> 3) & 1) * 16);

        float acc[2][4][4];
        #pragma unroll
        for (int i = 0; i < 2; i++)
            #pragma unroll
            for (int j = 0; j < 4; j++)
                #pragma unroll
                for (int x = 0; x < 4; x++) acc[i][j][x] = 0.0f;

        for (int s = 0; s < steps; s++) {
            uint32_t ko = (uint32_t)(s * 32);
            uint32_t ah[2][4], bh[2][4];
            LDSM4A(ah[0], a_addr + ko);
            LDSM4A(ah[1], a_addr + 16u * AROW + ko);
            LDSM4A(bh[0], b_addr + ko);
            LDSM4A(bh[1], b_addr + 16u * AROW + ko);
            #pragma unroll
            for (int mi = 0; mi < 2; mi++)
                #pragma unroll
                for (int nn = 0; nn < 4; nn++)
                    MMA4(acc[mi][nn], ah[mi], bh[nn >> 1][(nn & 1) * 2],
                         bh[nn >> 1][(nn & 1) * 2 + 1]);
        }

        #pragma unroll
        for (int mi = 0; mi < 2; mi++) {
            int rlo = row0 + warp_m * 32 + mi * 16 + (lane >> 2);
            #pragma unroll
            for (int nn = 0; nn < 4; nn++) {
                int col = t * 64 + warp_n * 32 + nn * 8 + (lane & 3) * 2;
                if (rlo < r) {
                    float d0 = acc[mi][nn][0] + biasm[col];
                    float d1 = acc[mi][nn][1] + biasm[col + 1];
                    reinterpret_cast<uint32_t*>(Cout)[((qbase + rlo) * OST + col) >> 1] =
                        pack_h2(d0 / (1.0f + expf(-d0)), d1 / (1.0f + expf(-d1)));
                }
                if (rlo + 8 < r) {
                    float d0 = acc[mi][nn][2] + biasm[col];
                    float d1 = acc[mi][nn][3] + biasm[col + 1];
                    reinterpret_cast<uint32_t*>(Cout)[((qbase + rlo + 8) * OST + col) >> 1] =
                        pack_h2(d0 / (1.0f + expf(-d0)), d1 / (1.0f + expf(-d1)));
                }
            }
        }
        __syncthreads();
    }

    // tail tile: cols 192..207 (16 W rows in buf 1)
    {
        CPA_WAIT0();
        __syncthreads();
        uint32_t wb = sb + (uint32_t)ASM + (uint32_t)WSM;
        uint32_t b_addr = wb +
            (uint32_t)((warp_n * 8 + (lane & 7)) * AROW + ((lane >> 3) & 1) * 16);

        float acc[2][4];
        #pragma unroll
        for (int i = 0; i < 2; i++)
            #pragma unroll
            for (int x = 0; x < 4; x++) acc[i][x] = 0.0f;

        for (int s = 0; s < steps; s++) {
            uint32_t ko = (uint32_t)(s * 32);
            uint32_t ah[2][4], b0, b1;
            LDSM4A(ah[0], a_addr + ko);
            LDSM4A(ah[1], a_addr + 16u * AROW + ko);
            LDSM2(b0, b1, b_addr + ko);
            #pragma unroll
            for (int mi = 0; mi < 2; mi++)
                MMA4(acc[mi], ah[mi], b0, b1);
        }

        #pragma unroll
        for (int mi = 0; mi < 2; mi++) {
            int rlo = row0 + warp_m * 32 + mi * 16 + (lane >> 2);
            int col = 192 + warp_n * 8 + (lane & 3) * 2;
            if (rlo < r) {
                float v0 = 0.0f, v1 = 0.0f;
                if (col < N) {
                    float d0 = acc[mi][0] + biasm[col];
                    float d1 = acc[mi][1] + biasm[col + 1];
                    v0 = d0 / (1.0f + expf(-d0));
                    v1 = d1 / (1.0f + expf(-d1));
                }
                reinterpret_cast<uint32_t*>(Cout)[((qbase + rlo) * OST + col) >> 1] =
                    pack_h2(v0, v1);
            }
            if (rlo + 8 < r) {
                float v0 = 0.0f, v1 = 0.0f;
                if (col < N) {
                    float d0 = acc[mi][2] + biasm[col];
                    float d1 = acc[mi][3] + biasm[col + 1];
                    v0 = d0 / (1.0f + expf(-d0));
                    v1 = d1 / (1.0f + expf(-d1));
                }
                reinterpret_cast<uint32_t*>(Cout)[((qbase + rlo + 8) * OST + col) >> 1] =
                    pack_h2(v0, v1);
            }
        }
    }
#undef LOAD_W
}

// ======== layer-4 GEMM: 128-row CTAs (N=66 padded 80) fused with sampling epilogue ========
__global__ void __launch_bounds__(256, 2) gemm_l4(
    const float* __restrict__ b4, const int* __restrict__ elites,
    int r, int K,
    const float* __restrict__ obs, float* __restrict__ out, int n)
{
    const __half* Ain = g_B;
    const __half* Wt  = g_W4;

    // smem: A [0,18432) 128 rows x 144B; B [18432,29952) 80 rows x 144B;
    // epilogue staging f32[128][80] = 40960 (reuses whole buffer)
    __shared__ __align__(16) char sm[40960];
    uint32_t sb = smem_u32(sm);
    int tid = threadIdx.x, lane = tid & 31, wid = tid >> 5;
    int warp_m = wid >> 1, warp_n = wid & 1;
    int row0 = blockIdx.x * 128;
    int m = blockIdx.y;
    int ev = elites[m];
    size_t qbase = (size_t)m * r;
    size_t wbase = (size_t)ev * 80 * OST;

    float acc[2][5][4];
    #pragma unroll
    for (int i = 0; i < 2; i++)
        #pragma unroll
        for (int j = 0; j < 5; j++)
            #pragma unroll
            for (int x = 0; x < 4; x++) acc[i][j][x] = 0.0f;

    uint32_t a_addr = sb + (uint32_t)((warp_m * 32 + (lane & 15)) * 144 + (lane >> 4) * 16);
    uint32_t b_addr = sb + 18432u +
        (uint32_t)((warp_n * 40 + (lane & 7) + ((lane >> 4) << 3)) * 144 + ((lane >> 3) & 1) * 16);
    uint32_t b2_addr = sb + 18432u +
        (uint32_t)((warp_n * 40 + 32 + (lane & 7)) * 144 + ((lane >> 3) & 1) * 16);

    int chunks = (K + 63) >> 6;
    for (int c = 0; c < chunks; c++) {
        int ccol = c * 64;
        // A: 128 rows x 8 segs = 1024
        #pragma unroll
        for (int i = 0; i < 4; i++) {
            int idx = tid + i * 256;
            int rr = idx >> 3, u = idx & 7;
            int grow = row0 + rr;
            int kc = ccol + u * 8;
            uint4 vh = make_uint4(0, 0, 0, 0);
            if (grow < r && kc < OST)
                vh = *reinterpret_cast<const uint4*>(Ain + (qbase + grow) * OST + kc);
            *reinterpret_cast<uint4*>(sm + rr * 144 + u * 16) = vh;
        }
        // B: 80 rows x 8 segs = 640
        #pragma unroll
        for (int i = 0; i < 3; i++) {
            int idx = tid + i * 256;
            if (idx < 640) {
                int nr = idx >> 3, u = idx & 7;
                int kc = ccol + u * 8;
                uint4 wv = make_uint4(0, 0, 0, 0);
                if (kc < OST)
                    wv = *reinterpret_cast<const uint4*>(Wt + wbase + (size_t)nr * OST + kc);
                *reinterpret_cast<uint4*>(sm + 18432 + nr * 144 + u * 16) = wv;
            }
        }
        __syncthreads();

        int steps = (K - ccol + 15) >> 4;
        if (steps > 4) steps = 4;
        for (int s = 0; s < steps; s++) {
            uint32_t ko = (uint32_t)(s * 32);
            uint32_t ah[2][4], bh[2][4], p0, p1;
            LDSM4A(ah[0], a_addr + ko);
            LDSM4A(ah[1], a_addr + 16u * 144 + ko);
            LDSM4A(bh[0], b_addr + ko);
            LDSM4A(bh[1], b_addr + 16u * 144 + ko);
            LDSM2(p0, p1, b2_addr + ko);
            #pragma unroll
            for (int mi = 0; mi < 2; mi++) {
                #pragma unroll
                for (int nn = 0; nn < 4; nn++)
                    MMA4(acc[mi][nn], ah[mi], bh[nn >> 1][(nn & 1) * 2],
                         bh[nn >> 1][(nn & 1) * 2 + 1]);
                MMA4(acc[mi][4], ah[mi], p0, p1);
            }
        }
        __syncthreads();
    }

    // stage accumulators to smem [128][80] f32
    float* stg = reinterpret_cast<float*>(sm);
    #pragma unroll
    for (int mi = 0; mi < 2; mi++) {
        int rlo = warp_m * 32 + mi * 16 + (lane >> 2);
        int colb = warp_n * 40 + (lane & 3) * 2;
        #pragma unroll
        for (int j = 0; j < 5; j++) {
            int col = colb + j * 8;
            stg[rlo * 80 + col]           = acc[mi][j][0];
            stg[rlo * 80 + col + 1]       = acc[mi][j][1];
            stg[(rlo + 8) * 80 + col]     = acc[mi][j][2];
            stg[(rlo + 8) * 80 + col + 1] = acc[mi][j][3];
        }
    }
    __syncthreads();

    // per-row sampling / scatter / reward / terminal (128 rows, 128 threads)
    if (tid < 128) {
        int j = row0 + tid;
        if (j < r) {
            size_t q = qbase + j;
            int i = (int)g_src[q];
            if (i < n) {
                const float* bm = b4 + (size_t)ev * 66;
                const float* row = stg + tid * 80;
                uint32_t fbase = ((uint32_t)ev * (uint32_t)r + (uint32_t)j) * 33u;
                float sumsq = 0.0f;
                for (int d = 0; d < 33; d++) {
                    float mean = row[d] + bm[d];
                    float lv = row[33 + d] + bm[33 + d];
                    lv = 0.5f - softplusf(0.5f - lv);
                    lv = -10.0f + softplusf(lv + 10.0f);
                    float sd = expf(0.5f * lv);
                    float nz = normal_from_bits(rbits32(0u, 0u, fbase + (uint32_t)d));
                    float s = fmaf(nz, sd, mean);
                    if (d < 32) {
                        float no = s + obs[(size_t)i * OBS + d];
                        out[(size_t)i * OBS + d] = no;
                        sumsq += no * no;
                    } else {
                        out[(size_t)n * OBS + i] = s;
                    }
                }
                out[(size_t)n * (OBS + 1) + i] = (sqrtf(sumsq) > 50.0f) ? 1.0f : 0.0f;
            }
        }
    }
}

// ================= launch =================
extern "C" void kernel_launch(void* const* d_in, const int* in_sizes, int n_in,
                              void* d_out, int out_size) {
    const float* obs = (const float*)d_in[0];
    const float* act = (const float*)d_in[1];
    const float* mu  = (const float*)d_in[2];
    const float* sdv = (const float*)d_in[3];
    const float* W1  = (const float*)d_in[4];
    const float* b1  = (const float*)d_in[5];
    const float* W2  = (const float*)d_in[6];
    const float* b2  = (const float*)d_in[7];
    const float* W3  = (const float*)d_in[8];
    const float* b3  = (const float*)d_in[9];
    const float* W4  = (const float*)d_in[10];
    const float* b4  = (const float*)d_in[11];
    const int* elites = (const int*)d_in[12];

    int n = in_sizes[0] / OBS;
    int e = in_sizes[12];
    int r = (n - 1) / e + 1;
    int P = e * r;
    if (P > PMAX) P = PMAX;
    int Mm = in_sizes[4] / (CIN * HID);
    if (Mm > MMAX) Mm = MMAX;

    uint32_t nk0, nk1, s1a, s1b, s2a, s2b;
    threefry2x32(0u, 0u, 0u, 0u, nk0, nk1);
    threefry2x32(0u, 0u, 0u, 1u, s1a, s1b);
    threefry2x32(nk0, nk1, 0u, 1u, s2a, s2b);

    const int TB = 256;
    int gb = (P + TB - 1) / TB;

    void* histPtr = nullptr;
    cudaGetSymbolAddress(&histPtr, g_hist);
    cudaMemsetAsync(histPtr, 0, 2 * NB * sizeof(uint32_t));

    int t1 = Mm * 256 * 64;
    int t2 = Mm * 256 * OST;
    int t4 = Mm * 80 * OST;
    int ttot = t1 + 2 * t2 + t4;
    int mtot = ttot + P;
    prep_and_hist<<<(mtot + 255) / 256, 256>>>(W1, W2, W3, W4, t1, t2, t4,
                                               s1a, s1b, s2a, s2b, P);

    scan2_kernel<<<1, 1024>>>();
    scatter2_kernel<<<gb, TB>>>(P);
    rank2_kernel<<<gb, TB>>>(P);

    gather_kernel<<<gb, TB>>>(obs, act, mu, sdv, n, P);

    cudaFuncSetAttribute(gemm_full<8>,  cudaFuncAttributeMaxDynamicSharedMemorySize, 36864);
    cudaFuncSetAttribute(gemm_full<26>, cudaFuncAttributeMaxDynamicSharedMemorySize, 110592);

    int mt = (r + 127) / 128;
    dim3 gridH(mt, e);
    gemm_full<8><<<gridH, 256, 36864>>>(0, b1, elites, r, CIN, HID);
    gemm_full<26><<<gridH, 256, 110592>>>(1, b2, elites, r, HID, HID);
    gemm_full<26><<<gridH, 256, 110592>>>(2, b3, elites, r, HID, HID);

    dim3 gridL4(mt, e);
    gemm_l4<<<gridL4, 256>>>(b4, elites, r, HID, obs, (float*)d_out, n);
}